// round 1
// baseline (speedup 1.0000x reference)
#include <cuda_runtime.h>
#include <math.h>

#define T_SEQ  2048
#define DMODEL 1024
#define NHEADS 16
#define HDIM   64

// Scratch (static device globals — no allocation allowed in kernel_launch)
__device__ float g_q[T_SEQ * DMODEL];
__device__ float g_k[T_SEQ * DMODEL];
__device__ float g_v[T_SEQ * DMODEL];
__device__ float g_y[T_SEQ * DMODEL];
__device__ float g_cos[T_SEQ * 16];
__device__ float g_sin[T_SEQ * 16];

// ---------------------------------------------------------------------------
// SGEMM: C[M,N] = A[M,K] * B[N,K]^T   (M=2048, N=K=1024, both K-contiguous)
// 128x128 tile, BK=8, 256 threads, 8x8 register tile per thread.
// ---------------------------------------------------------------------------
extern "C" __global__ void __launch_bounds__(256)
sgemm_nt(const float* __restrict__ A, const float* __restrict__ B,
         float* __restrict__ C)
{
    const int K = DMODEL, N = DMODEL;
    __shared__ float As[8][128];
    __shared__ float Bs[8][128];

    const int tid = threadIdx.x;
    const int m0  = blockIdx.y * 128;
    const int n0  = blockIdx.x * 128;

    const int lr = tid >> 1;          // 0..127 row within tile
    const int lc = (tid & 1) << 2;    // 0 or 4 (float4 column group)
    const float* Ap = A + (size_t)(m0 + lr) * K + lc;
    const float* Bp = B + (size_t)(n0 + lr) * K + lc;

    const int mB = (tid >> 4) << 3;   // 0..120
    const int nB = (tid & 15) << 3;   // 0..120

    float acc[8][8];
    #pragma unroll
    for (int i = 0; i < 8; i++)
        #pragma unroll
        for (int j = 0; j < 8; j++) acc[i][j] = 0.f;

    for (int k0 = 0; k0 < K; k0 += 8) {
        float4 av = *(const float4*)(Ap + k0);
        float4 bv = *(const float4*)(Bp + k0);
        As[lc + 0][lr] = av.x; As[lc + 1][lr] = av.y;
        As[lc + 2][lr] = av.z; As[lc + 3][lr] = av.w;
        Bs[lc + 0][lr] = bv.x; Bs[lc + 1][lr] = bv.y;
        Bs[lc + 2][lr] = bv.z; Bs[lc + 3][lr] = bv.w;
        __syncthreads();

        #pragma unroll
        for (int kk = 0; kk < 8; kk++) {
            float a[8], b[8];
            #pragma unroll
            for (int i = 0; i < 8; i++) a[i] = As[kk][mB + i];
            #pragma unroll
            for (int j = 0; j < 8; j++) b[j] = Bs[kk][nB + j];
            #pragma unroll
            for (int i = 0; i < 8; i++)
                #pragma unroll
                for (int j = 0; j < 8; j++)
                    acc[i][j] = fmaf(a[i], b[j], acc[i][j]);
        }
        __syncthreads();
    }

    #pragma unroll
    for (int i = 0; i < 8; i++) {
        float4* cp = (float4*)(C + (size_t)(m0 + mB + i) * N + n0 + nB);
        cp[0] = make_float4(acc[i][0], acc[i][1], acc[i][2], acc[i][3]);
        cp[1] = make_float4(acc[i][4], acc[i][5], acc[i][6], acc[i][7]);
    }
}

// ---------------------------------------------------------------------------
// Rotary tables: theta = t * invf computed in fp32 (matches reference's fp32
// product), then sincos in double for accurate range reduction (t*invf up to
// ~2047 rad).
// ---------------------------------------------------------------------------
extern "C" __global__ void rope_tables()
{
    int t = blockIdx.x;
    int j = threadIdx.x;  // 0..15  (freqs 16..31 are zero -> identity)
    float invf = exp2f(-10.0f * (float)j * (1.0f / 15.0f));  // 1024^(-j/15)
    float theta = (float)t * invf;
    double s, c;
    sincos((double)theta, &s, &c);
    g_cos[t * 16 + j] = (float)c;
    g_sin[t * 16 + j] = (float)s;
}

// ---------------------------------------------------------------------------
// Post: v = l0*v + l1*vi ; q,k = rotary(rmsnorm(q|k)) per (t, head).
// One block per (head, t), 64 threads = head_dim.
// ---------------------------------------------------------------------------
extern "C" __global__ void __launch_bounds__(64)
qkv_post(const float* __restrict__ vi, const float* __restrict__ lambdas)
{
    const int h = blockIdx.x;
    const int t = blockIdx.y;
    const int d = threadIdx.x;
    const int idx = t * DMODEL + h * HDIM + d;

    const float l0 = lambdas[0], l1 = lambdas[1];
    g_v[idx] = fmaf(l0, g_v[idx], l1 * vi[idx]);

    float qv = g_q[idx], kv = g_k[idx];
    float q2 = qv * qv, k2 = kv * kv;
    #pragma unroll
    for (int o = 16; o > 0; o >>= 1) {
        q2 += __shfl_xor_sync(0xffffffffu, q2, o);
        k2 += __shfl_xor_sync(0xffffffffu, k2, o);
    }
    __shared__ float red[4];
    if ((d & 31) == 0) { red[d >> 5] = q2; red[2 + (d >> 5)] = k2; }
    __syncthreads();

    const float eps = 1.1920929e-7f;  // FLT_EPSILON (matches jnp.finfo eps)
    float qn = qv * rsqrtf((red[0] + red[1]) * (1.f / 64.f) + eps);
    float kn = kv * rsqrtf((red[2] + red[3]) * (1.f / 64.f) + eps);

    __shared__ float sq[64], sk[64];
    sq[d] = qn; sk[d] = kn;
    __syncthreads();

    const int j = d & 31;
    float c = 1.f, s = 0.f;
    if (j < 16) { c = g_cos[t * 16 + j]; s = g_sin[t * 16 + j]; }
    float oq, ok;
    if (d < 32) {
        oq =  sq[d] * c + sq[d + 32] * s;
        ok =  sk[d] * c + sk[d + 32] * s;
    } else {
        oq = -sq[j] * s + sq[d] * c;
        ok = -sk[j] * s + sk[d] * c;
    }
    g_q[idx] = oq;
    g_k[idx] = ok;
}

// ---------------------------------------------------------------------------
// Flash attention, fp32, causal. BLOCK_M = BLOCK_N = 64, hd = 64.
// Grid: (32 q-tiles, 16 heads). 256 threads as 16x16, 4x4 frags.
// S is written into Ks's storage after the S-gemm (alias saves smem).
// ---------------------------------------------------------------------------
struct FlashSmem {
    float Qs[64][64];
    float Ks[64][65];      // padded; aliased as S[64][65] after QK^T
    float Vs[64][64];
    float m[64], l[64], alpha[64];
};

extern "C" __global__ void __launch_bounds__(256)
flash_attn()
{
    extern __shared__ char smem_raw[];
    FlashSmem& sm = *reinterpret_cast<FlashSmem*>(smem_raw);

    const int qt  = blockIdx.x;
    const int h   = blockIdx.y;
    const int tid = threadIdx.x;
    const int q0  = qt * 64;
    const int ty  = tid >> 4, tx = tid & 15;
    const int iB  = ty << 2, jB = tx << 2;
    const float NEG_INF = __int_as_float(0xff800000);

    // Load Q tile, pre-scaled by 1/sqrt(64)
    for (int i = tid; i < 64 * 16; i += 256) {
        int r = i >> 4, c = (i & 15) << 2;
        float4 v = *(const float4*)&g_q[(size_t)(q0 + r) * DMODEL + h * HDIM + c];
        sm.Qs[r][c]     = v.x * 0.125f;
        sm.Qs[r][c + 1] = v.y * 0.125f;
        sm.Qs[r][c + 2] = v.z * 0.125f;
        sm.Qs[r][c + 3] = v.w * 0.125f;
    }
    if (tid < 64) { sm.m[tid] = NEG_INF; sm.l[tid] = 0.f; }

    float O[4][4];
    #pragma unroll
    for (int i = 0; i < 4; i++)
        #pragma unroll
        for (int j = 0; j < 4; j++) O[i][j] = 0.f;

    __syncthreads();

    for (int kt = 0; kt <= qt; kt++) {
        const int k0 = kt * 64;
        for (int i = tid; i < 64 * 16; i += 256) {
            int r = i >> 4, c = (i & 15) << 2;
            float4 kv = *(const float4*)&g_k[(size_t)(k0 + r) * DMODEL + h * HDIM + c];
            sm.Ks[r][c] = kv.x; sm.Ks[r][c + 1] = kv.y;
            sm.Ks[r][c + 2] = kv.z; sm.Ks[r][c + 3] = kv.w;
            float4 vv = *(const float4*)&g_v[(size_t)(k0 + r) * DMODEL + h * HDIM + c];
            *(float4*)&sm.Vs[r][c] = vv;
        }
        __syncthreads();

        // S = Q * K^T (4x4 frag per thread)
        float s[4][4];
        #pragma unroll
        for (int i = 0; i < 4; i++)
            #pragma unroll
            for (int j = 0; j < 4; j++) s[i][j] = 0.f;
        #pragma unroll 8
        for (int d = 0; d < 64; d++) {
            float a[4], b[4];
            #pragma unroll
            for (int i = 0; i < 4; i++) a[i] = sm.Qs[iB + i][d];
            #pragma unroll
            for (int j = 0; j < 4; j++) b[j] = sm.Ks[jB + j][d];
            #pragma unroll
            for (int i = 0; i < 4; i++)
                #pragma unroll
                for (int j = 0; j < 4; j++)
                    s[i][j] = fmaf(a[i], b[j], s[i][j]);
        }
        __syncthreads();  // all reads of Ks complete; safe to alias

        float (*S)[65] = sm.Ks;
        #pragma unroll
        for (int i = 0; i < 4; i++)
            #pragma unroll
            for (int j = 0; j < 4; j++) {
                float val = s[i][j];
                if (kt == qt && (k0 + jB + j) > (q0 + iB + i)) val = -1e30f;
                S[iB + i][jB + j] = val;
            }
        __syncthreads();

        // Online softmax: 4 threads per row (row = tid>>2, 16 cols each)
        {
            const int row = tid >> 2;
            const int part = tid & 3;
            float* srow = S[row];
            float mx = NEG_INF;
            #pragma unroll
            for (int i = 0; i < 16; i++) mx = fmaxf(mx, srow[part * 16 + i]);
            mx = fmaxf(mx, __shfl_xor_sync(0xffffffffu, mx, 1));
            mx = fmaxf(mx, __shfl_xor_sync(0xffffffffu, mx, 2));
            const float mold = sm.m[row];
            const float mnew = fmaxf(mold, mx);
            float sum = 0.f;
            #pragma unroll
            for (int i = 0; i < 16; i++) {
                float p = expf(srow[part * 16 + i] - mnew);
                srow[part * 16 + i] = p;
                sum += p;
            }
            sum += __shfl_xor_sync(0xffffffffu, sum, 1);
            sum += __shfl_xor_sync(0xffffffffu, sum, 2);
            if (part == 0) {
                float al = expf(mold - mnew);   // 0 when mold = -inf
                sm.alpha[row] = al;
                sm.m[row] = mnew;
                sm.l[row] = sm.l[row] * al + sum;
            }
        }
        __syncthreads();

        // O = O * alpha + P * V
        float al[4];
        #pragma unroll
        for (int i = 0; i < 4; i++) al[i] = sm.alpha[iB + i];
        #pragma unroll
        for (int i = 0; i < 4; i++)
            #pragma unroll
            for (int j = 0; j < 4; j++) O[i][j] *= al[i];
        #pragma unroll 8
        for (int j2 = 0; j2 < 64; j2++) {
            float p[4], v2[4];
            #pragma unroll
            for (int i = 0; i < 4; i++) p[i] = S[iB + i][j2];
            #pragma unroll
            for (int j = 0; j < 4; j++) v2[j] = sm.Vs[j2][jB + j];
            #pragma unroll
            for (int i = 0; i < 4; i++)
                #pragma unroll
                for (int j = 0; j < 4; j++)
                    O[i][j] = fmaf(p[i], v2[j], O[i][j]);
        }
        __syncthreads();
    }

    // Epilogue: divide by l, store to y
    #pragma unroll
    for (int i = 0; i < 4; i++) {
        float inv = 1.f / sm.l[iB + i];
        float4 o4 = make_float4(O[i][0] * inv, O[i][1] * inv,
                                O[i][2] * inv, O[i][3] * inv);
        *(float4*)&g_y[(size_t)(q0 + iB + i) * DMODEL + h * HDIM + jB] = o4;
    }
}

// ---------------------------------------------------------------------------
extern "C" void kernel_launch(void* const* d_in, const int* in_sizes, int n_in,
                              void* d_out, int out_size)
{
    const float* x   = (const float*)d_in[0];
    const float* vi  = (const float*)d_in[1];
    const float* Wq  = (const float*)d_in[2];
    const float* Wk  = (const float*)d_in[3];
    const float* Wv  = (const float*)d_in[4];
    const float* Wp  = (const float*)d_in[5];
    const float* lam = (const float*)d_in[6];
    float* out = (float*)d_out;

    float *gq, *gk, *gv, *gy;
    cudaGetSymbolAddress((void**)&gq, g_q);
    cudaGetSymbolAddress((void**)&gk, g_k);
    cudaGetSymbolAddress((void**)&gv, g_v);
    cudaGetSymbolAddress((void**)&gy, g_y);

    dim3 ggrid(DMODEL / 128, T_SEQ / 128);
    sgemm_nt<<<ggrid, 256>>>(x, Wq, gq);
    sgemm_nt<<<ggrid, 256>>>(x, Wk, gk);
    sgemm_nt<<<ggrid, 256>>>(x, Wv, gv);

    rope_tables<<<T_SEQ, 16>>>();
    qkv_post<<<dim3(NHEADS, T_SEQ), 64>>>(vi, lam);

    cudaFuncSetAttribute(flash_attn, cudaFuncAttributeMaxDynamicSharedMemorySize,
                         (int)sizeof(FlashSmem));
    flash_attn<<<dim3(T_SEQ / 64, NHEADS), 256, sizeof(FlashSmem)>>>();

    sgemm_nt<<<ggrid, 256>>>(gy, Wp, out);
}

// round 3
// speedup vs baseline: 1.6071x; 1.6071x over previous
#include <cuda_runtime.h>
#include <cuda_bf16.h>
#include <math.h>
#include <stdint.h>

#define T_SEQ  2048
#define DMODEL 1024
#define NHEADS 16
#define HDIM   64
#define KBIG   3072              // [hi | lo | hi] x [hi | hi | lo]
#define BK     64
#define NSTAGES (KBIG / BK)      // 48

// ---------------------------------------------------------------------------
// Scratch (static device globals — no allocation allowed in kernel_launch)
// ---------------------------------------------------------------------------
__device__ float g_q[T_SEQ * DMODEL];
__device__ float g_k[T_SEQ * DMODEL];
__device__ float g_v[T_SEQ * DMODEL];
__device__ float g_y[T_SEQ * DMODEL];
__device__ float g_cos[T_SEQ * 16];
__device__ float g_sin[T_SEQ * 16];
__device__ __align__(16) __nv_bfloat16 g_Abig[T_SEQ * KBIG];
__device__ __align__(16) __nv_bfloat16 g_Wqb[DMODEL * KBIG];
__device__ __align__(16) __nv_bfloat16 g_Wkb[DMODEL * KBIG];
__device__ __align__(16) __nv_bfloat16 g_Wvb[DMODEL * KBIG];
__device__ __align__(16) __nv_bfloat16 g_Wpb[DMODEL * KBIG];

// ---------------------------------------------------------------------------
__device__ __forceinline__ uint32_t smem_u32(const void* p) {
    uint32_t a;
    asm("{ .reg .u64 t; cvta.to.shared.u64 t, %1; cvt.u32.u64 %0, t; }"
        : "=r"(a) : "l"(p));
    return a;
}

__device__ __forceinline__ void ldsm_x4(uint32_t& r0, uint32_t& r1,
                                        uint32_t& r2, uint32_t& r3,
                                        uint32_t addr) {
    asm volatile("ldmatrix.sync.aligned.m8n8.x4.shared.b16 {%0,%1,%2,%3}, [%4];"
                 : "=r"(r0), "=r"(r1), "=r"(r2), "=r"(r3) : "r"(addr));
}

__device__ __forceinline__ void mma16816(float* d, const uint32_t* a,
                                         const uint32_t* b) {
    asm volatile(
        "mma.sync.aligned.m16n8k16.row.col.f32.bf16.bf16.f32 "
        "{%0,%1,%2,%3}, {%4,%5,%6,%7}, {%8,%9}, {%0,%1,%2,%3};"
        : "+f"(d[0]), "+f"(d[1]), "+f"(d[2]), "+f"(d[3])
        : "r"(a[0]), "r"(a[1]), "r"(a[2]), "r"(a[3]), "r"(b[0]), "r"(b[1]));
}

// ---------------------------------------------------------------------------
// Packing: fp32 -> bf16 hi/lo split with concatenated K.
// A rows:  [hi | lo | hi] ; W rows: [hi | hi | lo]
// ---------------------------------------------------------------------------
extern "C" __global__ void pack_a(const float* __restrict__ src,
                                  __nv_bfloat16* __restrict__ dst) {
    const int r = blockIdx.x;
    for (int k = threadIdx.x; k < DMODEL; k += blockDim.x) {
        float v = src[(size_t)r * DMODEL + k];
        __nv_bfloat16 hi = __float2bfloat16(v);
        __nv_bfloat16 lo = __float2bfloat16(v - __bfloat162float(hi));
        size_t base = (size_t)r * KBIG;
        dst[base + k] = hi;
        dst[base + DMODEL + k] = lo;
        dst[base + 2 * DMODEL + k] = hi;
    }
}

extern "C" __global__ void pack_w(const float* __restrict__ src,
                                  __nv_bfloat16* __restrict__ dst) {
    const int r = blockIdx.x;
    for (int k = threadIdx.x; k < DMODEL; k += blockDim.x) {
        float v = src[(size_t)r * DMODEL + k];
        __nv_bfloat16 hi = __float2bfloat16(v);
        __nv_bfloat16 lo = __float2bfloat16(v - __bfloat162float(hi));
        size_t base = (size_t)r * KBIG;
        dst[base + k] = hi;
        dst[base + DMODEL + k] = hi;
        dst[base + 2 * DMODEL + k] = lo;
    }
}

// ---------------------------------------------------------------------------
// mma.sync bf16 GEMM: C[M,1024] = Abig[M,3072] * Bbig[1024,3072]^T (fp32 acc)
// 128x128 CTA tile, 8 warps (2x4) of 64x32, BK=64, double-buffered smem.
// smem rows: 128B, swizzled at 16B-quad granularity: q' = q ^ (row&7).
// Layout: [buf0: A 16K | B 16K][buf1: A 16K | B 16K]  = 65536 bytes dynamic.
// ---------------------------------------------------------------------------
#define GEMM_SMEM_BYTES 65536

extern "C" __global__ void __launch_bounds__(256)
gemm_bf16(const __nv_bfloat16* __restrict__ A,
          const __nv_bfloat16* __restrict__ B,
          float* __restrict__ C)
{
    extern __shared__ __align__(1024) char smem[];
    const uint32_t sbase = smem_u32(smem);

    const int tid  = threadIdx.x;
    const int wid  = tid >> 5;
    const int lane = tid & 31;
    const int n0 = blockIdx.x * 128;
    const int m0 = blockIdx.y * 128;
    const int wm = (wid >> 2) * 64;
    const int wn = (wid & 3) * 32;

    // -- global-load mapping: thread covers 4 rows (stride 32), one 16B quad
    const int lrow = tid >> 3;           // 0..31
    const int lq   = tid & 7;            // quad within 128B row
    const __nv_bfloat16* Ag = A + (size_t)(m0 + lrow) * KBIG + lq * 8;
    const __nv_bfloat16* Bg = B + (size_t)(n0 + lrow) * KBIG + lq * 8;
    const uint32_t st_off = lrow * 128 + ((lq ^ (lrow & 7)) << 4);

    // -- ldmatrix source offsets (byte offsets within one buffer half)
    uint32_t aoff[4][4], boff[4][2];
    #pragma unroll
    for (int ks = 0; ks < 4; ks++) {
        #pragma unroll
        for (int mf = 0; mf < 4; mf++) {
            int row = wm + 16 * mf + ((lane >> 3) & 1) * 8 + (lane & 7);
            int ch  = 2 * ks + (lane >> 4);
            aoff[ks][mf] = row * 128 + ((ch ^ (row & 7)) << 4);
        }
        #pragma unroll
        for (int np = 0; np < 2; np++) {
            int row = wn + 16 * np + ((lane >> 4) << 3) + (lane & 7);
            int ch  = 2 * ks + ((lane >> 3) & 1);
            boff[ks][np] = row * 128 + ((ch ^ (row & 7)) << 4);
        }
    }

    float acc[4][4][4];
    #pragma unroll
    for (int i = 0; i < 4; i++)
        #pragma unroll
        for (int j = 0; j < 4; j++)
            #pragma unroll
            for (int r = 0; r < 4; r++) acc[i][j][r] = 0.f;

    // -- prologue: stage 0 into buf 0
    {
        #pragma unroll
        for (int j = 0; j < 4; j++) {
            uint4 va = *(const uint4*)(Ag + (size_t)32 * j * KBIG);
            uint4 vb = *(const uint4*)(Bg + (size_t)32 * j * KBIG);
            *(uint4*)(smem + st_off + j * 4096)         = va;
            *(uint4*)(smem + 16384 + st_off + j * 4096) = vb;
        }
    }
    __syncthreads();

    for (int s = 0; s < NSTAGES; s++) {
        const int buf = s & 1;
        uint4 nA[4], nB[4];
        if (s + 1 < NSTAGES) {
            const int ko = (s + 1) * BK;
            #pragma unroll
            for (int j = 0; j < 4; j++) {
                nA[j] = *(const uint4*)(Ag + (size_t)32 * j * KBIG + ko);
                nB[j] = *(const uint4*)(Bg + (size_t)32 * j * KBIG + ko);
            }
        }

        const uint32_t ab32 = sbase + buf * 32768;
        const uint32_t bb32 = ab32 + 16384;
        #pragma unroll
        for (int ks = 0; ks < 4; ks++) {
            uint32_t af[4][4], bf[2][4];
            #pragma unroll
            for (int mf = 0; mf < 4; mf++)
                ldsm_x4(af[mf][0], af[mf][1], af[mf][2], af[mf][3],
                        ab32 + aoff[ks][mf]);
            #pragma unroll
            for (int np = 0; np < 2; np++)
                ldsm_x4(bf[np][0], bf[np][1], bf[np][2], bf[np][3],
                        bb32 + boff[ks][np]);
            #pragma unroll
            for (int mf = 0; mf < 4; mf++)
                #pragma unroll
                for (int nf = 0; nf < 4; nf++)
                    mma16816(acc[mf][nf], af[mf], &bf[nf >> 1][(nf & 1) * 2]);
        }

        if (s + 1 < NSTAGES) {
            char* dst = smem + (buf ^ 1) * 32768;
            #pragma unroll
            for (int j = 0; j < 4; j++) {
                *(uint4*)(dst + st_off + j * 4096)         = nA[j];
                *(uint4*)(dst + 16384 + st_off + j * 4096) = nB[j];
            }
        }
        __syncthreads();
    }

    // -- epilogue: fragment -> C (fp32)
    const int gr = lane >> 2;
    const int gc = (lane & 3) * 2;
    #pragma unroll
    for (int mf = 0; mf < 4; mf++)
        #pragma unroll
        for (int nf = 0; nf < 4; nf++) {
            const int row = m0 + wm + 16 * mf + gr;
            const int col = n0 + wn + 8 * nf + gc;
            *(float2*)&C[(size_t)row * DMODEL + col] =
                make_float2(acc[mf][nf][0], acc[mf][nf][1]);
            *(float2*)&C[(size_t)(row + 8) * DMODEL + col] =
                make_float2(acc[mf][nf][2], acc[mf][nf][3]);
        }
}

// ---------------------------------------------------------------------------
// Rotary tables (fp32 theta product to match reference, double sincos)
// ---------------------------------------------------------------------------
extern "C" __global__ void rope_tables()
{
    int t = blockIdx.x;
    int j = threadIdx.x;  // 0..15
    float invf = exp2f(-10.0f * (float)j * (1.0f / 15.0f));
    float theta = (float)t * invf;
    double s, c;
    sincos((double)theta, &s, &c);
    g_cos[t * 16 + j] = (float)c;
    g_sin[t * 16 + j] = (float)s;
}

// ---------------------------------------------------------------------------
// Post: v = l0*v + l1*vi ; q,k = rotary(rmsnorm(q|k))
// ---------------------------------------------------------------------------
extern "C" __global__ void __launch_bounds__(64)
qkv_post(const float* __restrict__ vi, const float* __restrict__ lambdas)
{
    const int h = blockIdx.x;
    const int t = blockIdx.y;
    const int d = threadIdx.x;
    const int idx = t * DMODEL + h * HDIM + d;

    const float l0 = lambdas[0], l1 = lambdas[1];
    g_v[idx] = fmaf(l0, g_v[idx], l1 * vi[idx]);

    float qv = g_q[idx], kv = g_k[idx];
    float q2 = qv * qv, k2 = kv * kv;
    #pragma unroll
    for (int o = 16; o > 0; o >>= 1) {
        q2 += __shfl_xor_sync(0xffffffffu, q2, o);
        k2 += __shfl_xor_sync(0xffffffffu, k2, o);
    }
    __shared__ float red[4];
    if ((d & 31) == 0) { red[d >> 5] = q2; red[2 + (d >> 5)] = k2; }
    __syncthreads();

    const float eps = 1.1920929e-7f;
    float qn = qv * rsqrtf((red[0] + red[1]) * (1.f / 64.f) + eps);
    float kn = kv * rsqrtf((red[2] + red[3]) * (1.f / 64.f) + eps);

    __shared__ float sq[64], sk[64];
    sq[d] = qn; sk[d] = kn;
    __syncthreads();

    const int j = d & 31;
    float c = 1.f, s = 0.f;
    if (j < 16) { c = g_cos[t * 16 + j]; s = g_sin[t * 16 + j]; }
    float oq, ok;
    if (d < 32) {
        oq =  sq[d] * c + sq[d + 32] * s;
        ok =  sk[d] * c + sk[d + 32] * s;
    } else {
        oq = -sq[j] * s + sq[d] * c;
        ok = -sk[j] * s + sk[d] * c;
    }
    g_q[idx] = oq;
    g_k[idx] = ok;
}

// ---------------------------------------------------------------------------
// Flash attention, fp32, causal. 64x64 tiles, hd=64. (unchanged from R1)
// ---------------------------------------------------------------------------
struct FlashSmem {
    float Qs[64][64];
    float Ks[64][65];
    float Vs[64][64];
    float m[64], l[64], alpha[64];
};

extern "C" __global__ void __launch_bounds__(256)
flash_attn()
{
    extern __shared__ char smem_raw[];
    FlashSmem& sm = *reinterpret_cast<FlashSmem*>(smem_raw);

    const int qt  = blockIdx.x;
    const int h   = blockIdx.y;
    const int tid = threadIdx.x;
    const int q0  = qt * 64;
    const int ty  = tid >> 4, tx = tid & 15;
    const int iB  = ty << 2, jB = tx << 2;
    const float NEG_INF = __int_as_float(0xff800000);

    for (int i = tid; i < 64 * 16; i += 256) {
        int r = i >> 4, c = (i & 15) << 2;
        float4 v = *(const float4*)&g_q[(size_t)(q0 + r) * DMODEL + h * HDIM + c];
        sm.Qs[r][c]     = v.x * 0.125f;
        sm.Qs[r][c + 1] = v.y * 0.125f;
        sm.Qs[r][c + 2] = v.z * 0.125f;
        sm.Qs[r][c + 3] = v.w * 0.125f;
    }
    if (tid < 64) { sm.m[tid] = NEG_INF; sm.l[tid] = 0.f; }

    float O[4][4];
    #pragma unroll
    for (int i = 0; i < 4; i++)
        #pragma unroll
        for (int j = 0; j < 4; j++) O[i][j] = 0.f;

    __syncthreads();

    for (int kt = 0; kt <= qt; kt++) {
        const int k0 = kt * 64;
        for (int i = tid; i < 64 * 16; i += 256) {
            int r = i >> 4, c = (i & 15) << 2;
            float4 kv = *(const float4*)&g_k[(size_t)(k0 + r) * DMODEL + h * HDIM + c];
            sm.Ks[r][c] = kv.x; sm.Ks[r][c + 1] = kv.y;
            sm.Ks[r][c + 2] = kv.z; sm.Ks[r][c + 3] = kv.w;
            float4 vv = *(const float4*)&g_v[(size_t)(k0 + r) * DMODEL + h * HDIM + c];
            *(float4*)&sm.Vs[r][c] = vv;
        }
        __syncthreads();

        float s[4][4];
        #pragma unroll
        for (int i = 0; i < 4; i++)
            #pragma unroll
            for (int j = 0; j < 4; j++) s[i][j] = 0.f;
        #pragma unroll 8
        for (int d = 0; d < 64; d++) {
            float a[4], b[4];
            #pragma unroll
            for (int i = 0; i < 4; i++) a[i] = sm.Qs[iB + i][d];
            #pragma unroll
            for (int j = 0; j < 4; j++) b[j] = sm.Ks[jB + j][d];
            #pragma unroll
            for (int i = 0; i < 4; i++)
                #pragma unroll
                for (int j = 0; j < 4; j++)
                    s[i][j] = fmaf(a[i], b[j], s[i][j]);
        }
        __syncthreads();

        float (*S)[65] = sm.Ks;
        #pragma unroll
        for (int i = 0; i < 4; i++)
            #pragma unroll
            for (int j = 0; j < 4; j++) {
                float val = s[i][j];
                if (kt == qt && (k0 + jB + j) > (q0 + iB + i)) val = -1e30f;
                S[iB + i][jB + j] = val;
            }
        __syncthreads();

        {
            const int row = tid >> 2;
            const int part = tid & 3;
            float* srow = S[row];
            float mx = NEG_INF;
            #pragma unroll
            for (int i = 0; i < 16; i++) mx = fmaxf(mx, srow[part * 16 + i]);
            mx = fmaxf(mx, __shfl_xor_sync(0xffffffffu, mx, 1));
            mx = fmaxf(mx, __shfl_xor_sync(0xffffffffu, mx, 2));
            const float mold = sm.m[row];
            const float mnew = fmaxf(mold, mx);
            float sum = 0.f;
            #pragma unroll
            for (int i = 0; i < 16; i++) {
                float p = expf(srow[part * 16 + i] - mnew);
                srow[part * 16 + i] = p;
                sum += p;
            }
            sum += __shfl_xor_sync(0xffffffffu, sum, 1);
            sum += __shfl_xor_sync(0xffffffffu, sum, 2);
            if (part == 0) {
                float al = expf(mold - mnew);
                sm.alpha[row] = al;
                sm.m[row] = mnew;
                sm.l[row] = sm.l[row] * al + sum;
            }
        }
        __syncthreads();

        float al[4];
        #pragma unroll
        for (int i = 0; i < 4; i++) al[i] = sm.alpha[iB + i];
        #pragma unroll
        for (int i = 0; i < 4; i++)
            #pragma unroll
            for (int j = 0; j < 4; j++) O[i][j] *= al[i];
        #pragma unroll 8
        for (int j2 = 0; j2 < 64; j2++) {
            float p[4], v2[4];
            #pragma unroll
            for (int i = 0; i < 4; i++) p[i] = S[iB + i][j2];
            #pragma unroll
            for (int j = 0; j < 4; j++) v2[j] = sm.Vs[j2][jB + j];
            #pragma unroll
            for (int i = 0; i < 4; i++)
                #pragma unroll
                for (int j = 0; j < 4; j++)
                    O[i][j] = fmaf(p[i], v2[j], O[i][j]);
        }
        __syncthreads();
    }

    #pragma unroll
    for (int i = 0; i < 4; i++) {
        float inv = 1.f / sm.l[iB + i];
        float4 o4 = make_float4(O[i][0] * inv, O[i][1] * inv,
                                O[i][2] * inv, O[i][3] * inv);
        *(float4*)&g_y[(size_t)(q0 + iB + i) * DMODEL + h * HDIM + jB] = o4;
    }
}

// ---------------------------------------------------------------------------
extern "C" void kernel_launch(void* const* d_in, const int* in_sizes, int n_in,
                              void* d_out, int out_size)
{
    const float* x   = (const float*)d_in[0];
    const float* vi  = (const float*)d_in[1];
    const float* Wq  = (const float*)d_in[2];
    const float* Wk  = (const float*)d_in[3];
    const float* Wv  = (const float*)d_in[4];
    const float* Wp  = (const float*)d_in[5];
    const float* lam = (const float*)d_in[6];
    float* out = (float*)d_out;

    float *gq, *gk, *gv, *gy;
    __nv_bfloat16 *gA, *gWq, *gWk, *gWv, *gWp;
    cudaGetSymbolAddress((void**)&gq, g_q);
    cudaGetSymbolAddress((void**)&gk, g_k);
    cudaGetSymbolAddress((void**)&gv, g_v);
    cudaGetSymbolAddress((void**)&gy, g_y);
    cudaGetSymbolAddress((void**)&gA, g_Abig);
    cudaGetSymbolAddress((void**)&gWq, g_Wqb);
    cudaGetSymbolAddress((void**)&gWk, g_Wkb);
    cudaGetSymbolAddress((void**)&gWv, g_Wvb);
    cudaGetSymbolAddress((void**)&gWp, g_Wpb);

    cudaFuncSetAttribute(gemm_bf16, cudaFuncAttributeMaxDynamicSharedMemorySize,
                         GEMM_SMEM_BYTES);
    cudaFuncSetAttribute(flash_attn, cudaFuncAttributeMaxDynamicSharedMemorySize,
                         (int)sizeof(FlashSmem));

    // Pack weights + activations (hi/lo split, concatenated K)
    pack_w<<<DMODEL, 256>>>(Wq, gWq);
    pack_w<<<DMODEL, 256>>>(Wk, gWk);
    pack_w<<<DMODEL, 256>>>(Wv, gWv);
    pack_w<<<DMODEL, 256>>>(Wp, gWp);
    pack_a<<<T_SEQ, 256>>>(x, gA);

    dim3 ggrid(DMODEL / 128, T_SEQ / 128);
    gemm_bf16<<<ggrid, 256, GEMM_SMEM_BYTES>>>(gA, gWq, gq);
    gemm_bf16<<<ggrid, 256, GEMM_SMEM_BYTES>>>(gA, gWk, gk);
    gemm_bf16<<<ggrid, 256, GEMM_SMEM_BYTES>>>(gA, gWv, gv);

    rope_tables<<<T_SEQ, 16>>>();
    qkv_post<<<dim3(NHEADS, T_SEQ), 64>>>(vi, lam);

    flash_attn<<<dim3(T_SEQ / 64, NHEADS), 256, sizeof(FlashSmem)>>>();

    pack_a<<<T_SEQ, 256>>>(gy, gA);
    gemm_bf16<<<ggrid, 256, GEMM_SMEM_BYTES>>>(gA, gWp, out);
}

// round 4
// speedup vs baseline: 2.8469x; 1.7715x over previous
#include <cuda_runtime.h>
#include <cuda_bf16.h>
#include <math.h>
#include <stdint.h>

#define T_SEQ  2048
#define DMODEL 1024
#define NHEADS 16
#define HDIM   64
#define KBIG   3072              // [hi | lo | hi] x [hi | hi | lo]
#define BK     64
#define NSTAGES (KBIG / BK)      // 48

// ---------------------------------------------------------------------------
// Scratch (static device globals — no allocation allowed in kernel_launch)
// ---------------------------------------------------------------------------
__device__ float g_q[T_SEQ * DMODEL];
__device__ float g_k[T_SEQ * DMODEL];
__device__ float g_v[T_SEQ * DMODEL];
__device__ float g_y[T_SEQ * DMODEL];
__device__ float g_cos[T_SEQ * 16];
__device__ float g_sin[T_SEQ * 16];
__device__ __align__(16) __nv_bfloat16 g_Abig[T_SEQ * KBIG];
__device__ __align__(16) __nv_bfloat16 g_Wqb[DMODEL * KBIG];
__device__ __align__(16) __nv_bfloat16 g_Wkb[DMODEL * KBIG];
__device__ __align__(16) __nv_bfloat16 g_Wvb[DMODEL * KBIG];
__device__ __align__(16) __nv_bfloat16 g_Wpb[DMODEL * KBIG];
// bf16 hi/lo splits for attention (q pre-scaled by 1/8)
__device__ __align__(16) __nv_bfloat16 g_qhi[T_SEQ * DMODEL];
__device__ __align__(16) __nv_bfloat16 g_qlo[T_SEQ * DMODEL];
__device__ __align__(16) __nv_bfloat16 g_khi[T_SEQ * DMODEL];
__device__ __align__(16) __nv_bfloat16 g_klo[T_SEQ * DMODEL];
__device__ __align__(16) __nv_bfloat16 g_vhi[T_SEQ * DMODEL];
__device__ __align__(16) __nv_bfloat16 g_vlo[T_SEQ * DMODEL];

// ---------------------------------------------------------------------------
__device__ __forceinline__ uint32_t smem_u32(const void* p) {
    uint32_t a;
    asm("{ .reg .u64 t; cvta.to.shared.u64 t, %1; cvt.u32.u64 %0, t; }"
        : "=r"(a) : "l"(p));
    return a;
}

__device__ __forceinline__ void ldsm_x4(uint32_t* r, uint32_t addr) {
    asm volatile("ldmatrix.sync.aligned.m8n8.x4.shared.b16 {%0,%1,%2,%3}, [%4];"
                 : "=r"(r[0]), "=r"(r[1]), "=r"(r[2]), "=r"(r[3]) : "r"(addr));
}

__device__ __forceinline__ void ldsm_x4_t(uint32_t* r, uint32_t addr) {
    asm volatile("ldmatrix.sync.aligned.m8n8.x4.trans.shared.b16 {%0,%1,%2,%3}, [%4];"
                 : "=r"(r[0]), "=r"(r[1]), "=r"(r[2]), "=r"(r[3]) : "r"(addr));
}

__device__ __forceinline__ void mma16816(float* d, const uint32_t* a,
                                         const uint32_t* b) {
    asm volatile(
        "mma.sync.aligned.m16n8k16.row.col.f32.bf16.bf16.f32 "
        "{%0,%1,%2,%3}, {%4,%5,%6,%7}, {%8,%9}, {%0,%1,%2,%3};"
        : "+f"(d[0]), "+f"(d[1]), "+f"(d[2]), "+f"(d[3])
        : "r"(a[0]), "r"(a[1]), "r"(a[2]), "r"(a[3]), "r"(b[0]), "r"(b[1]));
}

__device__ __forceinline__ uint32_t pack_bf16x2(float lo, float hi) {
    uint32_t r;
    asm("cvt.rn.bf16x2.f32 %0, %1, %2;" : "=r"(r) : "f"(hi), "f"(lo));
    return r;
}

// ---------------------------------------------------------------------------
// Packing: fp32 -> bf16 hi/lo split with concatenated K.
// ---------------------------------------------------------------------------
extern "C" __global__ void pack_a(const float* __restrict__ src,
                                  __nv_bfloat16* __restrict__ dst) {
    const int r = blockIdx.x;
    for (int k = threadIdx.x; k < DMODEL; k += blockDim.x) {
        float v = src[(size_t)r * DMODEL + k];
        __nv_bfloat16 hi = __float2bfloat16(v);
        __nv_bfloat16 lo = __float2bfloat16(v - __bfloat162float(hi));
        size_t base = (size_t)r * KBIG;
        dst[base + k] = hi;
        dst[base + DMODEL + k] = lo;
        dst[base + 2 * DMODEL + k] = hi;
    }
}

extern "C" __global__ void pack_w4(const float* __restrict__ w0,
                                   const float* __restrict__ w1,
                                   const float* __restrict__ w2,
                                   const float* __restrict__ w3,
                                   __nv_bfloat16* __restrict__ d0,
                                   __nv_bfloat16* __restrict__ d1,
                                   __nv_bfloat16* __restrict__ d2,
                                   __nv_bfloat16* __restrict__ d3) {
    const int r = blockIdx.x;
    const float* src = (blockIdx.y == 0) ? w0 : (blockIdx.y == 1) ? w1
                     : (blockIdx.y == 2) ? w2 : w3;
    __nv_bfloat16* dst = (blockIdx.y == 0) ? d0 : (blockIdx.y == 1) ? d1
                       : (blockIdx.y == 2) ? d2 : d3;
    for (int k = threadIdx.x; k < DMODEL; k += blockDim.x) {
        float v = src[(size_t)r * DMODEL + k];
        __nv_bfloat16 hi = __float2bfloat16(v);
        __nv_bfloat16 lo = __float2bfloat16(v - __bfloat162float(hi));
        size_t base = (size_t)r * KBIG;
        dst[base + k] = hi;
        dst[base + DMODEL + k] = hi;
        dst[base + 2 * DMODEL + k] = lo;
    }
}

// ---------------------------------------------------------------------------
// mma.sync bf16 GEMM: C[M,1024] = Abig[M,3072] * Bbig[1024,3072]^T (fp32 acc)
// 128x128 CTA tile, 8 warps (2x4) of 64x32, BK=64, double-buffered smem.
// ---------------------------------------------------------------------------
#define GEMM_SMEM_BYTES 65536

extern "C" __global__ void __launch_bounds__(256)
gemm_bf16(const __nv_bfloat16* __restrict__ A,
          const __nv_bfloat16* __restrict__ B,
          float* __restrict__ C)
{
    extern __shared__ __align__(1024) char smem[];
    const uint32_t sbase = smem_u32(smem);

    const int tid  = threadIdx.x;
    const int wid  = tid >> 5;
    const int lane = tid & 31;
    const int n0 = blockIdx.x * 128;
    const int m0 = blockIdx.y * 128;
    const int wm = (wid >> 2) * 64;
    const int wn = (wid & 3) * 32;

    const int lrow = tid >> 3;
    const int lq   = tid & 7;
    const __nv_bfloat16* Ag = A + (size_t)(m0 + lrow) * KBIG + lq * 8;
    const __nv_bfloat16* Bg = B + (size_t)(n0 + lrow) * KBIG + lq * 8;
    const uint32_t st_off = lrow * 128 + ((lq ^ (lrow & 7)) << 4);

    uint32_t aoff[4][4], boff[4][2];
    #pragma unroll
    for (int ks = 0; ks < 4; ks++) {
        #pragma unroll
        for (int mf = 0; mf < 4; mf++) {
            int row = wm + 16 * mf + ((lane >> 3) & 1) * 8 + (lane & 7);
            int ch  = 2 * ks + (lane >> 4);
            aoff[ks][mf] = row * 128 + ((ch ^ (row & 7)) << 4);
        }
        #pragma unroll
        for (int np = 0; np < 2; np++) {
            int row = wn + 16 * np + ((lane >> 4) << 3) + (lane & 7);
            int ch  = 2 * ks + ((lane >> 3) & 1);
            boff[ks][np] = row * 128 + ((ch ^ (row & 7)) << 4);
        }
    }

    float acc[4][4][4];
    #pragma unroll
    for (int i = 0; i < 4; i++)
        #pragma unroll
        for (int j = 0; j < 4; j++)
            #pragma unroll
            for (int r = 0; r < 4; r++) acc[i][j][r] = 0.f;

    {
        #pragma unroll
        for (int j = 0; j < 4; j++) {
            uint4 va = *(const uint4*)(Ag + (size_t)32 * j * KBIG);
            uint4 vb = *(const uint4*)(Bg + (size_t)32 * j * KBIG);
            *(uint4*)(smem + st_off + j * 4096)         = va;
            *(uint4*)(smem + 16384 + st_off + j * 4096) = vb;
        }
    }
    __syncthreads();

    for (int s = 0; s < NSTAGES; s++) {
        const int buf = s & 1;
        uint4 nA[4], nB[4];
        if (s + 1 < NSTAGES) {
            const int ko = (s + 1) * BK;
            #pragma unroll
            for (int j = 0; j < 4; j++) {
                nA[j] = *(const uint4*)(Ag + (size_t)32 * j * KBIG + ko);
                nB[j] = *(const uint4*)(Bg + (size_t)32 * j * KBIG + ko);
            }
        }

        const uint32_t ab32 = sbase + buf * 32768;
        const uint32_t bb32 = ab32 + 16384;
        #pragma unroll
        for (int ks = 0; ks < 4; ks++) {
            uint32_t af[4][4], bf[2][4];
            #pragma unroll
            for (int mf = 0; mf < 4; mf++)
                ldsm_x4(af[mf], ab32 + aoff[ks][mf]);
            #pragma unroll
            for (int np = 0; np < 2; np++)
                ldsm_x4(bf[np], bb32 + boff[ks][np]);
            #pragma unroll
            for (int mf = 0; mf < 4; mf++)
                #pragma unroll
                for (int nf = 0; nf < 4; nf++)
                    mma16816(acc[mf][nf], af[mf], &bf[nf >> 1][(nf & 1) * 2]);
        }

        if (s + 1 < NSTAGES) {
            char* dst = smem + (buf ^ 1) * 32768;
            #pragma unroll
            for (int j = 0; j < 4; j++) {
                *(uint4*)(dst + st_off + j * 4096)         = nA[j];
                *(uint4*)(dst + 16384 + st_off + j * 4096) = nB[j];
            }
        }
        __syncthreads();
    }

    const int gr = lane >> 2;
    const int gc = (lane & 3) * 2;
    #pragma unroll
    for (int mf = 0; mf < 4; mf++)
        #pragma unroll
        for (int nf = 0; nf < 4; nf++) {
            const int row = m0 + wm + 16 * mf + gr;
            const int col = n0 + wn + 8 * nf + gc;
            *(float2*)&C[(size_t)row * DMODEL + col] =
                make_float2(acc[mf][nf][0], acc[mf][nf][1]);
            *(float2*)&C[(size_t)(row + 8) * DMODEL + col] =
                make_float2(acc[mf][nf][2], acc[mf][nf][3]);
        }
}

// ---------------------------------------------------------------------------
extern "C" __global__ void rope_tables()
{
    int t = blockIdx.x;
    int j = threadIdx.x;  // 0..15
    float invf = exp2f(-10.0f * (float)j * (1.0f / 15.0f));
    float theta = (float)t * invf;
    double s, c;
    sincos((double)theta, &s, &c);
    g_cos[t * 16 + j] = (float)c;
    g_sin[t * 16 + j] = (float)s;
}

// ---------------------------------------------------------------------------
// Post: v = l0*v + l1*vi ; q,k = rotary(rmsnorm(q|k)); emit bf16 hi/lo splits
// (q pre-scaled by 1/8 = 1/sqrt(hd)).
// ---------------------------------------------------------------------------
extern "C" __global__ void __launch_bounds__(64)
qkv_post(const float* __restrict__ vi, const float* __restrict__ lambdas)
{
    const int h = blockIdx.x;
    const int t = blockIdx.y;
    const int d = threadIdx.x;
    const int idx = t * DMODEL + h * HDIM + d;

    const float l0 = lambdas[0], l1 = lambdas[1];
    float vv = fmaf(l0, g_v[idx], l1 * vi[idx]);
    {
        __nv_bfloat16 vh = __float2bfloat16(vv);
        g_vhi[idx] = vh;
        g_vlo[idx] = __float2bfloat16(vv - __bfloat162float(vh));
    }

    float qv = g_q[idx], kv = g_k[idx];
    float q2 = qv * qv, k2 = kv * kv;
    #pragma unroll
    for (int o = 16; o > 0; o >>= 1) {
        q2 += __shfl_xor_sync(0xffffffffu, q2, o);
        k2 += __shfl_xor_sync(0xffffffffu, k2, o);
    }
    __shared__ float red[4];
    if ((d & 31) == 0) { red[d >> 5] = q2; red[2 + (d >> 5)] = k2; }
    __syncthreads();

    const float eps = 1.1920929e-7f;
    float qn = qv * rsqrtf((red[0] + red[1]) * (1.f / 64.f) + eps);
    float kn = kv * rsqrtf((red[2] + red[3]) * (1.f / 64.f) + eps);

    __shared__ float sq[64], sk[64];
    sq[d] = qn; sk[d] = kn;
    __syncthreads();

    const int j = d & 31;
    float c = 1.f, s = 0.f;
    if (j < 16) { c = g_cos[t * 16 + j]; s = g_sin[t * 16 + j]; }
    float oq, ok;
    if (d < 32) {
        oq =  sq[d] * c + sq[d + 32] * s;
        ok =  sk[d] * c + sk[d + 32] * s;
    } else {
        oq = -sq[j] * s + sq[d] * c;
        ok = -sk[j] * s + sk[d] * c;
    }

    float qs = oq * 0.125f;
    __nv_bfloat16 qh = __float2bfloat16(qs);
    g_qhi[idx] = qh;
    g_qlo[idx] = __float2bfloat16(qs - __bfloat162float(qh));
    __nv_bfloat16 kh = __float2bfloat16(ok);
    g_khi[idx] = kh;
    g_klo[idx] = __float2bfloat16(ok - __bfloat162float(kh));
}

// ---------------------------------------------------------------------------
// Tensor-core flash attention, causal, 64x64 tiles, hd=64, 4 warps.
// S = Qhi*Khi^T + Qlo*Khi^T + Qhi*Klo^T ; PV = Phi*Vhi + Plo*Vhi + Phi*Vlo.
// smem: Khi@0  Klo@8K  Vhi@16K  Vlo@24K (rows 128B, 16B-quad XOR swizzle).
// Q staged through Khi/Klo areas before the kt loop.
// ---------------------------------------------------------------------------
#define SW(row, q) ((row) * 128 + (((q) ^ ((row) & 7)) << 4))

__device__ __forceinline__ void load_tile64(char* dst,
                                            const __nv_bfloat16* __restrict__ src,
                                            int tid) {
    const int row = tid >> 1;
    const int qb  = (tid & 1) * 4;
    const uint4* s = (const uint4*)(src + (size_t)row * DMODEL) + qb;
    #pragma unroll
    for (int j = 0; j < 4; j++)
        *(uint4*)(dst + SW(row, qb + j)) = s[j];
}

extern "C" __global__ void __launch_bounds__(128)
flash_mma()
{
    __shared__ __align__(1024) char sm[32768];
    const uint32_t sb = smem_u32(sm);
    const uint32_t KHI = sb, KLO = sb + 8192, VHI = sb + 16384, VLO = sb + 24576;

    const int qt   = blockIdx.x;
    const int h    = blockIdx.y;
    const int tid  = threadIdx.x;
    const int lane = tid & 31;
    const int wq   = tid >> 5;          // warp -> 16-row slice
    const int q0   = qt * 64;
    const size_t hcol = (size_t)h * HDIM;

    // ---- stage Q (hi/lo) and grab fragments
    load_tile64(sm,        g_qhi + (size_t)q0 * DMODEL + hcol, tid);
    load_tile64(sm + 8192, g_qlo + (size_t)q0 * DMODEL + hcol, tid);
    __syncthreads();

    uint32_t qh[4][4], ql[4][4];
    #pragma unroll
    for (int ks = 0; ks < 4; ks++) {
        int row = wq * 16 + ((lane >> 3) & 1) * 8 + (lane & 7);
        int ch  = 2 * ks + (lane >> 4);
        uint32_t off = SW(row, ch);
        ldsm_x4(qh[ks], KHI + off);
        ldsm_x4(ql[ks], KLO + off);
    }
    __syncthreads();

    float O[8][4];
    #pragma unroll
    for (int i = 0; i < 8; i++)
        #pragma unroll
        for (int r = 0; r < 4; r++) O[i][r] = 0.f;
    float m0r = -INFINITY, m1r = -INFINITY, l0r = 0.f, l1r = 0.f;

    const int gr = lane >> 2;            // 0..7
    const int gc = 2 * (lane & 3);       // 0,2,4,6
    const int r0 = wq * 16 + gr;         // tile-local rows owned
    const int r1 = r0 + 8;

    for (int kt = 0; kt <= qt; kt++) {
        const size_t kbase = (size_t)kt * 64 * DMODEL + hcol;
        load_tile64(sm,         g_khi + kbase, tid);
        load_tile64(sm + 8192,  g_klo + kbase, tid);
        load_tile64(sm + 16384, g_vhi + kbase, tid);
        load_tile64(sm + 24576, g_vlo + kbase, tid);
        __syncthreads();

        // ---- S = Q K^T (3-term split), 64 cols in 8 n8 frags
        float S[8][4];
        #pragma unroll
        for (int i = 0; i < 8; i++)
            #pragma unroll
            for (int r = 0; r < 4; r++) S[i][r] = 0.f;

        #pragma unroll
        for (int ks = 0; ks < 4; ks++) {
            uint32_t bh[4][4], bl[4][4];
            #pragma unroll
            for (int np = 0; np < 4; np++) {
                int row = np * 16 + ((lane >> 4) << 3) + (lane & 7);
                int ch  = 2 * ks + ((lane >> 3) & 1);
                uint32_t off = SW(row, ch);
                ldsm_x4(bh[np], KHI + off);
                ldsm_x4(bl[np], KLO + off);
            }
            #pragma unroll
            for (int nf = 0; nf < 8; nf++) {
                const uint32_t* b  = &bh[nf >> 1][(nf & 1) * 2];
                const uint32_t* b2 = &bl[nf >> 1][(nf & 1) * 2];
                mma16816(S[nf], qh[ks], b);
                mma16816(S[nf], ql[ks], b);
                mma16816(S[nf], qh[ks], b2);
            }
        }

        // ---- causal mask (diagonal tile only; q0 == k0)
        if (kt == qt) {
            #pragma unroll
            for (int nf = 0; nf < 8; nf++) {
                int c0 = 8 * nf + gc;
                if (c0     > r0) S[nf][0] = -1e30f;
                if (c0 + 1 > r0) S[nf][1] = -1e30f;
                if (c0     > r1) S[nf][2] = -1e30f;
                if (c0 + 1 > r1) S[nf][3] = -1e30f;
            }
        }

        // ---- online softmax (rows r0, r1 shared by lane quads)
        float mx0 = -INFINITY, mx1 = -INFINITY;
        #pragma unroll
        for (int nf = 0; nf < 8; nf++) {
            mx0 = fmaxf(mx0, fmaxf(S[nf][0], S[nf][1]));
            mx1 = fmaxf(mx1, fmaxf(S[nf][2], S[nf][3]));
        }
        mx0 = fmaxf(mx0, __shfl_xor_sync(0xffffffffu, mx0, 1));
        mx0 = fmaxf(mx0, __shfl_xor_sync(0xffffffffu, mx0, 2));
        mx1 = fmaxf(mx1, __shfl_xor_sync(0xffffffffu, mx1, 1));
        mx1 = fmaxf(mx1, __shfl_xor_sync(0xffffffffu, mx1, 2));

        const float mn0 = fmaxf(m0r, mx0);
        const float mn1 = fmaxf(m1r, mx1);
        const float a0 = __expf(m0r - mn0);
        const float a1 = __expf(m1r - mn1);

        float s0 = 0.f, s1 = 0.f;
        uint32_t Ahi[4][4], Alo[4][4];
        #pragma unroll
        for (int js = 0; js < 4; js++) {
            #pragma unroll
            for (int half = 0; half < 2; half++) {
                const int nf = 2 * js + half;
                float p0 = __expf(S[nf][0] - mn0);
                float p1 = __expf(S[nf][1] - mn0);
                float p2 = __expf(S[nf][2] - mn1);
                float p3 = __expf(S[nf][3] - mn1);
                s0 += p0 + p1;
                s1 += p2 + p3;
                float h0 = __bfloat162float(__float2bfloat16(p0));
                float h1 = __bfloat162float(__float2bfloat16(p1));
                float h2 = __bfloat162float(__float2bfloat16(p2));
                float h3 = __bfloat162float(__float2bfloat16(p3));
                Ahi[js][half * 2 + 0] = pack_bf16x2(h0, h1);
                Ahi[js][half * 2 + 1] = pack_bf16x2(h2, h3);
                Alo[js][half * 2 + 0] = pack_bf16x2(p0 - h0, p1 - h1);
                Alo[js][half * 2 + 1] = pack_bf16x2(p2 - h2, p3 - h3);
            }
        }
        s0 += __shfl_xor_sync(0xffffffffu, s0, 1);
        s0 += __shfl_xor_sync(0xffffffffu, s0, 2);
        s1 += __shfl_xor_sync(0xffffffffu, s1, 1);
        s1 += __shfl_xor_sync(0xffffffffu, s1, 2);
        l0r = l0r * a0 + s0;
        l1r = l1r * a1 + s1;
        m0r = mn0;
        m1r = mn1;

        // ---- O = O*alpha + P V (3-term split)
        #pragma unroll
        for (int nf = 0; nf < 8; nf++) {
            O[nf][0] *= a0; O[nf][1] *= a0;
            O[nf][2] *= a1; O[nf][3] *= a1;
        }
        #pragma unroll
        for (int js = 0; js < 4; js++) {
            uint32_t vh[4][4], vl[4][4];
            #pragma unroll
            for (int np = 0; np < 4; np++) {
                int row = js * 16 + ((lane >> 3) & 1) * 8 + (lane & 7);
                int ch  = 2 * np + (lane >> 4);
                uint32_t off = SW(row, ch);
                ldsm_x4_t(vh[np], VHI + off);
                ldsm_x4_t(vl[np], VLO + off);
            }
            #pragma unroll
            for (int nf = 0; nf < 8; nf++) {
                const uint32_t* b  = &vh[nf >> 1][(nf & 1) * 2];
                const uint32_t* b2 = &vl[nf >> 1][(nf & 1) * 2];
                mma16816(O[nf], Ahi[js], b);
                mma16816(O[nf], Alo[js], b);
                mma16816(O[nf], Ahi[js], b2);
            }
        }
        __syncthreads();
    }

    // ---- epilogue
    const float i0 = 1.f / l0r;
    const float i1 = 1.f / l1r;
    #pragma unroll
    for (int nf = 0; nf < 8; nf++) {
        const size_t col = hcol + 8 * nf + gc;
        *(float2*)&g_y[(size_t)(q0 + r0) * DMODEL + col] =
            make_float2(O[nf][0] * i0, O[nf][1] * i0);
        *(float2*)&g_y[(size_t)(q0 + r1) * DMODEL + col] =
            make_float2(O[nf][2] * i1, O[nf][3] * i1);
    }
}

// ---------------------------------------------------------------------------
extern "C" void kernel_launch(void* const* d_in, const int* in_sizes, int n_in,
                              void* d_out, int out_size)
{
    const float* x   = (const float*)d_in[0];
    const float* vi  = (const float*)d_in[1];
    const float* Wq  = (const float*)d_in[2];
    const float* Wk  = (const float*)d_in[3];
    const float* Wv  = (const float*)d_in[4];
    const float* Wp  = (const float*)d_in[5];
    const float* lam = (const float*)d_in[6];
    float* out = (float*)d_out;

    float *gq, *gk, *gv, *gy;
    __nv_bfloat16 *gA, *gWq, *gWk, *gWv, *gWp;
    cudaGetSymbolAddress((void**)&gq, g_q);
    cudaGetSymbolAddress((void**)&gk, g_k);
    cudaGetSymbolAddress((void**)&gv, g_v);
    cudaGetSymbolAddress((void**)&gy, g_y);
    cudaGetSymbolAddress((void**)&gA, g_Abig);
    cudaGetSymbolAddress((void**)&gWq, g_Wqb);
    cudaGetSymbolAddress((void**)&gWk, g_Wkb);
    cudaGetSymbolAddress((void**)&gWv, g_Wvb);
    cudaGetSymbolAddress((void**)&gWp, g_Wpb);

    cudaFuncSetAttribute(gemm_bf16, cudaFuncAttributeMaxDynamicSharedMemorySize,
                         GEMM_SMEM_BYTES);

    pack_w4<<<dim3(DMODEL, 4), 256>>>(Wq, Wk, Wv, Wp, gWq, gWk, gWv, gWp);
    pack_a<<<T_SEQ, 256>>>(x, gA);

    dim3 ggrid(DMODEL / 128, T_SEQ / 128);
    gemm_bf16<<<ggrid, 256, GEMM_SMEM_BYTES>>>(gA, gWq, gq);
    gemm_bf16<<<ggrid, 256, GEMM_SMEM_BYTES>>>(gA, gWk, gk);
    gemm_bf16<<<ggrid, 256, GEMM_SMEM_BYTES>>>(gA, gWv, gv);

    rope_tables<<<T_SEQ, 16>>>();
    qkv_post<<<dim3(NHEADS, T_SEQ), 64>>>(vi, lam);

    flash_mma<<<dim3(T_SEQ / 64, NHEADS), 128>>>();

    pack_a<<<T_SEQ, 256>>>(gy, gA);
    gemm_bf16<<<ggrid, 256, GEMM_SMEM_BYTES>>>(gA, gWp, out);
}

// round 5
// speedup vs baseline: 3.1932x; 1.1217x over previous
#include <cuda_runtime.h>
#include <cuda_bf16.h>
#include <math.h>
#include <stdint.h>

#define T_SEQ  2048
#define DMODEL 1024
#define NHEADS 16
#define HDIM   64
#define KBIG   3072              // [hi | lo | hi] x [hi | hi | lo]
#define BK     64
#define NSTAGES (KBIG / BK)      // 48
#define NPIPE  3

// ---------------------------------------------------------------------------
// Scratch (static device globals — no allocation allowed in kernel_launch)
// ---------------------------------------------------------------------------
__device__ float g_q[T_SEQ * DMODEL];
__device__ float g_k[T_SEQ * DMODEL];
__device__ float g_v[T_SEQ * DMODEL];
__device__ float g_y[T_SEQ * DMODEL];
__device__ float g_cos[T_SEQ * 16];
__device__ float g_sin[T_SEQ * 16];
__device__ __align__(16) __nv_bfloat16 g_Abig[T_SEQ * KBIG];
__device__ __align__(16) __nv_bfloat16 g_Wqkv[3 * DMODEL * KBIG];
__device__ __align__(16) __nv_bfloat16 g_Wpb[DMODEL * KBIG];
// bf16 hi/lo splits for attention (q pre-scaled by 1/8)
__device__ __align__(16) __nv_bfloat16 g_qhi[T_SEQ * DMODEL];
__device__ __align__(16) __nv_bfloat16 g_qlo[T_SEQ * DMODEL];
__device__ __align__(16) __nv_bfloat16 g_khi[T_SEQ * DMODEL];
__device__ __align__(16) __nv_bfloat16 g_klo[T_SEQ * DMODEL];
__device__ __align__(16) __nv_bfloat16 g_vhi[T_SEQ * DMODEL];
__device__ __align__(16) __nv_bfloat16 g_vlo[T_SEQ * DMODEL];

// ---------------------------------------------------------------------------
__device__ __forceinline__ uint32_t smem_u32(const void* p) {
    uint32_t a;
    asm("{ .reg .u64 t; cvta.to.shared.u64 t, %1; cvt.u32.u64 %0, t; }"
        : "=r"(a) : "l"(p));
    return a;
}

__device__ __forceinline__ void ldsm_x4(uint32_t* r, uint32_t addr) {
    asm volatile("ldmatrix.sync.aligned.m8n8.x4.shared.b16 {%0,%1,%2,%3}, [%4];"
                 : "=r"(r[0]), "=r"(r[1]), "=r"(r[2]), "=r"(r[3]) : "r"(addr));
}

__device__ __forceinline__ void ldsm_x4_t(uint32_t* r, uint32_t addr) {
    asm volatile("ldmatrix.sync.aligned.m8n8.x4.trans.shared.b16 {%0,%1,%2,%3}, [%4];"
                 : "=r"(r[0]), "=r"(r[1]), "=r"(r[2]), "=r"(r[3]) : "r"(addr));
}

__device__ __forceinline__ void mma16816(float* d, const uint32_t* a,
                                         const uint32_t* b) {
    asm volatile(
        "mma.sync.aligned.m16n8k16.row.col.f32.bf16.bf16.f32 "
        "{%0,%1,%2,%3}, {%4,%5,%6,%7}, {%8,%9}, {%0,%1,%2,%3};"
        : "+f"(d[0]), "+f"(d[1]), "+f"(d[2]), "+f"(d[3])
        : "r"(a[0]), "r"(a[1]), "r"(a[2]), "r"(a[3]), "r"(b[0]), "r"(b[1]));
}

__device__ __forceinline__ uint32_t pack_bf16x2(float lo, float hi) {
    uint32_t r;
    asm("cvt.rn.bf16x2.f32 %0, %1, %2;" : "=r"(r) : "f"(hi), "f"(lo));
    return r;
}

__device__ __forceinline__ void cp_async16(uint32_t dst, const void* src) {
    asm volatile("cp.async.cg.shared.global [%0], [%1], 16;"
                 :: "r"(dst), "l"(src));
}
#define CP_COMMIT() asm volatile("cp.async.commit_group;" ::: "memory")
#define CP_WAIT(n)  asm volatile("cp.async.wait_group %0;" :: "n"(n) : "memory")

// ---------------------------------------------------------------------------
// Packing: fp32 -> bf16 hi/lo split with concatenated K.
// ---------------------------------------------------------------------------
extern "C" __global__ void pack_a(const float* __restrict__ src,
                                  __nv_bfloat16* __restrict__ dst) {
    const int r = blockIdx.x;
    for (int k = threadIdx.x; k < DMODEL; k += blockDim.x) {
        float v = src[(size_t)r * DMODEL + k];
        __nv_bfloat16 hi = __float2bfloat16(v);
        __nv_bfloat16 lo = __float2bfloat16(v - __bfloat162float(hi));
        size_t base = (size_t)r * KBIG;
        dst[base + k] = hi;
        dst[base + DMODEL + k] = lo;
        dst[base + 2 * DMODEL + k] = hi;
    }
}

// y = 0,1,2 -> rows y*1024+r of g_Wqkv ; y = 3 -> g_Wpb
extern "C" __global__ void pack_w4(const float* __restrict__ w0,
                                   const float* __restrict__ w1,
                                   const float* __restrict__ w2,
                                   const float* __restrict__ w3,
                                   __nv_bfloat16* __restrict__ dqkv,
                                   __nv_bfloat16* __restrict__ dp) {
    const int r = blockIdx.x;
    const int y = blockIdx.y;
    const float* src = (y == 0) ? w0 : (y == 1) ? w1 : (y == 2) ? w2 : w3;
    __nv_bfloat16* dst = (y == 3) ? (dp + (size_t)r * KBIG)
                                  : (dqkv + (size_t)(y * DMODEL + r) * KBIG);
    for (int k = threadIdx.x; k < DMODEL; k += blockDim.x) {
        float v = src[(size_t)r * DMODEL + k];
        __nv_bfloat16 hi = __float2bfloat16(v);
        __nv_bfloat16 lo = __float2bfloat16(v - __bfloat162float(hi));
        dst[k] = hi;
        dst[DMODEL + k] = hi;
        dst[2 * DMODEL + k] = lo;
    }
}

// ---------------------------------------------------------------------------
// mma.sync bf16 GEMM with cp.async 3-stage pipeline.
// C_sel[M,1024] = A[M,KBIG] * B[NB,KBIG]^T, 128x128 CTA tile, 8 warps.
// Output CTA tile routed to C0/C1/C2 by n0>>10 (fused QKV) — for the proj
// GEMM all three point at the same buffer.
// smem: NPIPE stages of 32KB (A 16K | B 16K), 16B-quad XOR swizzle rows.
// ---------------------------------------------------------------------------
#define GEMM_SMEM_BYTES (NPIPE * 32768)

extern "C" __global__ void __launch_bounds__(256)
gemm_bf16(const __nv_bfloat16* __restrict__ A,
          const __nv_bfloat16* __restrict__ B,
          float* __restrict__ C0, float* __restrict__ C1,
          float* __restrict__ C2)
{
    extern __shared__ __align__(1024) char smem[];
    const uint32_t sbase = smem_u32(smem);

    const int tid  = threadIdx.x;
    const int wid  = tid >> 5;
    const int lane = tid & 31;
    const int n0 = blockIdx.x * 128;
    const int m0 = blockIdx.y * 128;
    const int wm = (wid >> 2) * 64;
    const int wn = (wid & 3) * 32;

    const int lrow = tid >> 3;
    const int lq   = tid & 7;
    const __nv_bfloat16* Ag = A + (size_t)(m0 + lrow) * KBIG + lq * 8;
    const __nv_bfloat16* Bg = B + (size_t)(n0 + lrow) * KBIG + lq * 8;
    const uint32_t st_off = lrow * 128 + ((lq ^ (lrow & 7)) << 4);

    uint32_t aoff[4][4], boff[4][2];
    #pragma unroll
    for (int ks = 0; ks < 4; ks++) {
        #pragma unroll
        for (int mf = 0; mf < 4; mf++) {
            int row = wm + 16 * mf + ((lane >> 3) & 1) * 8 + (lane & 7);
            int ch  = 2 * ks + (lane >> 4);
            aoff[ks][mf] = row * 128 + ((ch ^ (row & 7)) << 4);
        }
        #pragma unroll
        for (int np = 0; np < 2; np++) {
            int row = wn + 16 * np + ((lane >> 4) << 3) + (lane & 7);
            int ch  = 2 * ks + ((lane >> 3) & 1);
            boff[ks][np] = row * 128 + ((ch ^ (row & 7)) << 4);
        }
    }

    float acc[4][4][4];
    #pragma unroll
    for (int i = 0; i < 4; i++)
        #pragma unroll
        for (int j = 0; j < 4; j++)
            #pragma unroll
            for (int r = 0; r < 4; r++) acc[i][j][r] = 0.f;

    // stage issue: 4 A-quads + 4 B-quads per thread via cp.async
    auto issue = [&](int s) {
        const uint32_t dst = sbase + (s % NPIPE) * 32768 + st_off;
        const size_t ko = (size_t)s * BK;
        #pragma unroll
        for (int j = 0; j < 4; j++) {
            cp_async16(dst + j * 4096,         Ag + (size_t)32 * j * KBIG + ko);
            cp_async16(dst + 16384 + j * 4096, Bg + (size_t)32 * j * KBIG + ko);
        }
        CP_COMMIT();
    };

    #pragma unroll
    for (int s = 0; s < NPIPE - 1; s++) issue(s);

    for (int s = 0; s < NSTAGES; s++) {
        if (s + 1 < NSTAGES) { CP_WAIT(NPIPE - 2); } else { CP_WAIT(0); }
        __syncthreads();
        if (s + NPIPE - 1 < NSTAGES) issue(s + NPIPE - 1);

        const uint32_t ab32 = sbase + (s % NPIPE) * 32768;
        const uint32_t bb32 = ab32 + 16384;
        #pragma unroll
        for (int ks = 0; ks < 4; ks++) {
            uint32_t af[4][4], bf[2][4];
            #pragma unroll
            for (int mf = 0; mf < 4; mf++)
                ldsm_x4(af[mf], ab32 + aoff[ks][mf]);
            #pragma unroll
            for (int np = 0; np < 2; np++)
                ldsm_x4(bf[np], bb32 + boff[ks][np]);
            #pragma unroll
            for (int mf = 0; mf < 4; mf++)
                #pragma unroll
                for (int nf = 0; nf < 4; nf++)
                    mma16816(acc[mf][nf], af[mf], &bf[nf >> 1][(nf & 1) * 2]);
        }
        __syncthreads();
    }

    const int sel = n0 >> 10;
    float* __restrict__ C = (sel == 0) ? C0 : (sel == 1) ? C1 : C2;
    const int nl = n0 & 1023;
    const int gr = lane >> 2;
    const int gc = (lane & 3) * 2;
    #pragma unroll
    for (int mf = 0; mf < 4; mf++)
        #pragma unroll
        for (int nf = 0; nf < 4; nf++) {
            const int row = m0 + wm + 16 * mf + gr;
            const int col = nl + wn + 8 * nf + gc;
            *(float2*)&C[(size_t)row * DMODEL + col] =
                make_float2(acc[mf][nf][0], acc[mf][nf][1]);
            *(float2*)&C[(size_t)(row + 8) * DMODEL + col] =
                make_float2(acc[mf][nf][2], acc[mf][nf][3]);
        }
}

// ---------------------------------------------------------------------------
extern "C" __global__ void rope_tables()
{
    int t = blockIdx.x;
    int j = threadIdx.x;  // 0..15
    float invf = exp2f(-10.0f * (float)j * (1.0f / 15.0f));
    float theta = (float)t * invf;
    double s, c;
    sincos((double)theta, &s, &c);
    g_cos[t * 16 + j] = (float)c;
    g_sin[t * 16 + j] = (float)s;
}

// ---------------------------------------------------------------------------
// Post: v = l0*v + l1*vi ; q,k = rotary(rmsnorm(q|k)); emit bf16 hi/lo splits
// (q pre-scaled by 1/8 = 1/sqrt(hd)).
// ---------------------------------------------------------------------------
extern "C" __global__ void __launch_bounds__(64)
qkv_post(const float* __restrict__ vi, const float* __restrict__ lambdas)
{
    const int h = blockIdx.x;
    const int t = blockIdx.y;
    const int d = threadIdx.x;
    const int idx = t * DMODEL + h * HDIM + d;

    const float l0 = lambdas[0], l1 = lambdas[1];
    float vv = fmaf(l0, g_v[idx], l1 * vi[idx]);
    {
        __nv_bfloat16 vh = __float2bfloat16(vv);
        g_vhi[idx] = vh;
        g_vlo[idx] = __float2bfloat16(vv - __bfloat162float(vh));
    }

    float qv = g_q[idx], kv = g_k[idx];
    float q2 = qv * qv, k2 = kv * kv;
    #pragma unroll
    for (int o = 16; o > 0; o >>= 1) {
        q2 += __shfl_xor_sync(0xffffffffu, q2, o);
        k2 += __shfl_xor_sync(0xffffffffu, k2, o);
    }
    __shared__ float red[4];
    if ((d & 31) == 0) { red[d >> 5] = q2; red[2 + (d >> 5)] = k2; }
    __syncthreads();

    const float eps = 1.1920929e-7f;
    float qn = qv * rsqrtf((red[0] + red[1]) * (1.f / 64.f) + eps);
    float kn = kv * rsqrtf((red[2] + red[3]) * (1.f / 64.f) + eps);

    __shared__ float sq[64], sk[64];
    sq[d] = qn; sk[d] = kn;
    __syncthreads();

    const int j = d & 31;
    float c = 1.f, s = 0.f;
    if (j < 16) { c = g_cos[t * 16 + j]; s = g_sin[t * 16 + j]; }
    float oq, ok;
    if (d < 32) {
        oq =  sq[d] * c + sq[d + 32] * s;
        ok =  sk[d] * c + sk[d + 32] * s;
    } else {
        oq = -sq[j] * s + sq[d] * c;
        ok = -sk[j] * s + sk[d] * c;
    }

    float qs = oq * 0.125f;
    __nv_bfloat16 qh = __float2bfloat16(qs);
    g_qhi[idx] = qh;
    g_qlo[idx] = __float2bfloat16(qs - __bfloat162float(qh));
    __nv_bfloat16 kh = __float2bfloat16(ok);
    g_khi[idx] = kh;
    g_klo[idx] = __float2bfloat16(ok - __bfloat162float(kh));
}

// ---------------------------------------------------------------------------
// Tensor-core flash attention, causal, 64x64 tiles, hd=64, 4 warps.
// ---------------------------------------------------------------------------
#define SW(row, q) ((row) * 128 + (((q) ^ ((row) & 7)) << 4))

__device__ __forceinline__ void load_tile64(char* dst,
                                            const __nv_bfloat16* __restrict__ src,
                                            int tid) {
    const int row = tid >> 1;
    const int qb  = (tid & 1) * 4;
    const uint4* s = (const uint4*)(src + (size_t)row * DMODEL) + qb;
    #pragma unroll
    for (int j = 0; j < 4; j++)
        *(uint4*)(dst + SW(row, qb + j)) = s[j];
}

extern "C" __global__ void __launch_bounds__(128)
flash_mma()
{
    __shared__ __align__(1024) char sm[32768];
    const uint32_t sb = smem_u32(sm);
    const uint32_t KHI = sb, KLO = sb + 8192, VHI = sb + 16384, VLO = sb + 24576;

    const int qt   = blockIdx.x;
    const int h    = blockIdx.y;
    const int tid  = threadIdx.x;
    const int lane = tid & 31;
    const int wq   = tid >> 5;
    const int q0   = qt * 64;
    const size_t hcol = (size_t)h * HDIM;

    load_tile64(sm,        g_qhi + (size_t)q0 * DMODEL + hcol, tid);
    load_tile64(sm + 8192, g_qlo + (size_t)q0 * DMODEL + hcol, tid);
    __syncthreads();

    uint32_t qh[4][4], ql[4][4];
    #pragma unroll
    for (int ks = 0; ks < 4; ks++) {
        int row = wq * 16 + ((lane >> 3) & 1) * 8 + (lane & 7);
        int ch  = 2 * ks + (lane >> 4);
        uint32_t off = SW(row, ch);
        ldsm_x4(qh[ks], KHI + off);
        ldsm_x4(ql[ks], KLO + off);
    }
    __syncthreads();

    float O[8][4];
    #pragma unroll
    for (int i = 0; i < 8; i++)
        #pragma unroll
        for (int r = 0; r < 4; r++) O[i][r] = 0.f;
    float m0r = -INFINITY, m1r = -INFINITY, l0r = 0.f, l1r = 0.f;

    const int gr = lane >> 2;
    const int gc = 2 * (lane & 3);
    const int r0 = wq * 16 + gr;
    const int r1 = r0 + 8;

    for (int kt = 0; kt <= qt; kt++) {
        const size_t kbase = (size_t)kt * 64 * DMODEL + hcol;
        load_tile64(sm,         g_khi + kbase, tid);
        load_tile64(sm + 8192,  g_klo + kbase, tid);
        load_tile64(sm + 16384, g_vhi + kbase, tid);
        load_tile64(sm + 24576, g_vlo + kbase, tid);
        __syncthreads();

        float S[8][4];
        #pragma unroll
        for (int i = 0; i < 8; i++)
            #pragma unroll
            for (int r = 0; r < 4; r++) S[i][r] = 0.f;

        #pragma unroll
        for (int ks = 0; ks < 4; ks++) {
            uint32_t bh[4][4], bl[4][4];
            #pragma unroll
            for (int np = 0; np < 4; np++) {
                int row = np * 16 + ((lane >> 4) << 3) + (lane & 7);
                int ch  = 2 * ks + ((lane >> 3) & 1);
                uint32_t off = SW(row, ch);
                ldsm_x4(bh[np], KHI + off);
                ldsm_x4(bl[np], KLO + off);
            }
            #pragma unroll
            for (int nf = 0; nf < 8; nf++) {
                const uint32_t* b  = &bh[nf >> 1][(nf & 1) * 2];
                const uint32_t* b2 = &bl[nf >> 1][(nf & 1) * 2];
                mma16816(S[nf], qh[ks], b);
                mma16816(S[nf], ql[ks], b);
                mma16816(S[nf], qh[ks], b2);
            }
        }

        if (kt == qt) {
            #pragma unroll
            for (int nf = 0; nf < 8; nf++) {
                int c0 = 8 * nf + gc;
                if (c0     > r0) S[nf][0] = -1e30f;
                if (c0 + 1 > r0) S[nf][1] = -1e30f;
                if (c0     > r1) S[nf][2] = -1e30f;
                if (c0 + 1 > r1) S[nf][3] = -1e30f;
            }
        }

        float mx0 = -INFINITY, mx1 = -INFINITY;
        #pragma unroll
        for (int nf = 0; nf < 8; nf++) {
            mx0 = fmaxf(mx0, fmaxf(S[nf][0], S[nf][1]));
            mx1 = fmaxf(mx1, fmaxf(S[nf][2], S[nf][3]));
        }
        mx0 = fmaxf(mx0, __shfl_xor_sync(0xffffffffu, mx0, 1));
        mx0 = fmaxf(mx0, __shfl_xor_sync(0xffffffffu, mx0, 2));
        mx1 = fmaxf(mx1, __shfl_xor_sync(0xffffffffu, mx1, 1));
        mx1 = fmaxf(mx1, __shfl_xor_sync(0xffffffffu, mx1, 2));

        const float mn0 = fmaxf(m0r, mx0);
        const float mn1 = fmaxf(m1r, mx1);
        const float a0 = __expf(m0r - mn0);
        const float a1 = __expf(m1r - mn1);

        float s0 = 0.f, s1 = 0.f;
        uint32_t Ahi[4][4], Alo[4][4];
        #pragma unroll
        for (int js = 0; js < 4; js++) {
            #pragma unroll
            for (int half = 0; half < 2; half++) {
                const int nf = 2 * js + half;
                float p0 = __expf(S[nf][0] - mn0);
                float p1 = __expf(S[nf][1] - mn0);
                float p2 = __expf(S[nf][2] - mn1);
                float p3 = __expf(S[nf][3] - mn1);
                s0 += p0 + p1;
                s1 += p2 + p3;
                float h0 = __bfloat162float(__float2bfloat16(p0));
                float h1 = __bfloat162float(__float2bfloat16(p1));
                float h2 = __bfloat162float(__float2bfloat16(p2));
                float h3 = __bfloat162float(__float2bfloat16(p3));
                Ahi[js][half * 2 + 0] = pack_bf16x2(h0, h1);
                Ahi[js][half * 2 + 1] = pack_bf16x2(h2, h3);
                Alo[js][half * 2 + 0] = pack_bf16x2(p0 - h0, p1 - h1);
                Alo[js][half * 2 + 1] = pack_bf16x2(p2 - h2, p3 - h3);
            }
        }
        s0 += __shfl_xor_sync(0xffffffffu, s0, 1);
        s0 += __shfl_xor_sync(0xffffffffu, s0, 2);
        s1 += __shfl_xor_sync(0xffffffffu, s1, 1);
        s1 += __shfl_xor_sync(0xffffffffu, s1, 2);
        l0r = l0r * a0 + s0;
        l1r = l1r * a1 + s1;
        m0r = mn0;
        m1r = mn1;

        #pragma unroll
        for (int nf = 0; nf < 8; nf++) {
            O[nf][0] *= a0; O[nf][1] *= a0;
            O[nf][2] *= a1; O[nf][3] *= a1;
        }
        #pragma unroll
        for (int js = 0; js < 4; js++) {
            uint32_t vh[4][4], vl[4][4];
            #pragma unroll
            for (int np = 0; np < 4; np++) {
                int row = js * 16 + ((lane >> 3) & 1) * 8 + (lane & 7);
                int ch  = 2 * np + (lane >> 4);
                uint32_t off = SW(row, ch);
                ldsm_x4_t(vh[np], VHI + off);
                ldsm_x4_t(vl[np], VLO + off);
            }
            #pragma unroll
            for (int nf = 0; nf < 8; nf++) {
                const uint32_t* b  = &vh[nf >> 1][(nf & 1) * 2];
                const uint32_t* b2 = &vl[nf >> 1][(nf & 1) * 2];
                mma16816(O[nf], Ahi[js], b);
                mma16816(O[nf], Alo[js], b);
                mma16816(O[nf], Ahi[js], b2);
            }
        }
        __syncthreads();
    }

    const float i0 = 1.f / l0r;
    const float i1 = 1.f / l1r;
    #pragma unroll
    for (int nf = 0; nf < 8; nf++) {
        const size_t col = hcol + 8 * nf + gc;
        *(float2*)&g_y[(size_t)(q0 + r0) * DMODEL + col] =
            make_float2(O[nf][0] * i0, O[nf][1] * i0);
        *(float2*)&g_y[(size_t)(q0 + r1) * DMODEL + col] =
            make_float2(O[nf][2] * i1, O[nf][3] * i1);
    }
}

// ---------------------------------------------------------------------------
extern "C" void kernel_launch(void* const* d_in, const int* in_sizes, int n_in,
                              void* d_out, int out_size)
{
    const float* x   = (const float*)d_in[0];
    const float* vi  = (const float*)d_in[1];
    const float* Wq  = (const float*)d_in[2];
    const float* Wk  = (const float*)d_in[3];
    const float* Wv  = (const float*)d_in[4];
    const float* Wp  = (const float*)d_in[5];
    const float* lam = (const float*)d_in[6];
    float* out = (float*)d_out;

    float *gq, *gk, *gv, *gy;
    __nv_bfloat16 *gA, *gWqkv, *gWp;
    cudaGetSymbolAddress((void**)&gq, g_q);
    cudaGetSymbolAddress((void**)&gk, g_k);
    cudaGetSymbolAddress((void**)&gv, g_v);
    cudaGetSymbolAddress((void**)&gy, g_y);
    cudaGetSymbolAddress((void**)&gA, g_Abig);
    cudaGetSymbolAddress((void**)&gWqkv, g_Wqkv);
    cudaGetSymbolAddress((void**)&gWp, g_Wpb);

    cudaFuncSetAttribute(gemm_bf16, cudaFuncAttributeMaxDynamicSharedMemorySize,
                         GEMM_SMEM_BYTES);

    pack_w4<<<dim3(DMODEL, 4), 256>>>(Wq, Wk, Wv, Wp, gWqkv, gWp);
    pack_a<<<T_SEQ, 256>>>(x, gA);

    // fused QKV: N = 3072
    gemm_bf16<<<dim3(3 * DMODEL / 128, T_SEQ / 128), 256, GEMM_SMEM_BYTES>>>(
        gA, gWqkv, gq, gk, gv);

    rope_tables<<<T_SEQ, 16>>>();
    qkv_post<<<dim3(NHEADS, T_SEQ), 64>>>(vi, lam);

    flash_mma<<<dim3(T_SEQ / 64, NHEADS), 128>>>();

    pack_a<<<T_SEQ, 256>>>(gy, gA);
    gemm_bf16<<<dim3(DMODEL / 128, T_SEQ / 128), 256, GEMM_SMEM_BYTES>>>(
        gA, gWp, out, out, out);
}

// round 6
// speedup vs baseline: 3.2559x; 1.0196x over previous
#include <cuda_runtime.h>
#include <cuda_bf16.h>
#include <math.h>
#include <stdint.h>

#define T_SEQ  2048
#define DMODEL 1024
#define NHEADS 16
#define HDIM   64
#define KBIG   3072              // [hi | lo | hi] x [hi | hi | lo]
#define BK     64
#define NSTAGES (KBIG / BK)      // 48
#define NPIPE  3

// ---------------------------------------------------------------------------
// Scratch (static device globals — no allocation allowed in kernel_launch)
// ---------------------------------------------------------------------------
__device__ float g_q[T_SEQ * DMODEL];
__device__ float g_k[T_SEQ * DMODEL];
__device__ float g_v[T_SEQ * DMODEL];
__device__ float g_cos[T_SEQ * 16];
__device__ float g_sin[T_SEQ * 16];
__device__ __align__(16) __nv_bfloat16 g_Abig[T_SEQ * KBIG];
__device__ __align__(16) __nv_bfloat16 g_Wqkv[3 * DMODEL * KBIG];
__device__ __align__(16) __nv_bfloat16 g_Wpb[DMODEL * KBIG];
// bf16 hi/lo splits for attention (q pre-scaled by 1/8)
__device__ __align__(16) __nv_bfloat16 g_qhi[T_SEQ * DMODEL];
__device__ __align__(16) __nv_bfloat16 g_qlo[T_SEQ * DMODEL];
__device__ __align__(16) __nv_bfloat16 g_khi[T_SEQ * DMODEL];
__device__ __align__(16) __nv_bfloat16 g_klo[T_SEQ * DMODEL];
__device__ __align__(16) __nv_bfloat16 g_vhi[T_SEQ * DMODEL];
__device__ __align__(16) __nv_bfloat16 g_vlo[T_SEQ * DMODEL];

// ---------------------------------------------------------------------------
__device__ __forceinline__ uint32_t smem_u32(const void* p) {
    uint32_t a;
    asm("{ .reg .u64 t; cvta.to.shared.u64 t, %1; cvt.u32.u64 %0, t; }"
        : "=r"(a) : "l"(p));
    return a;
}

__device__ __forceinline__ void ldsm_x4(uint32_t* r, uint32_t addr) {
    asm volatile("ldmatrix.sync.aligned.m8n8.x4.shared.b16 {%0,%1,%2,%3}, [%4];"
                 : "=r"(r[0]), "=r"(r[1]), "=r"(r[2]), "=r"(r[3]) : "r"(addr));
}

__device__ __forceinline__ void ldsm_x4_t(uint32_t* r, uint32_t addr) {
    asm volatile("ldmatrix.sync.aligned.m8n8.x4.trans.shared.b16 {%0,%1,%2,%3}, [%4];"
                 : "=r"(r[0]), "=r"(r[1]), "=r"(r[2]), "=r"(r[3]) : "r"(addr));
}

__device__ __forceinline__ void mma16816(float* d, const uint32_t* a,
                                         const uint32_t* b) {
    asm volatile(
        "mma.sync.aligned.m16n8k16.row.col.f32.bf16.bf16.f32 "
        "{%0,%1,%2,%3}, {%4,%5,%6,%7}, {%8,%9}, {%0,%1,%2,%3};"
        : "+f"(d[0]), "+f"(d[1]), "+f"(d[2]), "+f"(d[3])
        : "r"(a[0]), "r"(a[1]), "r"(a[2]), "r"(a[3]), "r"(b[0]), "r"(b[1]));
}

__device__ __forceinline__ uint32_t pack_bf16x2(float lo, float hi) {
    uint32_t r;
    asm("cvt.rn.bf16x2.f32 %0, %1, %2;" : "=r"(r) : "f"(hi), "f"(lo));
    return r;
}

__device__ __forceinline__ void cp_async16(uint32_t dst, const void* src) {
    asm volatile("cp.async.cg.shared.global [%0], [%1], 16;"
                 :: "r"(dst), "l"(src));
}
#define CP_COMMIT() asm volatile("cp.async.commit_group;" ::: "memory")
#define CP_WAIT(n)  asm volatile("cp.async.wait_group %0;" :: "n"(n) : "memory")

// ---------------------------------------------------------------------------
// Packing: fp32 -> bf16 hi/lo split with concatenated K.
// ---------------------------------------------------------------------------
extern "C" __global__ void pack_a(const float* __restrict__ src,
                                  __nv_bfloat16* __restrict__ dst) {
    const int r = blockIdx.x;
    for (int k = threadIdx.x; k < DMODEL; k += blockDim.x) {
        float v = src[(size_t)r * DMODEL + k];
        __nv_bfloat16 hi = __float2bfloat16(v);
        __nv_bfloat16 lo = __float2bfloat16(v - __bfloat162float(hi));
        size_t base = (size_t)r * KBIG;
        dst[base + k] = hi;
        dst[base + DMODEL + k] = lo;
        dst[base + 2 * DMODEL + k] = hi;
    }
}

// y = 0,1,2 -> rows y*1024+r of g_Wqkv ; y = 3 -> g_Wpb
extern "C" __global__ void pack_w4(const float* __restrict__ w0,
                                   const float* __restrict__ w1,
                                   const float* __restrict__ w2,
                                   const float* __restrict__ w3,
                                   __nv_bfloat16* __restrict__ dqkv,
                                   __nv_bfloat16* __restrict__ dp) {
    const int r = blockIdx.x;
    const int y = blockIdx.y;
    const float* src = (y == 0) ? w0 : (y == 1) ? w1 : (y == 2) ? w2 : w3;
    __nv_bfloat16* dst = (y == 3) ? (dp + (size_t)r * KBIG)
                                  : (dqkv + (size_t)(y * DMODEL + r) * KBIG);
    for (int k = threadIdx.x; k < DMODEL; k += blockDim.x) {
        float v = src[(size_t)r * DMODEL + k];
        __nv_bfloat16 hi = __float2bfloat16(v);
        __nv_bfloat16 lo = __float2bfloat16(v - __bfloat162float(hi));
        dst[k] = hi;
        dst[DMODEL + k] = hi;
        dst[2 * DMODEL + k] = lo;
    }
}

// ---------------------------------------------------------------------------
// mma.sync bf16 GEMM with cp.async 3-stage pipeline, 2 CTAs/SM.
// C_sel[M,1024] = A[M,KBIG] * B[NB,KBIG]^T, 128x128 CTA tile, 8 warps.
// ---------------------------------------------------------------------------
#define GEMM_SMEM_BYTES (NPIPE * 32768)

extern "C" __global__ void __launch_bounds__(256, 2)
gemm_bf16(const __nv_bfloat16* __restrict__ A,
          const __nv_bfloat16* __restrict__ B,
          float* __restrict__ C0, float* __restrict__ C1,
          float* __restrict__ C2)
{
    extern __shared__ __align__(1024) char smem[];
    const uint32_t sbase = smem_u32(smem);

    const int tid  = threadIdx.x;
    const int wid  = tid >> 5;
    const int lane = tid & 31;
    const int n0 = blockIdx.x * 128;
    const int m0 = blockIdx.y * 128;
    const int wm = (wid >> 2) * 64;
    const int wn = (wid & 3) * 32;

    const int lrow = tid >> 3;
    const int lq   = tid & 7;
    const __nv_bfloat16* Ag = A + (size_t)(m0 + lrow) * KBIG + lq * 8;
    const __nv_bfloat16* Bg = B + (size_t)(n0 + lrow) * KBIG + lq * 8;
    const uint32_t st_off = lrow * 128 + ((lq ^ (lrow & 7)) << 4);

    uint32_t aoff[4][4], boff[4][2];
    #pragma unroll
    for (int ks = 0; ks < 4; ks++) {
        #pragma unroll
        for (int mf = 0; mf < 4; mf++) {
            int row = wm + 16 * mf + ((lane >> 3) & 1) * 8 + (lane & 7);
            int ch  = 2 * ks + (lane >> 4);
            aoff[ks][mf] = row * 128 + ((ch ^ (row & 7)) << 4);
        }
        #pragma unroll
        for (int np = 0; np < 2; np++) {
            int row = wn + 16 * np + ((lane >> 4) << 3) + (lane & 7);
            int ch  = 2 * ks + ((lane >> 3) & 1);
            boff[ks][np] = row * 128 + ((ch ^ (row & 7)) << 4);
        }
    }

    float acc[4][4][4];
    #pragma unroll
    for (int i = 0; i < 4; i++)
        #pragma unroll
        for (int j = 0; j < 4; j++)
            #pragma unroll
            for (int r = 0; r < 4; r++) acc[i][j][r] = 0.f;

    auto issue = [&](int s) {
        const uint32_t dst = sbase + (s % NPIPE) * 32768 + st_off;
        const size_t ko = (size_t)s * BK;
        #pragma unroll
        for (int j = 0; j < 4; j++) {
            cp_async16(dst + j * 4096,         Ag + (size_t)32 * j * KBIG + ko);
            cp_async16(dst + 16384 + j * 4096, Bg + (size_t)32 * j * KBIG + ko);
        }
        CP_COMMIT();
    };

    #pragma unroll
    for (int s = 0; s < NPIPE - 1; s++) issue(s);

    for (int s = 0; s < NSTAGES; s++) {
        if (s + 1 < NSTAGES) { CP_WAIT(NPIPE - 2); } else { CP_WAIT(0); }
        __syncthreads();
        if (s + NPIPE - 1 < NSTAGES) issue(s + NPIPE - 1);

        const uint32_t ab32 = sbase + (s % NPIPE) * 32768;
        const uint32_t bb32 = ab32 + 16384;
        #pragma unroll
        for (int ks = 0; ks < 4; ks++) {
            uint32_t af[4][4], bf[2][4];
            #pragma unroll
            for (int mf = 0; mf < 4; mf++)
                ldsm_x4(af[mf], ab32 + aoff[ks][mf]);
            #pragma unroll
            for (int np = 0; np < 2; np++)
                ldsm_x4(bf[np], bb32 + boff[ks][np]);
            #pragma unroll
            for (int mf = 0; mf < 4; mf++)
                #pragma unroll
                for (int nf = 0; nf < 4; nf++)
                    mma16816(acc[mf][nf], af[mf], &bf[nf >> 1][(nf & 1) * 2]);
        }
        __syncthreads();
    }

    const int sel = n0 >> 10;
    float* __restrict__ C = (sel == 0) ? C0 : (sel == 1) ? C1 : C2;
    const int nl = n0 & 1023;
    const int gr = lane >> 2;
    const int gc = (lane & 3) * 2;
    #pragma unroll
    for (int mf = 0; mf < 4; mf++)
        #pragma unroll
        for (int nf = 0; nf < 4; nf++) {
            const int row = m0 + wm + 16 * mf + gr;
            const int col = nl + wn + 8 * nf + gc;
            *(float2*)&C[(size_t)row * DMODEL + col] =
                make_float2(acc[mf][nf][0], acc[mf][nf][1]);
            *(float2*)&C[(size_t)(row + 8) * DMODEL + col] =
                make_float2(acc[mf][nf][2], acc[mf][nf][3]);
        }
}

// ---------------------------------------------------------------------------
extern "C" __global__ void rope_tables()
{
    int idx = blockIdx.x * blockDim.x + threadIdx.x;   // 32768
    int t = idx >> 4;
    int j = idx & 15;
    float invf = exp2f(-10.0f * (float)j * (1.0f / 15.0f));
    float theta = (float)t * invf;
    double s, c;
    sincos((double)theta, &s, &c);
    g_cos[t * 16 + j] = (float)c;
    g_sin[t * 16 + j] = (float)s;
}

// ---------------------------------------------------------------------------
// Post: v = l0*v + l1*vi ; q,k = rotary(rmsnorm(q|k)); emit bf16 hi/lo splits
// ---------------------------------------------------------------------------
extern "C" __global__ void __launch_bounds__(64)
qkv_post(const float* __restrict__ vi, const float* __restrict__ lambdas)
{
    const int h = blockIdx.x;
    const int t = blockIdx.y;
    const int d = threadIdx.x;
    const int idx = t * DMODEL + h * HDIM + d;

    const float l0 = lambdas[0], l1 = lambdas[1];
    float vv = fmaf(l0, g_v[idx], l1 * vi[idx]);
    {
        __nv_bfloat16 vh = __float2bfloat16(vv);
        g_vhi[idx] = vh;
        g_vlo[idx] = __float2bfloat16(vv - __bfloat162float(vh));
    }

    float qv = g_q[idx], kv = g_k[idx];
    float q2 = qv * qv, k2 = kv * kv;
    #pragma unroll
    for (int o = 16; o > 0; o >>= 1) {
        q2 += __shfl_xor_sync(0xffffffffu, q2, o);
        k2 += __shfl_xor_sync(0xffffffffu, k2, o);
    }
    __shared__ float red[4];
    if ((d & 31) == 0) { red[d >> 5] = q2; red[2 + (d >> 5)] = k2; }
    __syncthreads();

    const float eps = 1.1920929e-7f;
    float qn = qv * rsqrtf((red[0] + red[1]) * (1.f / 64.f) + eps);
    float kn = kv * rsqrtf((red[2] + red[3]) * (1.f / 64.f) + eps);

    __shared__ float sq[64], sk[64];
    sq[d] = qn; sk[d] = kn;
    __syncthreads();

    const int j = d & 31;
    float c = 1.f, s = 0.f;
    if (j < 16) { c = g_cos[t * 16 + j]; s = g_sin[t * 16 + j]; }
    float oq, ok;
    if (d < 32) {
        oq =  sq[d] * c + sq[d + 32] * s;
        ok =  sk[d] * c + sk[d + 32] * s;
    } else {
        oq = -sq[j] * s + sq[d] * c;
        ok = -sk[j] * s + sk[d] * c;
    }

    float qs = oq * 0.125f;
    __nv_bfloat16 qh = __float2bfloat16(qs);
    g_qhi[idx] = qh;
    g_qlo[idx] = __float2bfloat16(qs - __bfloat162float(qh));
    __nv_bfloat16 kh = __float2bfloat16(ok);
    g_khi[idx] = kh;
    g_klo[idx] = __float2bfloat16(ok - __bfloat162float(kh));
}

// ---------------------------------------------------------------------------
// Tensor-core flash attention, causal, 64x64 tiles, hd=64, 4 warps.
// cp.async double-buffered K/V tiles; qt reversed (heavy CTAs first);
// epilogue writes packed Abig [hi | lo | hi] directly.
// smem: 2 x 32KB buffers, each: Khi@0 Klo@8K Vhi@16K Vlo@24K.
// ---------------------------------------------------------------------------
#define SW(row, q) ((row) * 128 + (((q) ^ ((row) & 7)) << 4))
#define FLASH_SMEM_BYTES 65536

extern "C" __global__ void __launch_bounds__(128)
flash_mma()
{
    extern __shared__ __align__(1024) char smd[];
    const uint32_t sb = smem_u32(smd);

    const int qt   = (int)gridDim.x - 1 - (int)blockIdx.x;  // heavy first
    const int h    = blockIdx.y;
    const int tid  = threadIdx.x;
    const int lane = tid & 31;
    const int wq   = tid >> 5;
    const int q0   = qt * 64;
    const size_t hcol = (size_t)h * HDIM;

    const int frow = tid >> 1;           // 0..63
    const int fqb  = (tid & 1) * 4;      // 0 or 4

    auto issue_kv = [&](int kt, int buf) {
        const uint32_t dst = sb + buf * 32768;
        const size_t kbase = (size_t)(kt * 64 + frow) * DMODEL + hcol + fqb * 8;
        #pragma unroll
        for (int j = 0; j < 4; j++) {
            const uint32_t so = SW(frow, fqb + j);
            const size_t go = kbase + (size_t)j * 8;
            cp_async16(dst + so,         g_khi + go);
            cp_async16(dst + 8192 + so,  g_klo + go);
            cp_async16(dst + 16384 + so, g_vhi + go);
            cp_async16(dst + 24576 + so, g_vlo + go);
        }
        CP_COMMIT();
    };

    // group 0: K/V tile kt=0 into buf0 ; group 1: Q into buf1
    issue_kv(0, 0);
    {
        const uint32_t dst = sb + 32768;
        const size_t qbase = (size_t)(q0 + frow) * DMODEL + hcol + fqb * 8;
        #pragma unroll
        for (int j = 0; j < 4; j++) {
            const uint32_t so = SW(frow, fqb + j);
            cp_async16(dst + so,        g_qhi + qbase + (size_t)j * 8);
            cp_async16(dst + 8192 + so, g_qlo + qbase + (size_t)j * 8);
        }
        CP_COMMIT();
    }
    CP_WAIT(0);
    __syncthreads();

    uint32_t qh[4][4], ql[4][4];
    #pragma unroll
    for (int ks = 0; ks < 4; ks++) {
        int row = wq * 16 + ((lane >> 3) & 1) * 8 + (lane & 7);
        int ch  = 2 * ks + (lane >> 4);
        uint32_t off = SW(row, ch);
        ldsm_x4(qh[ks], sb + 32768 + off);
        ldsm_x4(ql[ks], sb + 32768 + 8192 + off);
    }
    __syncthreads();   // Q reads done; buf1 free for kt=1

    float O[8][4];
    #pragma unroll
    for (int i = 0; i < 8; i++)
        #pragma unroll
        for (int r = 0; r < 4; r++) O[i][r] = 0.f;
    float m0r = -INFINITY, m1r = -INFINITY, l0r = 0.f, l1r = 0.f;

    const int gr = lane >> 2;
    const int gc = 2 * (lane & 3);
    const int r0 = wq * 16 + gr;
    const int r1 = r0 + 8;

    for (int kt = 0; kt <= qt; kt++) {
        const int buf = kt & 1;
        if (kt > 0) { CP_WAIT(0); __syncthreads(); }
        if (kt + 1 <= qt) issue_kv(kt + 1, buf ^ 1);

        const uint32_t KHI = sb + buf * 32768;
        const uint32_t KLO = KHI + 8192;
        const uint32_t VHI = KHI + 16384;
        const uint32_t VLO = KHI + 24576;

        float S[8][4];
        #pragma unroll
        for (int i = 0; i < 8; i++)
            #pragma unroll
            for (int r = 0; r < 4; r++) S[i][r] = 0.f;

        #pragma unroll
        for (int ks = 0; ks < 4; ks++) {
            uint32_t bh[4][4], bl[4][4];
            #pragma unroll
            for (int np = 0; np < 4; np++) {
                int row = np * 16 + ((lane >> 4) << 3) + (lane & 7);
                int ch  = 2 * ks + ((lane >> 3) & 1);
                uint32_t off = SW(row, ch);
                ldsm_x4(bh[np], KHI + off);
                ldsm_x4(bl[np], KLO + off);
            }
            #pragma unroll
            for (int nf = 0; nf < 8; nf++) {
                const uint32_t* b  = &bh[nf >> 1][(nf & 1) * 2];
                const uint32_t* b2 = &bl[nf >> 1][(nf & 1) * 2];
                mma16816(S[nf], qh[ks], b);
                mma16816(S[nf], ql[ks], b);
                mma16816(S[nf], qh[ks], b2);
            }
        }

        if (kt == qt) {
            #pragma unroll
            for (int nf = 0; nf < 8; nf++) {
                int c0 = 8 * nf + gc;
                if (c0     > r0) S[nf][0] = -1e30f;
                if (c0 + 1 > r0) S[nf][1] = -1e30f;
                if (c0     > r1) S[nf][2] = -1e30f;
                if (c0 + 1 > r1) S[nf][3] = -1e30f;
            }
        }

        float mx0 = -INFINITY, mx1 = -INFINITY;
        #pragma unroll
        for (int nf = 0; nf < 8; nf++) {
            mx0 = fmaxf(mx0, fmaxf(S[nf][0], S[nf][1]));
            mx1 = fmaxf(mx1, fmaxf(S[nf][2], S[nf][3]));
        }
        mx0 = fmaxf(mx0, __shfl_xor_sync(0xffffffffu, mx0, 1));
        mx0 = fmaxf(mx0, __shfl_xor_sync(0xffffffffu, mx0, 2));
        mx1 = fmaxf(mx1, __shfl_xor_sync(0xffffffffu, mx1, 1));
        mx1 = fmaxf(mx1, __shfl_xor_sync(0xffffffffu, mx1, 2));

        const float mn0 = fmaxf(m0r, mx0);
        const float mn1 = fmaxf(m1r, mx1);
        const float a0 = __expf(m0r - mn0);
        const float a1 = __expf(m1r - mn1);

        float s0 = 0.f, s1 = 0.f;
        uint32_t Ahi[4][4], Alo[4][4];
        #pragma unroll
        for (int js = 0; js < 4; js++) {
            #pragma unroll
            for (int half = 0; half < 2; half++) {
                const int nf = 2 * js + half;
                float p0 = __expf(S[nf][0] - mn0);
                float p1 = __expf(S[nf][1] - mn0);
                float p2 = __expf(S[nf][2] - mn1);
                float p3 = __expf(S[nf][3] - mn1);
                s0 += p0 + p1;
                s1 += p2 + p3;
                float h0 = __bfloat162float(__float2bfloat16(p0));
                float h1 = __bfloat162float(__float2bfloat16(p1));
                float h2 = __bfloat162float(__float2bfloat16(p2));
                float h3 = __bfloat162float(__float2bfloat16(p3));
                Ahi[js][half * 2 + 0] = pack_bf16x2(h0, h1);
                Ahi[js][half * 2 + 1] = pack_bf16x2(h2, h3);
                Alo[js][half * 2 + 0] = pack_bf16x2(p0 - h0, p1 - h1);
                Alo[js][half * 2 + 1] = pack_bf16x2(p2 - h2, p3 - h3);
            }
        }
        s0 += __shfl_xor_sync(0xffffffffu, s0, 1);
        s0 += __shfl_xor_sync(0xffffffffu, s0, 2);
        s1 += __shfl_xor_sync(0xffffffffu, s1, 1);
        s1 += __shfl_xor_sync(0xffffffffu, s1, 2);
        l0r = l0r * a0 + s0;
        l1r = l1r * a1 + s1;
        m0r = mn0;
        m1r = mn1;

        #pragma unroll
        for (int nf = 0; nf < 8; nf++) {
            O[nf][0] *= a0; O[nf][1] *= a0;
            O[nf][2] *= a1; O[nf][3] *= a1;
        }
        #pragma unroll
        for (int js = 0; js < 4; js++) {
            uint32_t vh[4][4], vl[4][4];
            #pragma unroll
            for (int np = 0; np < 4; np++) {
                int row = js * 16 + ((lane >> 3) & 1) * 8 + (lane & 7);
                int ch  = 2 * np + (lane >> 4);
                uint32_t off = SW(row, ch);
                ldsm_x4_t(vh[np], VHI + off);
                ldsm_x4_t(vl[np], VLO + off);
            }
            #pragma unroll
            for (int nf = 0; nf < 8; nf++) {
                const uint32_t* b  = &vh[nf >> 1][(nf & 1) * 2];
                const uint32_t* b2 = &vl[nf >> 1][(nf & 1) * 2];
                mma16816(O[nf], Ahi[js], b);
                mma16816(O[nf], Alo[js], b);
                mma16816(O[nf], Ahi[js], b2);
            }
        }
        __syncthreads();   // reads of buf done; safe to cp.async into it next iter
    }

    // ---- epilogue: write packed Abig rows [hi | lo | hi] directly
    const float i0 = 1.f / l0r;
    const float i1 = 1.f / l1r;
    #pragma unroll
    for (int nf = 0; nf < 8; nf++) {
        const size_t col = hcol + 8 * nf + gc;
        {
            float o0 = O[nf][0] * i0, o1 = O[nf][1] * i0;
            float h0 = __bfloat162float(__float2bfloat16(o0));
            float h1 = __bfloat162float(__float2bfloat16(o1));
            __nv_bfloat16* rowp = g_Abig + (size_t)(q0 + r0) * KBIG + col;
            *(uint32_t*)(rowp)              = pack_bf16x2(h0, h1);
            *(uint32_t*)(rowp + DMODEL)     = pack_bf16x2(o0 - h0, o1 - h1);
            *(uint32_t*)(rowp + 2 * DMODEL) = pack_bf16x2(h0, h1);
        }
        {
            float o0 = O[nf][2] * i1, o1 = O[nf][3] * i1;
            float h0 = __bfloat162float(__float2bfloat16(o0));
            float h1 = __bfloat162float(__float2bfloat16(o1));
            __nv_bfloat16* rowp = g_Abig + (size_t)(q0 + r1) * KBIG + col;
            *(uint32_t*)(rowp)              = pack_bf16x2(h0, h1);
            *(uint32_t*)(rowp + DMODEL)     = pack_bf16x2(o0 - h0, o1 - h1);
            *(uint32_t*)(rowp + 2 * DMODEL) = pack_bf16x2(h0, h1);
        }
    }
}

// ---------------------------------------------------------------------------
extern "C" void kernel_launch(void* const* d_in, const int* in_sizes, int n_in,
                              void* d_out, int out_size)
{
    const float* x   = (const float*)d_in[0];
    const float* vi  = (const float*)d_in[1];
    const float* Wq  = (const float*)d_in[2];
    const float* Wk  = (const float*)d_in[3];
    const float* Wv  = (const float*)d_in[4];
    const float* Wp  = (const float*)d_in[5];
    const float* lam = (const float*)d_in[6];
    float* out = (float*)d_out;

    float *gq, *gk, *gv;
    __nv_bfloat16 *gA, *gWqkv, *gWp;
    cudaGetSymbolAddress((void**)&gq, g_q);
    cudaGetSymbolAddress((void**)&gk, g_k);
    cudaGetSymbolAddress((void**)&gv, g_v);
    cudaGetSymbolAddress((void**)&gA, g_Abig);
    cudaGetSymbolAddress((void**)&gWqkv, g_Wqkv);
    cudaGetSymbolAddress((void**)&gWp, g_Wpb);

    cudaFuncSetAttribute(gemm_bf16, cudaFuncAttributeMaxDynamicSharedMemorySize,
                         GEMM_SMEM_BYTES);
    cudaFuncSetAttribute(flash_mma, cudaFuncAttributeMaxDynamicSharedMemorySize,
                         FLASH_SMEM_BYTES);

    pack_w4<<<dim3(DMODEL, 4), 256>>>(Wq, Wk, Wv, Wp, gWqkv, gWp);
    pack_a<<<T_SEQ, 256>>>(x, gA);

    // fused QKV: N = 3072
    gemm_bf16<<<dim3(3 * DMODEL / 128, T_SEQ / 128), 256, GEMM_SMEM_BYTES>>>(
        gA, gWqkv, gq, gk, gv);

    rope_tables<<<32, 1024>>>();
    qkv_post<<<dim3(NHEADS, T_SEQ), 64>>>(vi, lam);

    flash_mma<<<dim3(T_SEQ / 64, NHEADS), 128, FLASH_SMEM_BYTES>>>();

    gemm_bf16<<<dim3(DMODEL / 128, T_SEQ / 128), 256, GEMM_SMEM_BYTES>>>(
        gA, gWp, out, out, out);
}

// round 7
// speedup vs baseline: 3.3131x; 1.0176x over previous
#include <cuda_runtime.h>
#include <cuda_bf16.h>
#include <math.h>
#include <stdint.h>

#define T_SEQ  2048
#define DMODEL 1024
#define NHEADS 16
#define HDIM   64
#define KBIG   3072              // [hi | lo | hi] x [hi | hi | lo]
#define BK     64
#define NSTAGES (KBIG / BK)      // 48
#define NPIPE  3

// ---------------------------------------------------------------------------
// Scratch (static device globals — no allocation allowed in kernel_launch)
// ---------------------------------------------------------------------------
__device__ float g_q[T_SEQ * DMODEL];
__device__ float g_k[T_SEQ * DMODEL];
__device__ float g_v[T_SEQ * DMODEL];
__device__ __align__(16) __nv_bfloat16 g_Abig[T_SEQ * KBIG];
__device__ __align__(16) __nv_bfloat16 g_Wqkv[3 * DMODEL * KBIG];
__device__ __align__(16) __nv_bfloat16 g_Wpb[DMODEL * KBIG];
// bf16 hi/lo splits for attention (q pre-scaled by 1/8)
__device__ __align__(16) __nv_bfloat16 g_qhi[T_SEQ * DMODEL];
__device__ __align__(16) __nv_bfloat16 g_qlo[T_SEQ * DMODEL];
__device__ __align__(16) __nv_bfloat16 g_khi[T_SEQ * DMODEL];
__device__ __align__(16) __nv_bfloat16 g_klo[T_SEQ * DMODEL];
__device__ __align__(16) __nv_bfloat16 g_vhi[T_SEQ * DMODEL];
__device__ __align__(16) __nv_bfloat16 g_vlo[T_SEQ * DMODEL];

// ---------------------------------------------------------------------------
__device__ __forceinline__ uint32_t smem_u32(const void* p) {
    uint32_t a;
    asm("{ .reg .u64 t; cvta.to.shared.u64 t, %1; cvt.u32.u64 %0, t; }"
        : "=r"(a) : "l"(p));
    return a;
}

__device__ __forceinline__ void ldsm_x4(uint32_t* r, uint32_t addr) {
    asm volatile("ldmatrix.sync.aligned.m8n8.x4.shared.b16 {%0,%1,%2,%3}, [%4];"
                 : "=r"(r[0]), "=r"(r[1]), "=r"(r[2]), "=r"(r[3]) : "r"(addr));
}

__device__ __forceinline__ void ldsm_x4_t(uint32_t* r, uint32_t addr) {
    asm volatile("ldmatrix.sync.aligned.m8n8.x4.trans.shared.b16 {%0,%1,%2,%3}, [%4];"
                 : "=r"(r[0]), "=r"(r[1]), "=r"(r[2]), "=r"(r[3]) : "r"(addr));
}

__device__ __forceinline__ void mma16816(float* d, const uint32_t* a,
                                         const uint32_t* b) {
    asm volatile(
        "mma.sync.aligned.m16n8k16.row.col.f32.bf16.bf16.f32 "
        "{%0,%1,%2,%3}, {%4,%5,%6,%7}, {%8,%9}, {%0,%1,%2,%3};"
        : "+f"(d[0]), "+f"(d[1]), "+f"(d[2]), "+f"(d[3])
        : "r"(a[0]), "r"(a[1]), "r"(a[2]), "r"(a[3]), "r"(b[0]), "r"(b[1]));
}

__device__ __forceinline__ uint32_t pack_bf16x2(float lo, float hi) {
    uint32_t r;
    asm("cvt.rn.bf16x2.f32 %0, %1, %2;" : "=r"(r) : "f"(hi), "f"(lo));
    return r;
}

__device__ __forceinline__ void cp_async16(uint32_t dst, const void* src) {
    asm volatile("cp.async.cg.shared.global [%0], [%1], 16;"
                 :: "r"(dst), "l"(src));
}
#define CP_COMMIT() asm volatile("cp.async.commit_group;" ::: "memory")
#define CP_WAIT(n)  asm volatile("cp.async.wait_group %0;" :: "n"(n) : "memory")

// ---------------------------------------------------------------------------
// Packing: fp32 -> bf16 hi/lo split with concatenated K.
// ---------------------------------------------------------------------------
extern "C" __global__ void pack_a(const float* __restrict__ src,
                                  __nv_bfloat16* __restrict__ dst) {
    const int r = blockIdx.x;
    for (int k = threadIdx.x; k < DMODEL; k += blockDim.x) {
        float v = src[(size_t)r * DMODEL + k];
        __nv_bfloat16 hi = __float2bfloat16(v);
        __nv_bfloat16 lo = __float2bfloat16(v - __bfloat162float(hi));
        size_t base = (size_t)r * KBIG;
        dst[base + k] = hi;
        dst[base + DMODEL + k] = lo;
        dst[base + 2 * DMODEL + k] = hi;
    }
}

// y = 0,1,2 -> rows y*1024+r of g_Wqkv ; y = 3 -> g_Wpb
extern "C" __global__ void pack_w4(const float* __restrict__ w0,
                                   const float* __restrict__ w1,
                                   const float* __restrict__ w2,
                                   const float* __restrict__ w3,
                                   __nv_bfloat16* __restrict__ dqkv,
                                   __nv_bfloat16* __restrict__ dp) {
    const int r = blockIdx.x;
    const int y = blockIdx.y;
    const float* src = (y == 0) ? w0 : (y == 1) ? w1 : (y == 2) ? w2 : w3;
    __nv_bfloat16* dst = (y == 3) ? (dp + (size_t)r * KBIG)
                                  : (dqkv + (size_t)(y * DMODEL + r) * KBIG);
    for (int k = threadIdx.x; k < DMODEL; k += blockDim.x) {
        float v = src[(size_t)r * DMODEL + k];
        __nv_bfloat16 hi = __float2bfloat16(v);
        __nv_bfloat16 lo = __float2bfloat16(v - __bfloat162float(hi));
        dst[k] = hi;
        dst[DMODEL + k] = hi;
        dst[2 * DMODEL + k] = lo;
    }
}

// ---------------------------------------------------------------------------
// mma.sync bf16 GEMM with cp.async 3-stage pipeline, 2 CTAs/SM.
// ---------------------------------------------------------------------------
#define GEMM_SMEM_BYTES (NPIPE * 32768)

extern "C" __global__ void __launch_bounds__(256, 2)
gemm_bf16(const __nv_bfloat16* __restrict__ A,
          const __nv_bfloat16* __restrict__ B,
          float* __restrict__ C0, float* __restrict__ C1,
          float* __restrict__ C2)
{
    extern __shared__ __align__(1024) char smem[];
    const uint32_t sbase = smem_u32(smem);

    const int tid  = threadIdx.x;
    const int wid  = tid >> 5;
    const int lane = tid & 31;
    const int n0 = blockIdx.x * 128;
    const int m0 = blockIdx.y * 128;
    const int wm = (wid >> 2) * 64;
    const int wn = (wid & 3) * 32;

    const int lrow = tid >> 3;
    const int lq   = tid & 7;
    const __nv_bfloat16* Ag = A + (size_t)(m0 + lrow) * KBIG + lq * 8;
    const __nv_bfloat16* Bg = B + (size_t)(n0 + lrow) * KBIG + lq * 8;
    const uint32_t st_off = lrow * 128 + ((lq ^ (lrow & 7)) << 4);

    uint32_t aoff[4][4], boff[4][2];
    #pragma unroll
    for (int ks = 0; ks < 4; ks++) {
        #pragma unroll
        for (int mf = 0; mf < 4; mf++) {
            int row = wm + 16 * mf + ((lane >> 3) & 1) * 8 + (lane & 7);
            int ch  = 2 * ks + (lane >> 4);
            aoff[ks][mf] = row * 128 + ((ch ^ (row & 7)) << 4);
        }
        #pragma unroll
        for (int np = 0; np < 2; np++) {
            int row = wn + 16 * np + ((lane >> 4) << 3) + (lane & 7);
            int ch  = 2 * ks + ((lane >> 3) & 1);
            boff[ks][np] = row * 128 + ((ch ^ (row & 7)) << 4);
        }
    }

    float acc[4][4][4];
    #pragma unroll
    for (int i = 0; i < 4; i++)
        #pragma unroll
        for (int j = 0; j < 4; j++)
            #pragma unroll
            for (int r = 0; r < 4; r++) acc[i][j][r] = 0.f;

    auto issue = [&](int s) {
        const uint32_t dst = sbase + (s % NPIPE) * 32768 + st_off;
        const size_t ko = (size_t)s * BK;
        #pragma unroll
        for (int j = 0; j < 4; j++) {
            cp_async16(dst + j * 4096,         Ag + (size_t)32 * j * KBIG + ko);
            cp_async16(dst + 16384 + j * 4096, Bg + (size_t)32 * j * KBIG + ko);
        }
        CP_COMMIT();
    };

    #pragma unroll
    for (int s = 0; s < NPIPE - 1; s++) issue(s);

    for (int s = 0; s < NSTAGES; s++) {
        if (s + 1 < NSTAGES) { CP_WAIT(NPIPE - 2); } else { CP_WAIT(0); }
        __syncthreads();
        if (s + NPIPE - 1 < NSTAGES) issue(s + NPIPE - 1);

        const uint32_t ab32 = sbase + (s % NPIPE) * 32768;
        const uint32_t bb32 = ab32 + 16384;
        #pragma unroll
        for (int ks = 0; ks < 4; ks++) {
            uint32_t af[4][4], bf[2][4];
            #pragma unroll
            for (int mf = 0; mf < 4; mf++)
                ldsm_x4(af[mf], ab32 + aoff[ks][mf]);
            #pragma unroll
            for (int np = 0; np < 2; np++)
                ldsm_x4(bf[np], bb32 + boff[ks][np]);
            #pragma unroll
            for (int mf = 0; mf < 4; mf++)
                #pragma unroll
                for (int nf = 0; nf < 4; nf++)
                    mma16816(acc[mf][nf], af[mf], &bf[nf >> 1][(nf & 1) * 2]);
        }
        __syncthreads();
    }

    const int sel = n0 >> 10;
    float* __restrict__ C = (sel == 0) ? C0 : (sel == 1) ? C1 : C2;
    const int nl = n0 & 1023;
    const int gr = lane >> 2;
    const int gc = (lane & 3) * 2;
    #pragma unroll
    for (int mf = 0; mf < 4; mf++)
        #pragma unroll
        for (int nf = 0; nf < 4; nf++) {
            const int row = m0 + wm + 16 * mf + gr;
            const int col = nl + wn + 8 * nf + gc;
            *(float2*)&C[(size_t)row * DMODEL + col] =
                make_float2(acc[mf][nf][0], acc[mf][nf][1]);
            *(float2*)&C[(size_t)(row + 8) * DMODEL + col] =
                make_float2(acc[mf][nf][2], acc[mf][nf][3]);
        }
}

// ---------------------------------------------------------------------------
// Fused post: one warp per (t,h). Lane j owns dims j and j+32.
// v blend + rmsnorm + inline rotary (sincosf) + bf16 hi/lo emission.
// No smem, no __syncthreads.
// ---------------------------------------------------------------------------
extern "C" __global__ void __launch_bounds__(256)
qkv_post(const float* __restrict__ vi, const float* __restrict__ lambdas)
{
    const int u = blockIdx.x * 8 + (threadIdx.x >> 5);   // unit = t*16+h
    const int j = threadIdx.x & 31;
    const int t = u >> 4;
    const int h = u & 15;
    const int base = t * DMODEL + h * HDIM;
    const int i0 = base + j;
    const int i1 = base + j + 32;

    const float l0 = lambdas[0], l1 = lambdas[1];
    {
        float v0 = fmaf(l0, g_v[i0], l1 * vi[i0]);
        float v1 = fmaf(l0, g_v[i1], l1 * vi[i1]);
        __nv_bfloat16 h0 = __float2bfloat16(v0);
        __nv_bfloat16 h1 = __float2bfloat16(v1);
        g_vhi[i0] = h0; g_vlo[i0] = __float2bfloat16(v0 - __bfloat162float(h0));
        g_vhi[i1] = h1; g_vlo[i1] = __float2bfloat16(v1 - __bfloat162float(h1));
    }

    float q0 = g_q[i0], q1 = g_q[i1];
    float k0 = g_k[i0], k1 = g_k[i1];
    float qs = q0 * q0 + q1 * q1;
    float ks = k0 * k0 + k1 * k1;
    #pragma unroll
    for (int o = 16; o > 0; o >>= 1) {
        qs += __shfl_xor_sync(0xffffffffu, qs, o);
        ks += __shfl_xor_sync(0xffffffffu, ks, o);
    }
    const float eps = 1.1920929e-7f;
    const float rq = rsqrtf(qs * (1.f / 64.f) + eps);
    const float rk = rsqrtf(ks * (1.f / 64.f) + eps);
    q0 *= rq; q1 *= rq; k0 *= rk; k1 *= rk;

    float c = 1.f, s = 0.f;
    if (j < 16) {
        float invf = exp2f(-10.0f * (float)j * (1.0f / 15.0f));
        sincosf((float)t * invf, &s, &c);
    }
    // outputs: dim j  = x1*c + x2*s ; dim j+32 = -x1*s + x2*c
    float qa = (q0 * c + q1 * s) * 0.125f;
    float qb = (q1 * c - q0 * s) * 0.125f;
    float ka =  k0 * c + k1 * s;
    float kb =  k1 * c - k0 * s;

    __nv_bfloat16 qha = __float2bfloat16(qa);
    __nv_bfloat16 qhb = __float2bfloat16(qb);
    g_qhi[i0] = qha; g_qlo[i0] = __float2bfloat16(qa - __bfloat162float(qha));
    g_qhi[i1] = qhb; g_qlo[i1] = __float2bfloat16(qb - __bfloat162float(qhb));
    __nv_bfloat16 kha = __float2bfloat16(ka);
    __nv_bfloat16 khb = __float2bfloat16(kb);
    g_khi[i0] = kha; g_klo[i0] = __float2bfloat16(ka - __bfloat162float(kha));
    g_khi[i1] = khb; g_klo[i1] = __float2bfloat16(kb - __bfloat162float(khb));
}

// ---------------------------------------------------------------------------
// Tensor-core flash attention, causal. 128-row Q tiles, 64-row K/V tiles,
// 8 warps. cp.async double-buffered K/V; heavy CTAs first; epilogue writes
// packed Abig [hi | lo | hi] directly.
// smem: buf0 32KB (Khi/Klo/Vhi/Vlo 8KB each), buf1 32KB (Q staging: Qhi 16K
// Qlo 16K, then reused as K/V buffer).
// ---------------------------------------------------------------------------
#define SW(row, q) ((row) * 128 + (((q) ^ ((row) & 7)) << 4))
#define FLASH_SMEM_BYTES 65536

extern "C" __global__ void __launch_bounds__(256)
flash_mma()
{
    extern __shared__ __align__(1024) char smd[];
    const uint32_t sb = smem_u32(smd);

    const int qt   = (int)gridDim.x - 1 - (int)blockIdx.x;  // heavy first
    const int h    = blockIdx.y;
    const int tid  = threadIdx.x;
    const int lane = tid & 31;
    const int wq   = tid >> 5;          // 0..7 -> 16-row slice of 128
    const int q0   = qt * 128;
    const int ktmax = 2 * qt + 1;
    const size_t hcol = (size_t)h * HDIM;

    // K/V tile loader: 64 rows, 256 threads -> 2 quads each
    const int krow = tid >> 2;
    const int kq2  = (tid & 3) * 2;
    auto issue_kv = [&](int kt, int buf) {
        const uint32_t dst = sb + buf * 32768;
        const size_t gb = (size_t)(kt * 64 + krow) * DMODEL + hcol + kq2 * 8;
        #pragma unroll
        for (int j = 0; j < 2; j++) {
            const uint32_t so = SW(krow, kq2 + j);
            const size_t go = gb + (size_t)j * 8;
            cp_async16(dst + so,         g_khi + go);
            cp_async16(dst + 8192 + so,  g_klo + go);
            cp_async16(dst + 16384 + so, g_vhi + go);
            cp_async16(dst + 24576 + so, g_vlo + go);
        }
        CP_COMMIT();
    };

    // stage kv0 -> buf0, Q -> buf1 (Qhi 16K + Qlo 16K)
    issue_kv(0, 0);
    {
        const int qrow = tid >> 1;           // 0..127
        const int qqb  = (tid & 1) * 4;
        const uint32_t dst = sb + 32768;
        const size_t gb = (size_t)(q0 + qrow) * DMODEL + hcol + qqb * 8;
        #pragma unroll
        for (int j = 0; j < 4; j++) {
            const uint32_t so = SW(qrow, qqb + j);
            cp_async16(dst + so,         g_qhi + gb + (size_t)j * 8);
            cp_async16(dst + 16384 + so, g_qlo + gb + (size_t)j * 8);
        }
        CP_COMMIT();
    }
    CP_WAIT(0);
    __syncthreads();

    uint32_t qh[4][4], ql[4][4];
    #pragma unroll
    for (int ks = 0; ks < 4; ks++) {
        int row = wq * 16 + ((lane >> 3) & 1) * 8 + (lane & 7);
        int ch  = 2 * ks + (lane >> 4);
        uint32_t off = SW(row, ch);
        ldsm_x4(qh[ks], sb + 32768 + off);
        ldsm_x4(ql[ks], sb + 32768 + 16384 + off);
    }
    __syncthreads();   // Q fragments in regs; buf1 free

    float O[8][4];
    #pragma unroll
    for (int i = 0; i < 8; i++)
        #pragma unroll
        for (int r = 0; r < 4; r++) O[i][r] = 0.f;
    float m0r = -INFINITY, m1r = -INFINITY, l0r = 0.f, l1r = 0.f;

    const int gr = lane >> 2;
    const int gc = 2 * (lane & 3);
    const int r0 = wq * 16 + gr;         // 0..127
    const int r1 = r0 + 8;
    const int grow0 = q0 + r0;
    const int grow1 = q0 + r1;

    for (int kt = 0; kt <= ktmax; kt++) {
        const int buf = kt & 1;
        if (kt > 0) { CP_WAIT(0); __syncthreads(); }
        if (kt + 1 <= ktmax) issue_kv(kt + 1, buf ^ 1);

        const uint32_t KHI = sb + buf * 32768;
        const uint32_t KLO = KHI + 8192;
        const uint32_t VHI = KHI + 16384;
        const uint32_t VLO = KHI + 24576;

        float S[8][4];
        #pragma unroll
        for (int i = 0; i < 8; i++)
            #pragma unroll
            for (int r = 0; r < 4; r++) S[i][r] = 0.f;

        #pragma unroll
        for (int ks = 0; ks < 4; ks++) {
            uint32_t bh[4][4], bl[4][4];
            #pragma unroll
            for (int np = 0; np < 4; np++) {
                int row = np * 16 + ((lane >> 4) << 3) + (lane & 7);
                int ch  = 2 * ks + ((lane >> 3) & 1);
                uint32_t off = SW(row, ch);
                ldsm_x4(bh[np], KHI + off);
                ldsm_x4(bl[np], KLO + off);
            }
            #pragma unroll
            for (int nf = 0; nf < 8; nf++) {
                const uint32_t* b  = &bh[nf >> 1][(nf & 1) * 2];
                const uint32_t* b2 = &bl[nf >> 1][(nf & 1) * 2];
                mma16816(S[nf], qh[ks], b);
                mma16816(S[nf], ql[ks], b);
                mma16816(S[nf], qh[ks], b2);
            }
        }

        if (kt >= 2 * qt) {   // last two tiles cross the diagonal
            const int k0c = kt * 64;
            #pragma unroll
            for (int nf = 0; nf < 8; nf++) {
                int cg = k0c + 8 * nf + gc;
                if (cg     > grow0) S[nf][0] = -1e30f;
                if (cg + 1 > grow0) S[nf][1] = -1e30f;
                if (cg     > grow1) S[nf][2] = -1e30f;
                if (cg + 1 > grow1) S[nf][3] = -1e30f;
            }
        }

        float mx0 = -INFINITY, mx1 = -INFINITY;
        #pragma unroll
        for (int nf = 0; nf < 8; nf++) {
            mx0 = fmaxf(mx0, fmaxf(S[nf][0], S[nf][1]));
            mx1 = fmaxf(mx1, fmaxf(S[nf][2], S[nf][3]));
        }
        mx0 = fmaxf(mx0, __shfl_xor_sync(0xffffffffu, mx0, 1));
        mx0 = fmaxf(mx0, __shfl_xor_sync(0xffffffffu, mx0, 2));
        mx1 = fmaxf(mx1, __shfl_xor_sync(0xffffffffu, mx1, 1));
        mx1 = fmaxf(mx1, __shfl_xor_sync(0xffffffffu, mx1, 2));

        const float mn0 = fmaxf(m0r, mx0);
        const float mn1 = fmaxf(m1r, mx1);
        const float a0 = __expf(m0r - mn0);
        const float a1 = __expf(m1r - mn1);

        float s0 = 0.f, s1 = 0.f;
        uint32_t Ahi[4][4], Alo[4][4];
        #pragma unroll
        for (int js = 0; js < 4; js++) {
            #pragma unroll
            for (int half = 0; half < 2; half++) {
                const int nf = 2 * js + half;
                float p0 = __expf(S[nf][0] - mn0);
                float p1 = __expf(S[nf][1] - mn0);
                float p2 = __expf(S[nf][2] - mn1);
                float p3 = __expf(S[nf][3] - mn1);
                s0 += p0 + p1;
                s1 += p2 + p3;
                float h0 = __bfloat162float(__float2bfloat16(p0));
                float h1 = __bfloat162float(__float2bfloat16(p1));
                float h2 = __bfloat162float(__float2bfloat16(p2));
                float h3 = __bfloat162float(__float2bfloat16(p3));
                Ahi[js][half * 2 + 0] = pack_bf16x2(h0, h1);
                Ahi[js][half * 2 + 1] = pack_bf16x2(h2, h3);
                Alo[js][half * 2 + 0] = pack_bf16x2(p0 - h0, p1 - h1);
                Alo[js][half * 2 + 1] = pack_bf16x2(p2 - h2, p3 - h3);
            }
        }
        s0 += __shfl_xor_sync(0xffffffffu, s0, 1);
        s0 += __shfl_xor_sync(0xffffffffu, s0, 2);
        s1 += __shfl_xor_sync(0xffffffffu, s1, 1);
        s1 += __shfl_xor_sync(0xffffffffu, s1, 2);
        l0r = l0r * a0 + s0;
        l1r = l1r * a1 + s1;
        m0r = mn0;
        m1r = mn1;

        #pragma unroll
        for (int nf = 0; nf < 8; nf++) {
            O[nf][0] *= a0; O[nf][1] *= a0;
            O[nf][2] *= a1; O[nf][3] *= a1;
        }
        #pragma unroll
        for (int js = 0; js < 4; js++) {
            uint32_t vh[4][4], vl[4][4];
            #pragma unroll
            for (int np = 0; np < 4; np++) {
                int row = js * 16 + ((lane >> 3) & 1) * 8 + (lane & 7);
                int ch  = 2 * np + (lane >> 4);
                uint32_t off = SW(row, ch);
                ldsm_x4_t(vh[np], VHI + off);
                ldsm_x4_t(vl[np], VLO + off);
            }
            #pragma unroll
            for (int nf = 0; nf < 8; nf++) {
                const uint32_t* b  = &vh[nf >> 1][(nf & 1) * 2];
                const uint32_t* b2 = &vl[nf >> 1][(nf & 1) * 2];
                mma16816(O[nf], Ahi[js], b);
                mma16816(O[nf], Alo[js], b);
                mma16816(O[nf], Ahi[js], b2);
            }
        }
        __syncthreads();
    }

    // epilogue: packed Abig rows [hi | lo | hi]
    const float i0 = 1.f / l0r;
    const float i1 = 1.f / l1r;
    #pragma unroll
    for (int nf = 0; nf < 8; nf++) {
        const size_t col = hcol + 8 * nf + gc;
        {
            float o0 = O[nf][0] * i0, o1 = O[nf][1] * i0;
            float h0 = __bfloat162float(__float2bfloat16(o0));
            float h1 = __bfloat162float(__float2bfloat16(o1));
            __nv_bfloat16* rowp = g_Abig + (size_t)grow0 * KBIG + col;
            *(uint32_t*)(rowp)              = pack_bf16x2(h0, h1);
            *(uint32_t*)(rowp + DMODEL)     = pack_bf16x2(o0 - h0, o1 - h1);
            *(uint32_t*)(rowp + 2 * DMODEL) = pack_bf16x2(h0, h1);
        }
        {
            float o0 = O[nf][2] * i1, o1 = O[nf][3] * i1;
            float h0 = __bfloat162float(__float2bfloat16(o0));
            float h1 = __bfloat162float(__float2bfloat16(o1));
            __nv_bfloat16* rowp = g_Abig + (size_t)grow1 * KBIG + col;
            *(uint32_t*)(rowp)              = pack_bf16x2(h0, h1);
            *(uint32_t*)(rowp + DMODEL)     = pack_bf16x2(o0 - h0, o1 - h1);
            *(uint32_t*)(rowp + 2 * DMODEL) = pack_bf16x2(h0, h1);
        }
    }
}

// ---------------------------------------------------------------------------
extern "C" void kernel_launch(void* const* d_in, const int* in_sizes, int n_in,
                              void* d_out, int out_size)
{
    const float* x   = (const float*)d_in[0];
    const float* vi  = (const float*)d_in[1];
    const float* Wq  = (const float*)d_in[2];
    const float* Wk  = (const float*)d_in[3];
    const float* Wv  = (const float*)d_in[4];
    const float* Wp  = (const float*)d_in[5];
    const float* lam = (const float*)d_in[6];
    float* out = (float*)d_out;

    float *gq, *gk, *gv;
    __nv_bfloat16 *gA, *gWqkv, *gWp;
    cudaGetSymbolAddress((void**)&gq, g_q);
    cudaGetSymbolAddress((void**)&gk, g_k);
    cudaGetSymbolAddress((void**)&gv, g_v);
    cudaGetSymbolAddress((void**)&gA, g_Abig);
    cudaGetSymbolAddress((void**)&gWqkv, g_Wqkv);
    cudaGetSymbolAddress((void**)&gWp, g_Wpb);

    cudaFuncSetAttribute(gemm_bf16, cudaFuncAttributeMaxDynamicSharedMemorySize,
                         GEMM_SMEM_BYTES);
    cudaFuncSetAttribute(flash_mma, cudaFuncAttributeMaxDynamicSharedMemorySize,
                         FLASH_SMEM_BYTES);

    pack_w4<<<dim3(DMODEL, 4), 256>>>(Wq, Wk, Wv, Wp, gWqkv, gWp);
    pack_a<<<T_SEQ, 256>>>(x, gA);

    // fused QKV: N = 3072
    gemm_bf16<<<dim3(3 * DMODEL / 128, T_SEQ / 128), 256, GEMM_SMEM_BYTES>>>(
        gA, gWqkv, gq, gk, gv);

    qkv_post<<<T_SEQ * NHEADS / 8, 256>>>(vi, lam);

    flash_mma<<<dim3(T_SEQ / 128, NHEADS), 256, FLASH_SMEM_BYTES>>>();

    gemm_bf16<<<dim3(DMODEL / 128, T_SEQ / 128), 256, GEMM_SMEM_BYTES>>>(
        gA, gWp, out, out, out);
}

// round 8
// speedup vs baseline: 4.9539x; 1.4952x over previous
#include <cuda_runtime.h>
#include <cuda_bf16.h>
#include <cuda_fp16.h>
#include <math.h>
#include <stdint.h>

#define T_SEQ  2048
#define DMODEL 1024
#define NHEADS 16
#define HDIM   64
#define KDIM   1024
#define BK     64
#define NSTAGES (KDIM / BK)      // 16
#define NPIPE  3

// ---------------------------------------------------------------------------
// Scratch (static device globals — no allocation allowed in kernel_launch)
// ---------------------------------------------------------------------------
__device__ float g_q[T_SEQ * DMODEL];
__device__ float g_k[T_SEQ * DMODEL];
__device__ float g_v[T_SEQ * DMODEL];
__device__ __align__(16) __half g_x16[T_SEQ * DMODEL];
__device__ __align__(16) __half g_y16[T_SEQ * DMODEL];
__device__ __align__(16) __half g_Wqkv16[3 * DMODEL * DMODEL];
__device__ __align__(16) __half g_Wp16[DMODEL * DMODEL];
// bf16 hi/lo splits for attention (q pre-scaled by 1/8)
__device__ __align__(16) __nv_bfloat16 g_qhi[T_SEQ * DMODEL];
__device__ __align__(16) __nv_bfloat16 g_qlo[T_SEQ * DMODEL];
__device__ __align__(16) __nv_bfloat16 g_khi[T_SEQ * DMODEL];
__device__ __align__(16) __nv_bfloat16 g_klo[T_SEQ * DMODEL];
__device__ __align__(16) __nv_bfloat16 g_vhi[T_SEQ * DMODEL];
__device__ __align__(16) __nv_bfloat16 g_vlo[T_SEQ * DMODEL];

// ---------------------------------------------------------------------------
__device__ __forceinline__ uint32_t smem_u32(const void* p) {
    uint32_t a;
    asm("{ .reg .u64 t; cvta.to.shared.u64 t, %1; cvt.u32.u64 %0, t; }"
        : "=r"(a) : "l"(p));
    return a;
}

__device__ __forceinline__ void ldsm_x4(uint32_t* r, uint32_t addr) {
    asm volatile("ldmatrix.sync.aligned.m8n8.x4.shared.b16 {%0,%1,%2,%3}, [%4];"
                 : "=r"(r[0]), "=r"(r[1]), "=r"(r[2]), "=r"(r[3]) : "r"(addr));
}

__device__ __forceinline__ void ldsm_x4_t(uint32_t* r, uint32_t addr) {
    asm volatile("ldmatrix.sync.aligned.m8n8.x4.trans.shared.b16 {%0,%1,%2,%3}, [%4];"
                 : "=r"(r[0]), "=r"(r[1]), "=r"(r[2]), "=r"(r[3]) : "r"(addr));
}

// bf16 MMA (attention)
__device__ __forceinline__ void mma16816(float* d, const uint32_t* a,
                                         const uint32_t* b) {
    asm volatile(
        "mma.sync.aligned.m16n8k16.row.col.f32.bf16.bf16.f32 "
        "{%0,%1,%2,%3}, {%4,%5,%6,%7}, {%8,%9}, {%0,%1,%2,%3};"
        : "+f"(d[0]), "+f"(d[1]), "+f"(d[2]), "+f"(d[3])
        : "r"(a[0]), "r"(a[1]), "r"(a[2]), "r"(a[3]), "r"(b[0]), "r"(b[1]));
}

// fp16 MMA (dense GEMMs)
__device__ __forceinline__ void mma16816h(float* d, const uint32_t* a,
                                          const uint32_t* b) {
    asm volatile(
        "mma.sync.aligned.m16n8k16.row.col.f32.f16.f16.f32 "
        "{%0,%1,%2,%3}, {%4,%5,%6,%7}, {%8,%9}, {%0,%1,%2,%3};"
        : "+f"(d[0]), "+f"(d[1]), "+f"(d[2]), "+f"(d[3])
        : "r"(a[0]), "r"(a[1]), "r"(a[2]), "r"(a[3]), "r"(b[0]), "r"(b[1]));
}

__device__ __forceinline__ uint32_t pack_bf16x2(float lo, float hi) {
    uint32_t r;
    asm("cvt.rn.bf16x2.f32 %0, %1, %2;" : "=r"(r) : "f"(hi), "f"(lo));
    return r;
}

__device__ __forceinline__ uint32_t pack_half2(float lo, float hi) {
    uint32_t r;
    asm("cvt.rn.f16x2.f32 %0, %1, %2;" : "=r"(r) : "f"(hi), "f"(lo));
    return r;
}

__device__ __forceinline__ void cp_async16(uint32_t dst, const void* src) {
    asm volatile("cp.async.cg.shared.global [%0], [%1], 16;"
                 :: "r"(dst), "l"(src));
}
#define CP_COMMIT() asm volatile("cp.async.commit_group;" ::: "memory")
#define CP_WAIT(n)  asm volatile("cp.async.wait_group %0;" :: "n"(n) : "memory")

// ---------------------------------------------------------------------------
// fp32 -> fp16 conversion: y selects among {x, Wq, Wk, Wv, Wp}
// ---------------------------------------------------------------------------
extern "C" __global__ void pack16(const float* __restrict__ x,
                                  const float* __restrict__ wq,
                                  const float* __restrict__ wk,
                                  const float* __restrict__ wv,
                                  const float* __restrict__ wp)
{
    const int y = blockIdx.y;
    const float* s;
    __half* d;
    int n4;                                  // count of float4 groups
    if (y == 0)      { s = x;  d = g_x16;                     n4 = T_SEQ * DMODEL / 4; }
    else if (y == 1) { s = wq; d = g_Wqkv16;                  n4 = DMODEL * DMODEL / 4; }
    else if (y == 2) { s = wk; d = g_Wqkv16 + DMODEL * DMODEL;     n4 = DMODEL * DMODEL / 4; }
    else if (y == 3) { s = wv; d = g_Wqkv16 + 2 * DMODEL * DMODEL; n4 = DMODEL * DMODEL / 4; }
    else             { s = wp; d = g_Wp16;                    n4 = DMODEL * DMODEL / 4; }

    for (int i = blockIdx.x * blockDim.x + threadIdx.x; i < n4;
         i += gridDim.x * blockDim.x) {
        float4 v = ((const float4*)s)[i];
        uint2 o;
        o.x = pack_half2(v.x, v.y);
        o.y = pack_half2(v.z, v.w);
        ((uint2*)d)[i] = o;
    }
}

// ---------------------------------------------------------------------------
// mma.sync fp16 GEMM, cp.async 3-stage pipeline, 2 CTAs/SM.
// C_sel[M,1024] = A[M,1024] * B[NB,1024]^T (fp32 acc). 128x128 tile, 8 warps.
// ---------------------------------------------------------------------------
#define GEMM_SMEM_BYTES (NPIPE * 32768)

extern "C" __global__ void __launch_bounds__(256, 2)
gemm_f16(const __half* __restrict__ A,
         const __half* __restrict__ B,
         float* __restrict__ C0, float* __restrict__ C1,
         float* __restrict__ C2)
{
    extern __shared__ __align__(1024) char smem[];
    const uint32_t sbase = smem_u32(smem);

    const int tid  = threadIdx.x;
    const int wid  = tid >> 5;
    const int lane = tid & 31;
    const int n0 = blockIdx.x * 128;
    const int m0 = blockIdx.y * 128;
    const int wm = (wid >> 2) * 64;
    const int wn = (wid & 3) * 32;

    const int lrow = tid >> 3;
    const int lq   = tid & 7;
    const __half* Ag = A + (size_t)(m0 + lrow) * KDIM + lq * 8;
    const __half* Bg = B + (size_t)(n0 + lrow) * KDIM + lq * 8;
    const uint32_t st_off = lrow * 128 + ((lq ^ (lrow & 7)) << 4);

    uint32_t aoff[4][4], boff[4][2];
    #pragma unroll
    for (int ks = 0; ks < 4; ks++) {
        #pragma unroll
        for (int mf = 0; mf < 4; mf++) {
            int row = wm + 16 * mf + ((lane >> 3) & 1) * 8 + (lane & 7);
            int ch  = 2 * ks + (lane >> 4);
            aoff[ks][mf] = row * 128 + ((ch ^ (row & 7)) << 4);
        }
        #pragma unroll
        for (int np = 0; np < 2; np++) {
            int row = wn + 16 * np + ((lane >> 4) << 3) + (lane & 7);
            int ch  = 2 * ks + ((lane >> 3) & 1);
            boff[ks][np] = row * 128 + ((ch ^ (row & 7)) << 4);
        }
    }

    float acc[4][4][4];
    #pragma unroll
    for (int i = 0; i < 4; i++)
        #pragma unroll
        for (int j = 0; j < 4; j++)
            #pragma unroll
            for (int r = 0; r < 4; r++) acc[i][j][r] = 0.f;

    auto issue = [&](int s) {
        const uint32_t dst = sbase + (s % NPIPE) * 32768 + st_off;
        const size_t ko = (size_t)s * BK;
        #pragma unroll
        for (int j = 0; j < 4; j++) {
            cp_async16(dst + j * 4096,         Ag + (size_t)32 * j * KDIM + ko);
            cp_async16(dst + 16384 + j * 4096, Bg + (size_t)32 * j * KDIM + ko);
        }
        CP_COMMIT();
    };

    #pragma unroll
    for (int s = 0; s < NPIPE - 1; s++) issue(s);

    for (int s = 0; s < NSTAGES; s++) {
        if (s + 1 < NSTAGES) { CP_WAIT(NPIPE - 2); } else { CP_WAIT(0); }
        __syncthreads();
        if (s + NPIPE - 1 < NSTAGES) issue(s + NPIPE - 1);

        const uint32_t ab32 = sbase + (s % NPIPE) * 32768;
        const uint32_t bb32 = ab32 + 16384;
        #pragma unroll
        for (int ks = 0; ks < 4; ks++) {
            uint32_t af[4][4], bf[2][4];
            #pragma unroll
            for (int mf = 0; mf < 4; mf++)
                ldsm_x4(af[mf], ab32 + aoff[ks][mf]);
            #pragma unroll
            for (int np = 0; np < 2; np++)
                ldsm_x4(bf[np], bb32 + boff[ks][np]);
            #pragma unroll
            for (int mf = 0; mf < 4; mf++)
                #pragma unroll
                for (int nf = 0; nf < 4; nf++)
                    mma16816h(acc[mf][nf], af[mf], &bf[nf >> 1][(nf & 1) * 2]);
        }
        __syncthreads();
    }

    const int sel = n0 >> 10;
    float* __restrict__ C = (sel == 0) ? C0 : (sel == 1) ? C1 : C2;
    const int nl = n0 & 1023;
    const int gr = lane >> 2;
    const int gc = (lane & 3) * 2;
    #pragma unroll
    for (int mf = 0; mf < 4; mf++)
        #pragma unroll
        for (int nf = 0; nf < 4; nf++) {
            const int row = m0 + wm + 16 * mf + gr;
            const int col = nl + wn + 8 * nf + gc;
            *(float2*)&C[(size_t)row * DMODEL + col] =
                make_float2(acc[mf][nf][0], acc[mf][nf][1]);
            *(float2*)&C[(size_t)(row + 8) * DMODEL + col] =
                make_float2(acc[mf][nf][2], acc[mf][nf][3]);
        }
}

// ---------------------------------------------------------------------------
// Fused post: one warp per (t,h). Lane j owns dims j and j+32.
// v blend + rmsnorm + inline rotary (sincosf) + bf16 hi/lo emission.
// ---------------------------------------------------------------------------
extern "C" __global__ void __launch_bounds__(256)
qkv_post(const float* __restrict__ vi, const float* __restrict__ lambdas)
{
    const int u = blockIdx.x * 8 + (threadIdx.x >> 5);   // unit = t*16+h
    const int j = threadIdx.x & 31;
    const int t = u >> 4;
    const int h = u & 15;
    const int base = t * DMODEL + h * HDIM;
    const int i0 = base + j;
    const int i1 = base + j + 32;

    const float l0 = lambdas[0], l1 = lambdas[1];
    {
        float v0 = fmaf(l0, g_v[i0], l1 * vi[i0]);
        float v1 = fmaf(l0, g_v[i1], l1 * vi[i1]);
        __nv_bfloat16 h0 = __float2bfloat16(v0);
        __nv_bfloat16 h1 = __float2bfloat16(v1);
        g_vhi[i0] = h0; g_vlo[i0] = __float2bfloat16(v0 - __bfloat162float(h0));
        g_vhi[i1] = h1; g_vlo[i1] = __float2bfloat16(v1 - __bfloat162float(h1));
    }

    float q0 = g_q[i0], q1 = g_q[i1];
    float k0 = g_k[i0], k1 = g_k[i1];
    float qs = q0 * q0 + q1 * q1;
    float ks = k0 * k0 + k1 * k1;
    #pragma unroll
    for (int o = 16; o > 0; o >>= 1) {
        qs += __shfl_xor_sync(0xffffffffu, qs, o);
        ks += __shfl_xor_sync(0xffffffffu, ks, o);
    }
    const float eps = 1.1920929e-7f;
    const float rq = rsqrtf(qs * (1.f / 64.f) + eps);
    const float rk = rsqrtf(ks * (1.f / 64.f) + eps);
    q0 *= rq; q1 *= rq; k0 *= rk; k1 *= rk;

    float c = 1.f, s = 0.f;
    if (j < 16) {
        float invf = exp2f(-10.0f * (float)j * (1.0f / 15.0f));
        sincosf((float)t * invf, &s, &c);
    }
    float qa = (q0 * c + q1 * s) * 0.125f;
    float qb = (q1 * c - q0 * s) * 0.125f;
    float ka =  k0 * c + k1 * s;
    float kb =  k1 * c - k0 * s;

    __nv_bfloat16 qha = __float2bfloat16(qa);
    __nv_bfloat16 qhb = __float2bfloat16(qb);
    g_qhi[i0] = qha; g_qlo[i0] = __float2bfloat16(qa - __bfloat162float(qha));
    g_qhi[i1] = qhb; g_qlo[i1] = __float2bfloat16(qb - __bfloat162float(qhb));
    __nv_bfloat16 kha = __float2bfloat16(ka);
    __nv_bfloat16 khb = __float2bfloat16(kb);
    g_khi[i0] = kha; g_klo[i0] = __float2bfloat16(ka - __bfloat162float(kha));
    g_khi[i1] = khb; g_klo[i1] = __float2bfloat16(kb - __bfloat162float(khb));
}

// ---------------------------------------------------------------------------
// Tensor-core flash attention, causal. 128-row Q tiles, 64-row K/V tiles,
// 8 warps, cp.async double-buffered K/V, heavy CTAs first.
// Epilogue writes y as fp16 (proj GEMM input).
// ---------------------------------------------------------------------------
#define SW(row, q) ((row) * 128 + (((q) ^ ((row) & 7)) << 4))
#define FLASH_SMEM_BYTES 65536

extern "C" __global__ void __launch_bounds__(256)
flash_mma()
{
    extern __shared__ __align__(1024) char smd[];
    const uint32_t sb = smem_u32(smd);

    const int qt   = (int)gridDim.x - 1 - (int)blockIdx.x;  // heavy first
    const int h    = blockIdx.y;
    const int tid  = threadIdx.x;
    const int lane = tid & 31;
    const int wq   = tid >> 5;
    const int q0   = qt * 128;
    const int ktmax = 2 * qt + 1;
    const size_t hcol = (size_t)h * HDIM;

    const int krow = tid >> 2;
    const int kq2  = (tid & 3) * 2;
    auto issue_kv = [&](int kt, int buf) {
        const uint32_t dst = sb + buf * 32768;
        const size_t gb = (size_t)(kt * 64 + krow) * DMODEL + hcol + kq2 * 8;
        #pragma unroll
        for (int j = 0; j < 2; j++) {
            const uint32_t so = SW(krow, kq2 + j);
            const size_t go = gb + (size_t)j * 8;
            cp_async16(dst + so,         g_khi + go);
            cp_async16(dst + 8192 + so,  g_klo + go);
            cp_async16(dst + 16384 + so, g_vhi + go);
            cp_async16(dst + 24576 + so, g_vlo + go);
        }
        CP_COMMIT();
    };

    issue_kv(0, 0);
    {
        const int qrow = tid >> 1;
        const int qqb  = (tid & 1) * 4;
        const uint32_t dst = sb + 32768;
        const size_t gb = (size_t)(q0 + qrow) * DMODEL + hcol + qqb * 8;
        #pragma unroll
        for (int j = 0; j < 4; j++) {
            const uint32_t so = SW(qrow, qqb + j);
            cp_async16(dst + so,         g_qhi + gb + (size_t)j * 8);
            cp_async16(dst + 16384 + so, g_qlo + gb + (size_t)j * 8);
        }
        CP_COMMIT();
    }
    CP_WAIT(0);
    __syncthreads();

    uint32_t qh[4][4], ql[4][4];
    #pragma unroll
    for (int ks = 0; ks < 4; ks++) {
        int row = wq * 16 + ((lane >> 3) & 1) * 8 + (lane & 7);
        int ch  = 2 * ks + (lane >> 4);
        uint32_t off = SW(row, ch);
        ldsm_x4(qh[ks], sb + 32768 + off);
        ldsm_x4(ql[ks], sb + 32768 + 16384 + off);
    }
    __syncthreads();

    float O[8][4];
    #pragma unroll
    for (int i = 0; i < 8; i++)
        #pragma unroll
        for (int r = 0; r < 4; r++) O[i][r] = 0.f;
    float m0r = -INFINITY, m1r = -INFINITY, l0r = 0.f, l1r = 0.f;

    const int gr = lane >> 2;
    const int gc = 2 * (lane & 3);
    const int r0 = wq * 16 + gr;
    const int r1 = r0 + 8;
    const int grow0 = q0 + r0;
    const int grow1 = q0 + r1;

    for (int kt = 0; kt <= ktmax; kt++) {
        const int buf = kt & 1;
        if (kt > 0) { CP_WAIT(0); __syncthreads(); }
        if (kt + 1 <= ktmax) issue_kv(kt + 1, buf ^ 1);

        const uint32_t KHI = sb + buf * 32768;
        const uint32_t KLO = KHI + 8192;
        const uint32_t VHI = KHI + 16384;
        const uint32_t VLO = KHI + 24576;

        float S[8][4];
        #pragma unroll
        for (int i = 0; i < 8; i++)
            #pragma unroll
            for (int r = 0; r < 4; r++) S[i][r] = 0.f;

        #pragma unroll
        for (int ks = 0; ks < 4; ks++) {
            uint32_t bh[4][4], bl[4][4];
            #pragma unroll
            for (int np = 0; np < 4; np++) {
                int row = np * 16 + ((lane >> 4) << 3) + (lane & 7);
                int ch  = 2 * ks + ((lane >> 3) & 1);
                uint32_t off = SW(row, ch);
                ldsm_x4(bh[np], KHI + off);
                ldsm_x4(bl[np], KLO + off);
            }
            #pragma unroll
            for (int nf = 0; nf < 8; nf++) {
                const uint32_t* b  = &bh[nf >> 1][(nf & 1) * 2];
                const uint32_t* b2 = &bl[nf >> 1][(nf & 1) * 2];
                mma16816(S[nf], qh[ks], b);
                mma16816(S[nf], ql[ks], b);
                mma16816(S[nf], qh[ks], b2);
            }
        }

        if (kt >= 2 * qt) {
            const int k0c = kt * 64;
            #pragma unroll
            for (int nf = 0; nf < 8; nf++) {
                int cg = k0c + 8 * nf + gc;
                if (cg     > grow0) S[nf][0] = -1e30f;
                if (cg + 1 > grow0) S[nf][1] = -1e30f;
                if (cg     > grow1) S[nf][2] = -1e30f;
                if (cg + 1 > grow1) S[nf][3] = -1e30f;
            }
        }

        float mx0 = -INFINITY, mx1 = -INFINITY;
        #pragma unroll
        for (int nf = 0; nf < 8; nf++) {
            mx0 = fmaxf(mx0, fmaxf(S[nf][0], S[nf][1]));
            mx1 = fmaxf(mx1, fmaxf(S[nf][2], S[nf][3]));
        }
        mx0 = fmaxf(mx0, __shfl_xor_sync(0xffffffffu, mx0, 1));
        mx0 = fmaxf(mx0, __shfl_xor_sync(0xffffffffu, mx0, 2));
        mx1 = fmaxf(mx1, __shfl_xor_sync(0xffffffffu, mx1, 1));
        mx1 = fmaxf(mx1, __shfl_xor_sync(0xffffffffu, mx1, 2));

        const float mn0 = fmaxf(m0r, mx0);
        const float mn1 = fmaxf(m1r, mx1);
        const float a0 = __expf(m0r - mn0);
        const float a1 = __expf(m1r - mn1);

        float s0 = 0.f, s1 = 0.f;
        uint32_t Ahi[4][4], Alo[4][4];
        #pragma unroll
        for (int js = 0; js < 4; js++) {
            #pragma unroll
            for (int half = 0; half < 2; half++) {
                const int nf = 2 * js + half;
                float p0 = __expf(S[nf][0] - mn0);
                float p1 = __expf(S[nf][1] - mn0);
                float p2 = __expf(S[nf][2] - mn1);
                float p3 = __expf(S[nf][3] - mn1);
                s0 += p0 + p1;
                s1 += p2 + p3;
                float h0 = __bfloat162float(__float2bfloat16(p0));
                float h1 = __bfloat162float(__float2bfloat16(p1));
                float h2 = __bfloat162float(__float2bfloat16(p2));
                float h3 = __bfloat162float(__float2bfloat16(p3));
                Ahi[js][half * 2 + 0] = pack_bf16x2(h0, h1);
                Ahi[js][half * 2 + 1] = pack_bf16x2(h2, h3);
                Alo[js][half * 2 + 0] = pack_bf16x2(p0 - h0, p1 - h1);
                Alo[js][half * 2 + 1] = pack_bf16x2(p2 - h2, p3 - h3);
            }
        }
        s0 += __shfl_xor_sync(0xffffffffu, s0, 1);
        s0 += __shfl_xor_sync(0xffffffffu, s0, 2);
        s1 += __shfl_xor_sync(0xffffffffu, s1, 1);
        s1 += __shfl_xor_sync(0xffffffffu, s1, 2);
        l0r = l0r * a0 + s0;
        l1r = l1r * a1 + s1;
        m0r = mn0;
        m1r = mn1;

        #pragma unroll
        for (int nf = 0; nf < 8; nf++) {
            O[nf][0] *= a0; O[nf][1] *= a0;
            O[nf][2] *= a1; O[nf][3] *= a1;
        }
        #pragma unroll
        for (int js = 0; js < 4; js++) {
            uint32_t vh[4][4], vl[4][4];
            #pragma unroll
            for (int np = 0; np < 4; np++) {
                int row = js * 16 + ((lane >> 3) & 1) * 8 + (lane & 7);
                int ch  = 2 * np + (lane >> 4);
                uint32_t off = SW(row, ch);
                ldsm_x4_t(vh[np], VHI + off);
                ldsm_x4_t(vl[np], VLO + off);
            }
            #pragma unroll
            for (int nf = 0; nf < 8; nf++) {
                const uint32_t* b  = &vh[nf >> 1][(nf & 1) * 2];
                const uint32_t* b2 = &vl[nf >> 1][(nf & 1) * 2];
                mma16816(O[nf], Ahi[js], b);
                mma16816(O[nf], Alo[js], b);
                mma16816(O[nf], Ahi[js], b2);
            }
        }
        __syncthreads();
    }

    // epilogue: y as fp16 (input to proj GEMM)
    const float i0 = 1.f / l0r;
    const float i1 = 1.f / l1r;
    #pragma unroll
    for (int nf = 0; nf < 8; nf++) {
        const size_t col = hcol + 8 * nf + gc;
        *(uint32_t*)(g_y16 + (size_t)grow0 * DMODEL + col) =
            pack_half2(O[nf][0] * i0, O[nf][1] * i0);
        *(uint32_t*)(g_y16 + (size_t)grow1 * DMODEL + col) =
            pack_half2(O[nf][2] * i1, O[nf][3] * i1);
    }
}

// ---------------------------------------------------------------------------
extern "C" void kernel_launch(void* const* d_in, const int* in_sizes, int n_in,
                              void* d_out, int out_size)
{
    const float* x   = (const float*)d_in[0];
    const float* vi  = (const float*)d_in[1];
    const float* Wq  = (const float*)d_in[2];
    const float* Wk  = (const float*)d_in[3];
    const float* Wv  = (const float*)d_in[4];
    const float* Wp  = (const float*)d_in[5];
    const float* lam = (const float*)d_in[6];
    float* out = (float*)d_out;

    float *gq, *gk, *gv;
    __half *gx16, *gy16, *gWqkv16, *gWp16;
    cudaGetSymbolAddress((void**)&gq, g_q);
    cudaGetSymbolAddress((void**)&gk, g_k);
    cudaGetSymbolAddress((void**)&gv, g_v);
    cudaGetSymbolAddress((void**)&gx16, g_x16);
    cudaGetSymbolAddress((void**)&gy16, g_y16);
    cudaGetSymbolAddress((void**)&gWqkv16, g_Wqkv16);
    cudaGetSymbolAddress((void**)&gWp16, g_Wp16);

    cudaFuncSetAttribute(gemm_f16, cudaFuncAttributeMaxDynamicSharedMemorySize,
                         GEMM_SMEM_BYTES);
    cudaFuncSetAttribute(flash_mma, cudaFuncAttributeMaxDynamicSharedMemorySize,
                         FLASH_SMEM_BYTES);

    pack16<<<dim3(256, 5), 256>>>(x, Wq, Wk, Wv, Wp);

    // fused QKV: N = 3072
    gemm_f16<<<dim3(3 * DMODEL / 128, T_SEQ / 128), 256, GEMM_SMEM_BYTES>>>(
        gx16, gWqkv16, gq, gk, gv);

    qkv_post<<<T_SEQ * NHEADS / 8, 256>>>(vi, lam);

    flash_mma<<<dim3(T_SEQ / 128, NHEADS), 256, FLASH_SMEM_BYTES>>>();

    gemm_f16<<<dim3(DMODEL / 128, T_SEQ / 128), 256, GEMM_SMEM_BYTES>>>(
        gy16, gWp16, out, out, out);
}

// round 9
// speedup vs baseline: 7.2527x; 1.4641x over previous
#include <cuda_runtime.h>
#include <cuda_bf16.h>
#include <cuda_fp16.h>
#include <math.h>
#include <stdint.h>

#define T_SEQ  2048
#define DMODEL 1024
#define NHEADS 16
#define HDIM   64
#define KDIM   1024
#define BK     64
#define NSTAGES (KDIM / BK)      // 16
#define NPIPE  3

// ---------------------------------------------------------------------------
// Scratch (static device globals — no allocation allowed in kernel_launch)
// ---------------------------------------------------------------------------
__device__ float g_q[T_SEQ * DMODEL];
__device__ float g_k[T_SEQ * DMODEL];
__device__ float g_v[T_SEQ * DMODEL];
__device__ __align__(16) __half g_x16[T_SEQ * DMODEL];
__device__ __align__(16) __half g_y16[T_SEQ * DMODEL];
__device__ __align__(16) __half g_Wqkv16[3 * DMODEL * DMODEL];
__device__ __align__(16) __half g_Wp16[DMODEL * DMODEL];
// fp16 q/k/v for attention (q pre-scaled by 1/8)
__device__ __align__(16) __half g_q16[T_SEQ * DMODEL];
__device__ __align__(16) __half g_k16[T_SEQ * DMODEL];
__device__ __align__(16) __half g_v16[T_SEQ * DMODEL];

// ---------------------------------------------------------------------------
__device__ __forceinline__ uint32_t smem_u32(const void* p) {
    uint32_t a;
    asm("{ .reg .u64 t; cvta.to.shared.u64 t, %1; cvt.u32.u64 %0, t; }"
        : "=r"(a) : "l"(p));
    return a;
}

__device__ __forceinline__ void ldsm_x4(uint32_t* r, uint32_t addr) {
    asm volatile("ldmatrix.sync.aligned.m8n8.x4.shared.b16 {%0,%1,%2,%3}, [%4];"
                 : "=r"(r[0]), "=r"(r[1]), "=r"(r[2]), "=r"(r[3]) : "r"(addr));
}

__device__ __forceinline__ void ldsm_x4_t(uint32_t* r, uint32_t addr) {
    asm volatile("ldmatrix.sync.aligned.m8n8.x4.trans.shared.b16 {%0,%1,%2,%3}, [%4];"
                 : "=r"(r[0]), "=r"(r[1]), "=r"(r[2]), "=r"(r[3]) : "r"(addr));
}

// fp16 MMA, fp32 accumulate
__device__ __forceinline__ void mma16816h(float* d, const uint32_t* a,
                                          const uint32_t* b) {
    asm volatile(
        "mma.sync.aligned.m16n8k16.row.col.f32.f16.f16.f32 "
        "{%0,%1,%2,%3}, {%4,%5,%6,%7}, {%8,%9}, {%0,%1,%2,%3};"
        : "+f"(d[0]), "+f"(d[1]), "+f"(d[2]), "+f"(d[3])
        : "r"(a[0]), "r"(a[1]), "r"(a[2]), "r"(a[3]), "r"(b[0]), "r"(b[1]));
}

__device__ __forceinline__ uint32_t pack_half2(float lo, float hi) {
    uint32_t r;
    asm("cvt.rn.f16x2.f32 %0, %1, %2;" : "=r"(r) : "f"(hi), "f"(lo));
    return r;
}

__device__ __forceinline__ void cp_async16(uint32_t dst, const void* src) {
    asm volatile("cp.async.cg.shared.global [%0], [%1], 16;"
                 :: "r"(dst), "l"(src));
}
#define CP_COMMIT() asm volatile("cp.async.commit_group;" ::: "memory")
#define CP_WAIT(n)  asm volatile("cp.async.wait_group %0;" :: "n"(n) : "memory")

// ---------------------------------------------------------------------------
// fp32 -> fp16 conversion: y selects among {x, Wq, Wk, Wv, Wp}
// ---------------------------------------------------------------------------
extern "C" __global__ void pack16(const float* __restrict__ x,
                                  const float* __restrict__ wq,
                                  const float* __restrict__ wk,
                                  const float* __restrict__ wv,
                                  const float* __restrict__ wp)
{
    const int y = blockIdx.y;
    const float* s;
    __half* d;
    int n4;
    if (y == 0)      { s = x;  d = g_x16;                          n4 = T_SEQ * DMODEL / 4; }
    else if (y == 1) { s = wq; d = g_Wqkv16;                       n4 = DMODEL * DMODEL / 4; }
    else if (y == 2) { s = wk; d = g_Wqkv16 + DMODEL * DMODEL;     n4 = DMODEL * DMODEL / 4; }
    else if (y == 3) { s = wv; d = g_Wqkv16 + 2 * DMODEL * DMODEL; n4 = DMODEL * DMODEL / 4; }
    else             { s = wp; d = g_Wp16;                         n4 = DMODEL * DMODEL / 4; }

    for (int i = blockIdx.x * blockDim.x + threadIdx.x; i < n4;
         i += gridDim.x * blockDim.x) {
        float4 v = ((const float4*)s)[i];
        uint2 o;
        o.x = pack_half2(v.x, v.y);
        o.y = pack_half2(v.z, v.w);
        ((uint2*)d)[i] = o;
    }
}

// ---------------------------------------------------------------------------
// mma.sync fp16 GEMM, cp.async 3-stage pipeline, 2 CTAs/SM.
// ---------------------------------------------------------------------------
#define GEMM_SMEM_BYTES (NPIPE * 32768)

extern "C" __global__ void __launch_bounds__(256, 2)
gemm_f16(const __half* __restrict__ A,
         const __half* __restrict__ B,
         float* __restrict__ C0, float* __restrict__ C1,
         float* __restrict__ C2)
{
    extern __shared__ __align__(1024) char smem[];
    const uint32_t sbase = smem_u32(smem);

    const int tid  = threadIdx.x;
    const int wid  = tid >> 5;
    const int lane = tid & 31;
    const int n0 = blockIdx.x * 128;
    const int m0 = blockIdx.y * 128;
    const int wm = (wid >> 2) * 64;
    const int wn = (wid & 3) * 32;

    const int lrow = tid >> 3;
    const int lq   = tid & 7;
    const __half* Ag = A + (size_t)(m0 + lrow) * KDIM + lq * 8;
    const __half* Bg = B + (size_t)(n0 + lrow) * KDIM + lq * 8;
    const uint32_t st_off = lrow * 128 + ((lq ^ (lrow & 7)) << 4);

    uint32_t aoff[4][4], boff[4][2];
    #pragma unroll
    for (int ks = 0; ks < 4; ks++) {
        #pragma unroll
        for (int mf = 0; mf < 4; mf++) {
            int row = wm + 16 * mf + ((lane >> 3) & 1) * 8 + (lane & 7);
            int ch  = 2 * ks + (lane >> 4);
            aoff[ks][mf] = row * 128 + ((ch ^ (row & 7)) << 4);
        }
        #pragma unroll
        for (int np = 0; np < 2; np++) {
            int row = wn + 16 * np + ((lane >> 4) << 3) + (lane & 7);
            int ch  = 2 * ks + ((lane >> 3) & 1);
            boff[ks][np] = row * 128 + ((ch ^ (row & 7)) << 4);
        }
    }

    float acc[4][4][4];
    #pragma unroll
    for (int i = 0; i < 4; i++)
        #pragma unroll
        for (int j = 0; j < 4; j++)
            #pragma unroll
            for (int r = 0; r < 4; r++) acc[i][j][r] = 0.f;

    auto issue = [&](int s) {
        const uint32_t dst = sbase + (s % NPIPE) * 32768 + st_off;
        const size_t ko = (size_t)s * BK;
        #pragma unroll
        for (int j = 0; j < 4; j++) {
            cp_async16(dst + j * 4096,         Ag + (size_t)32 * j * KDIM + ko);
            cp_async16(dst + 16384 + j * 4096, Bg + (size_t)32 * j * KDIM + ko);
        }
        CP_COMMIT();
    };

    #pragma unroll
    for (int s = 0; s < NPIPE - 1; s++) issue(s);

    for (int s = 0; s < NSTAGES; s++) {
        if (s + 1 < NSTAGES) { CP_WAIT(NPIPE - 2); } else { CP_WAIT(0); }
        __syncthreads();
        if (s + NPIPE - 1 < NSTAGES) issue(s + NPIPE - 1);

        const uint32_t ab32 = sbase + (s % NPIPE) * 32768;
        const uint32_t bb32 = ab32 + 16384;
        #pragma unroll
        for (int ks = 0; ks < 4; ks++) {
            uint32_t af[4][4], bf[2][4];
            #pragma unroll
            for (int mf = 0; mf < 4; mf++)
                ldsm_x4(af[mf], ab32 + aoff[ks][mf]);
            #pragma unroll
            for (int np = 0; np < 2; np++)
                ldsm_x4(bf[np], bb32 + boff[ks][np]);
            #pragma unroll
            for (int mf = 0; mf < 4; mf++)
                #pragma unroll
                for (int nf = 0; nf < 4; nf++)
                    mma16816h(acc[mf][nf], af[mf], &bf[nf >> 1][(nf & 1) * 2]);
        }
        __syncthreads();
    }

    const int sel = n0 >> 10;
    float* __restrict__ C = (sel == 0) ? C0 : (sel == 1) ? C1 : C2;
    const int nl = n0 & 1023;
    const int gr = lane >> 2;
    const int gc = (lane & 3) * 2;
    #pragma unroll
    for (int mf = 0; mf < 4; mf++)
        #pragma unroll
        for (int nf = 0; nf < 4; nf++) {
            const int row = m0 + wm + 16 * mf + gr;
            const int col = nl + wn + 8 * nf + gc;
            *(float2*)&C[(size_t)row * DMODEL + col] =
                make_float2(acc[mf][nf][0], acc[mf][nf][1]);
            *(float2*)&C[(size_t)(row + 8) * DMODEL + col] =
                make_float2(acc[mf][nf][2], acc[mf][nf][3]);
        }
}

// ---------------------------------------------------------------------------
// Fused post: one warp per (t,h). Lane j owns dims j and j+32.
// v blend + rmsnorm + inline rotary (sincosf) + fp16 emission.
// ---------------------------------------------------------------------------
extern "C" __global__ void __launch_bounds__(256)
qkv_post(const float* __restrict__ vi, const float* __restrict__ lambdas)
{
    const int u = blockIdx.x * 8 + (threadIdx.x >> 5);   // unit = t*16+h
    const int j = threadIdx.x & 31;
    const int t = u >> 4;
    const int h = u & 15;
    const int base = t * DMODEL + h * HDIM;
    const int i0 = base + j;
    const int i1 = base + j + 32;

    const float l0 = lambdas[0], l1 = lambdas[1];
    {
        float v0 = fmaf(l0, g_v[i0], l1 * vi[i0]);
        float v1 = fmaf(l0, g_v[i1], l1 * vi[i1]);
        g_v16[i0] = __float2half(v0);
        g_v16[i1] = __float2half(v1);
    }

    float q0 = g_q[i0], q1 = g_q[i1];
    float k0 = g_k[i0], k1 = g_k[i1];
    float qs = q0 * q0 + q1 * q1;
    float ks = k0 * k0 + k1 * k1;
    #pragma unroll
    for (int o = 16; o > 0; o >>= 1) {
        qs += __shfl_xor_sync(0xffffffffu, qs, o);
        ks += __shfl_xor_sync(0xffffffffu, ks, o);
    }
    const float eps = 1.1920929e-7f;
    const float rq = rsqrtf(qs * (1.f / 64.f) + eps);
    const float rk = rsqrtf(ks * (1.f / 64.f) + eps);
    q0 *= rq; q1 *= rq; k0 *= rk; k1 *= rk;

    float c = 1.f, s = 0.f;
    if (j < 16) {
        float invf = exp2f(-10.0f * (float)j * (1.0f / 15.0f));
        sincosf((float)t * invf, &s, &c);
    }
    float qa = (q0 * c + q1 * s) * 0.125f;
    float qb = (q1 * c - q0 * s) * 0.125f;
    float ka =  k0 * c + k1 * s;
    float kb =  k1 * c - k0 * s;

    g_q16[i0] = __float2half(qa);
    g_q16[i1] = __float2half(qb);
    g_k16[i0] = __float2half(ka);
    g_k16[i1] = __float2half(kb);
}

// ---------------------------------------------------------------------------
// fp16 tensor-core flash attention, causal. 128-row Q tiles, 64-row K/V
// tiles, 8 warps, cp.async double-buffered K/V, heavy CTAs first.
// Single-term fp16 S and PV (fp32 accum). Epilogue writes y fp16.
// smem: buf0 16KB (K 8K | V 8K), buf1 16KB; Q staged at +32KB (16KB).
// ---------------------------------------------------------------------------
#define SW(row, q) ((row) * 128 + (((q) ^ ((row) & 7)) << 4))
#define FLASH_SMEM_BYTES (49152)

extern "C" __global__ void __launch_bounds__(256, 2)
flash_mma()
{
    extern __shared__ __align__(1024) char smd[];
    const uint32_t sb = smem_u32(smd);

    const int qt   = (int)gridDim.x - 1 - (int)blockIdx.x;  // heavy first
    const int h    = blockIdx.y;
    const int tid  = threadIdx.x;
    const int lane = tid & 31;
    const int wq   = tid >> 5;
    const int q0   = qt * 128;
    const int ktmax = 2 * qt + 1;
    const size_t hcol = (size_t)h * HDIM;

    const int krow = tid >> 2;            // 0..63
    const int kq2  = (tid & 3) * 2;       // 0,2,4,6
    auto issue_kv = [&](int kt, int buf) {
        const uint32_t dst = sb + buf * 16384;
        const size_t gb = (size_t)(kt * 64 + krow) * DMODEL + hcol + kq2 * 8;
        #pragma unroll
        for (int j = 0; j < 2; j++) {
            const uint32_t so = SW(krow, kq2 + j);
            const size_t go = gb + (size_t)j * 8;
            cp_async16(dst + so,        g_k16 + go);
            cp_async16(dst + 8192 + so, g_v16 + go);
        }
        CP_COMMIT();
    };

    issue_kv(0, 0);
    {
        const int qrow = tid >> 1;
        const int qqb  = (tid & 1) * 4;
        const uint32_t dst = sb + 32768;
        const size_t gb = (size_t)(q0 + qrow) * DMODEL + hcol + qqb * 8;
        #pragma unroll
        for (int j = 0; j < 4; j++)
            cp_async16(dst + SW(qrow, qqb + j), g_q16 + gb + (size_t)j * 8);
        CP_COMMIT();
    }
    CP_WAIT(0);
    __syncthreads();

    uint32_t qf[4][4];
    #pragma unroll
    for (int ks = 0; ks < 4; ks++) {
        int row = wq * 16 + ((lane >> 3) & 1) * 8 + (lane & 7);
        int ch  = 2 * ks + (lane >> 4);
        ldsm_x4(qf[ks], sb + 32768 + SW(row, ch));
    }
    __syncthreads();

    float O[8][4];
    #pragma unroll
    for (int i = 0; i < 8; i++)
        #pragma unroll
        for (int r = 0; r < 4; r++) O[i][r] = 0.f;
    float m0r = -INFINITY, m1r = -INFINITY, l0r = 0.f, l1r = 0.f;

    const int gr = lane >> 2;
    const int gc = 2 * (lane & 3);
    const int r0 = wq * 16 + gr;
    const int r1 = r0 + 8;
    const int grow0 = q0 + r0;
    const int grow1 = q0 + r1;

    for (int kt = 0; kt <= ktmax; kt++) {
        const int buf = kt & 1;
        if (kt > 0) { CP_WAIT(0); __syncthreads(); }
        if (kt + 1 <= ktmax) issue_kv(kt + 1, buf ^ 1);

        const uint32_t KB = sb + buf * 16384;
        const uint32_t VB = KB + 8192;

        float S[8][4];
        #pragma unroll
        for (int i = 0; i < 8; i++)
            #pragma unroll
            for (int r = 0; r < 4; r++) S[i][r] = 0.f;

        #pragma unroll
        for (int ks = 0; ks < 4; ks++) {
            uint32_t bh[4][4];
            #pragma unroll
            for (int np = 0; np < 4; np++) {
                int row = np * 16 + ((lane >> 4) << 3) + (lane & 7);
                int ch  = 2 * ks + ((lane >> 3) & 1);
                ldsm_x4(bh[np], KB + SW(row, ch));
            }
            #pragma unroll
            for (int nf = 0; nf < 8; nf++)
                mma16816h(S[nf], qf[ks], &bh[nf >> 1][(nf & 1) * 2]);
        }

        if (kt >= 2 * qt) {
            const int k0c = kt * 64;
            #pragma unroll
            for (int nf = 0; nf < 8; nf++) {
                int cg = k0c + 8 * nf + gc;
                if (cg     > grow0) S[nf][0] = -1e30f;
                if (cg + 1 > grow0) S[nf][1] = -1e30f;
                if (cg     > grow1) S[nf][2] = -1e30f;
                if (cg + 1 > grow1) S[nf][3] = -1e30f;
            }
        }

        float mx0 = -INFINITY, mx1 = -INFINITY;
        #pragma unroll
        for (int nf = 0; nf < 8; nf++) {
            mx0 = fmaxf(mx0, fmaxf(S[nf][0], S[nf][1]));
            mx1 = fmaxf(mx1, fmaxf(S[nf][2], S[nf][3]));
        }
        mx0 = fmaxf(mx0, __shfl_xor_sync(0xffffffffu, mx0, 1));
        mx0 = fmaxf(mx0, __shfl_xor_sync(0xffffffffu, mx0, 2));
        mx1 = fmaxf(mx1, __shfl_xor_sync(0xffffffffu, mx1, 1));
        mx1 = fmaxf(mx1, __shfl_xor_sync(0xffffffffu, mx1, 2));

        const float mn0 = fmaxf(m0r, mx0);
        const float mn1 = fmaxf(m1r, mx1);
        const float a0 = __expf(m0r - mn0);
        const float a1 = __expf(m1r - mn1);

        float s0 = 0.f, s1 = 0.f;
        uint32_t Ap[4][4];
        #pragma unroll
        for (int js = 0; js < 4; js++) {
            #pragma unroll
            for (int half = 0; half < 2; half++) {
                const int nf = 2 * js + half;
                float p0 = __expf(S[nf][0] - mn0);
                float p1 = __expf(S[nf][1] - mn0);
                float p2 = __expf(S[nf][2] - mn1);
                float p3 = __expf(S[nf][3] - mn1);
                s0 += p0 + p1;
                s1 += p2 + p3;
                Ap[js][half * 2 + 0] = pack_half2(p0, p1);
                Ap[js][half * 2 + 1] = pack_half2(p2, p3);
            }
        }
        s0 += __shfl_xor_sync(0xffffffffu, s0, 1);
        s0 += __shfl_xor_sync(0xffffffffu, s0, 2);
        s1 += __shfl_xor_sync(0xffffffffu, s1, 1);
        s1 += __shfl_xor_sync(0xffffffffu, s1, 2);
        l0r = l0r * a0 + s0;
        l1r = l1r * a1 + s1;
        m0r = mn0;
        m1r = mn1;

        #pragma unroll
        for (int nf = 0; nf < 8; nf++) {
            O[nf][0] *= a0; O[nf][1] *= a0;
            O[nf][2] *= a1; O[nf][3] *= a1;
        }
        #pragma unroll
        for (int js = 0; js < 4; js++) {
            uint32_t vh[4][4];
            #pragma unroll
            for (int np = 0; np < 4; np++) {
                int row = js * 16 + ((lane >> 3) & 1) * 8 + (lane & 7);
                int ch  = 2 * np + (lane >> 4);
                ldsm_x4_t(vh[np], VB + SW(row, ch));
            }
            #pragma unroll
            for (int nf = 0; nf < 8; nf++)
                mma16816h(O[nf], Ap[js], &vh[nf >> 1][(nf & 1) * 2]);
        }
        __syncthreads();
    }

    // epilogue: y as fp16 (input to proj GEMM)
    const float i0 = 1.f / l0r;
    const float i1 = 1.f / l1r;
    #pragma unroll
    for (int nf = 0; nf < 8; nf++) {
        const size_t col = hcol + 8 * nf + gc;
        *(uint32_t*)(g_y16 + (size_t)grow0 * DMODEL + col) =
            pack_half2(O[nf][0] * i0, O[nf][1] * i0);
        *(uint32_t*)(g_y16 + (size_t)grow1 * DMODEL + col) =
            pack_half2(O[nf][2] * i1, O[nf][3] * i1);
    }
}

// ---------------------------------------------------------------------------
extern "C" void kernel_launch(void* const* d_in, const int* in_sizes, int n_in,
                              void* d_out, int out_size)
{
    const float* x   = (const float*)d_in[0];
    const float* vi  = (const float*)d_in[1];
    const float* Wq  = (const float*)d_in[2];
    const float* Wk  = (const float*)d_in[3];
    const float* Wv  = (const float*)d_in[4];
    const float* Wp  = (const float*)d_in[5];
    const float* lam = (const float*)d_in[6];
    float* out = (float*)d_out;

    float *gq, *gk, *gv;
    __half *gx16, *gy16, *gWqkv16, *gWp16;
    cudaGetSymbolAddress((void**)&gq, g_q);
    cudaGetSymbolAddress((void**)&gk, g_k);
    cudaGetSymbolAddress((void**)&gv, g_v);
    cudaGetSymbolAddress((void**)&gx16, g_x16);
    cudaGetSymbolAddress((void**)&gy16, g_y16);
    cudaGetSymbolAddress((void**)&gWqkv16, g_Wqkv16);
    cudaGetSymbolAddress((void**)&gWp16, g_Wp16);

    cudaFuncSetAttribute(gemm_f16, cudaFuncAttributeMaxDynamicSharedMemorySize,
                         GEMM_SMEM_BYTES);
    cudaFuncSetAttribute(flash_mma, cudaFuncAttributeMaxDynamicSharedMemorySize,
                         FLASH_SMEM_BYTES);

    pack16<<<dim3(256, 5), 256>>>(x, Wq, Wk, Wv, Wp);

    // fused QKV: N = 3072
    gemm_f16<<<dim3(3 * DMODEL / 128, T_SEQ / 128), 256, GEMM_SMEM_BYTES>>>(
        gx16, gWqkv16, gq, gk, gv);

    qkv_post<<<T_SEQ * NHEADS / 8, 256>>>(vi, lam);

    flash_mma<<<dim3(T_SEQ / 128, NHEADS), 256, FLASH_SMEM_BYTES>>>();

    gemm_f16<<<dim3(DMODEL / 128, T_SEQ / 128), 256, GEMM_SMEM_BYTES>>>(
        gy16, gWp16, out, out, out);
}

// round 10
// speedup vs baseline: 7.9798x; 1.1003x over previous
#include <cuda_runtime.h>
#include <cuda_bf16.h>
#include <cuda_fp16.h>
#include <math.h>
#include <stdint.h>

#define T_SEQ  2048
#define DMODEL 1024
#define NHEADS 16
#define HDIM   64
#define KDIM   1024
#define BK     64
#define NSTAGES (KDIM / BK)      // 16
#define NPIPE  3

// ---------------------------------------------------------------------------
// Scratch (static device globals — no allocation allowed in kernel_launch)
// ---------------------------------------------------------------------------
__device__ float g_q[T_SEQ * DMODEL];
__device__ float g_k[T_SEQ * DMODEL];
__device__ float g_v[T_SEQ * DMODEL];
__device__ __align__(16) __half g_x16[T_SEQ * DMODEL];
__device__ __align__(16) __half g_y16[T_SEQ * DMODEL];
__device__ __align__(16) __half g_Wqkv16[3 * DMODEL * DMODEL];
__device__ __align__(16) __half g_Wp16[DMODEL * DMODEL];
// fp16 q/k/v for attention (q pre-scaled by 0.125*log2e)
__device__ __align__(16) __half g_q16[T_SEQ * DMODEL];
__device__ __align__(16) __half g_k16[T_SEQ * DMODEL];
__device__ __align__(16) __half g_v16[T_SEQ * DMODEL];
// split-K attention partials
__device__ __align__(16) float g_part[2 * T_SEQ * DMODEL];
__device__ float g_ml[2 * T_SEQ * NHEADS * 2];   // [z][t][h][{m,l}]

// ---------------------------------------------------------------------------
__device__ __forceinline__ uint32_t smem_u32(const void* p) {
    uint32_t a;
    asm("{ .reg .u64 t; cvta.to.shared.u64 t, %1; cvt.u32.u64 %0, t; }"
        : "=r"(a) : "l"(p));
    return a;
}

__device__ __forceinline__ void ldsm_x4(uint32_t* r, uint32_t addr) {
    asm volatile("ldmatrix.sync.aligned.m8n8.x4.shared.b16 {%0,%1,%2,%3}, [%4];"
                 : "=r"(r[0]), "=r"(r[1]), "=r"(r[2]), "=r"(r[3]) : "r"(addr));
}

__device__ __forceinline__ void ldsm_x4_t(uint32_t* r, uint32_t addr) {
    asm volatile("ldmatrix.sync.aligned.m8n8.x4.trans.shared.b16 {%0,%1,%2,%3}, [%4];"
                 : "=r"(r[0]), "=r"(r[1]), "=r"(r[2]), "=r"(r[3]) : "r"(addr));
}

// fp16 MMA, fp32 accumulate
__device__ __forceinline__ void mma16816h(float* d, const uint32_t* a,
                                          const uint32_t* b) {
    asm volatile(
        "mma.sync.aligned.m16n8k16.row.col.f32.f16.f16.f32 "
        "{%0,%1,%2,%3}, {%4,%5,%6,%7}, {%8,%9}, {%0,%1,%2,%3};"
        : "+f"(d[0]), "+f"(d[1]), "+f"(d[2]), "+f"(d[3])
        : "r"(a[0]), "r"(a[1]), "r"(a[2]), "r"(a[3]), "r"(b[0]), "r"(b[1]));
}

__device__ __forceinline__ uint32_t pack_half2(float lo, float hi) {
    uint32_t r;
    asm("cvt.rn.f16x2.f32 %0, %1, %2;" : "=r"(r) : "f"(hi), "f"(lo));
    return r;
}

__device__ __forceinline__ void cp_async16(uint32_t dst, const void* src) {
    asm volatile("cp.async.cg.shared.global [%0], [%1], 16;"
                 :: "r"(dst), "l"(src));
}
#define CP_COMMIT() asm volatile("cp.async.commit_group;" ::: "memory")
#define CP_WAIT(n)  asm volatile("cp.async.wait_group %0;" :: "n"(n) : "memory")

// ---------------------------------------------------------------------------
// fp32 -> fp16 conversion: y selects among {x, Wq, Wk, Wv, Wp}
// ---------------------------------------------------------------------------
extern "C" __global__ void pack16(const float* __restrict__ x,
                                  const float* __restrict__ wq,
                                  const float* __restrict__ wk,
                                  const float* __restrict__ wv,
                                  const float* __restrict__ wp)
{
    const int y = blockIdx.y;
    const float* s;
    __half* d;
    int n4;
    if (y == 0)      { s = x;  d = g_x16;                          n4 = T_SEQ * DMODEL / 4; }
    else if (y == 1) { s = wq; d = g_Wqkv16;                       n4 = DMODEL * DMODEL / 4; }
    else if (y == 2) { s = wk; d = g_Wqkv16 + DMODEL * DMODEL;     n4 = DMODEL * DMODEL / 4; }
    else if (y == 3) { s = wv; d = g_Wqkv16 + 2 * DMODEL * DMODEL; n4 = DMODEL * DMODEL / 4; }
    else             { s = wp; d = g_Wp16;                         n4 = DMODEL * DMODEL / 4; }

    for (int i = blockIdx.x * blockDim.x + threadIdx.x; i < n4;
         i += gridDim.x * blockDim.x) {
        float4 v = ((const float4*)s)[i];
        uint2 o;
        o.x = pack_half2(v.x, v.y);
        o.y = pack_half2(v.z, v.w);
        ((uint2*)d)[i] = o;
    }
}

// ---------------------------------------------------------------------------
// mma.sync fp16 GEMM, cp.async 3-stage pipeline, 2 CTAs/SM.
// ---------------------------------------------------------------------------
#define GEMM_SMEM_BYTES (NPIPE * 32768)

extern "C" __global__ void __launch_bounds__(256, 2)
gemm_f16(const __half* __restrict__ A,
         const __half* __restrict__ B,
         float* __restrict__ C0, float* __restrict__ C1,
         float* __restrict__ C2)
{
    extern __shared__ __align__(1024) char smem[];
    const uint32_t sbase = smem_u32(smem);

    const int tid  = threadIdx.x;
    const int wid  = tid >> 5;
    const int lane = tid & 31;
    const int n0 = blockIdx.x * 128;
    const int m0 = blockIdx.y * 128;
    const int wm = (wid >> 2) * 64;
    const int wn = (wid & 3) * 32;

    const int lrow = tid >> 3;
    const int lq   = tid & 7;
    const __half* Ag = A + (size_t)(m0 + lrow) * KDIM + lq * 8;
    const __half* Bg = B + (size_t)(n0 + lrow) * KDIM + lq * 8;
    const uint32_t st_off = lrow * 128 + ((lq ^ (lrow & 7)) << 4);

    uint32_t aoff[4][4], boff[4][2];
    #pragma unroll
    for (int ks = 0; ks < 4; ks++) {
        #pragma unroll
        for (int mf = 0; mf < 4; mf++) {
            int row = wm + 16 * mf + ((lane >> 3) & 1) * 8 + (lane & 7);
            int ch  = 2 * ks + (lane >> 4);
            aoff[ks][mf] = row * 128 + ((ch ^ (row & 7)) << 4);
        }
        #pragma unroll
        for (int np = 0; np < 2; np++) {
            int row = wn + 16 * np + ((lane >> 4) << 3) + (lane & 7);
            int ch  = 2 * ks + ((lane >> 3) & 1);
            boff[ks][np] = row * 128 + ((ch ^ (row & 7)) << 4);
        }
    }

    float acc[4][4][4];
    #pragma unroll
    for (int i = 0; i < 4; i++)
        #pragma unroll
        for (int j = 0; j < 4; j++)
            #pragma unroll
            for (int r = 0; r < 4; r++) acc[i][j][r] = 0.f;

    auto issue = [&](int s) {
        const uint32_t dst = sbase + (s % NPIPE) * 32768 + st_off;
        const size_t ko = (size_t)s * BK;
        #pragma unroll
        for (int j = 0; j < 4; j++) {
            cp_async16(dst + j * 4096,         Ag + (size_t)32 * j * KDIM + ko);
            cp_async16(dst + 16384 + j * 4096, Bg + (size_t)32 * j * KDIM + ko);
        }
        CP_COMMIT();
    };

    #pragma unroll
    for (int s = 0; s < NPIPE - 1; s++) issue(s);

    for (int s = 0; s < NSTAGES; s++) {
        if (s + 1 < NSTAGES) { CP_WAIT(NPIPE - 2); } else { CP_WAIT(0); }
        __syncthreads();
        if (s + NPIPE - 1 < NSTAGES) issue(s + NPIPE - 1);

        const uint32_t ab32 = sbase + (s % NPIPE) * 32768;
        const uint32_t bb32 = ab32 + 16384;
        #pragma unroll
        for (int ks = 0; ks < 4; ks++) {
            uint32_t af[4][4], bf[2][4];
            #pragma unroll
            for (int mf = 0; mf < 4; mf++)
                ldsm_x4(af[mf], ab32 + aoff[ks][mf]);
            #pragma unroll
            for (int np = 0; np < 2; np++)
                ldsm_x4(bf[np], bb32 + boff[ks][np]);
            #pragma unroll
            for (int mf = 0; mf < 4; mf++)
                #pragma unroll
                for (int nf = 0; nf < 4; nf++)
                    mma16816h(acc[mf][nf], af[mf], &bf[nf >> 1][(nf & 1) * 2]);
        }
        __syncthreads();
    }

    const int sel = n0 >> 10;
    float* __restrict__ C = (sel == 0) ? C0 : (sel == 1) ? C1 : C2;
    const int nl = n0 & 1023;
    const int gr = lane >> 2;
    const int gc = (lane & 3) * 2;
    #pragma unroll
    for (int mf = 0; mf < 4; mf++)
        #pragma unroll
        for (int nf = 0; nf < 4; nf++) {
            const int row = m0 + wm + 16 * mf + gr;
            const int col = nl + wn + 8 * nf + gc;
            *(float2*)&C[(size_t)row * DMODEL + col] =
                make_float2(acc[mf][nf][0], acc[mf][nf][1]);
            *(float2*)&C[(size_t)(row + 8) * DMODEL + col] =
                make_float2(acc[mf][nf][2], acc[mf][nf][3]);
        }
}

// ---------------------------------------------------------------------------
// Fused post: one warp per (t,h). Lane j owns dims j and j+32.
// q is pre-scaled by 0.125 * log2(e) so attention works in exp2 domain.
// ---------------------------------------------------------------------------
extern "C" __global__ void __launch_bounds__(256)
qkv_post(const float* __restrict__ vi, const float* __restrict__ lambdas)
{
    const int u = blockIdx.x * 8 + (threadIdx.x >> 5);   // unit = t*16+h
    const int j = threadIdx.x & 31;
    const int t = u >> 4;
    const int h = u & 15;
    const int base = t * DMODEL + h * HDIM;
    const int i0 = base + j;
    const int i1 = base + j + 32;

    const float l0 = lambdas[0], l1 = lambdas[1];
    {
        float v0 = fmaf(l0, g_v[i0], l1 * vi[i0]);
        float v1 = fmaf(l0, g_v[i1], l1 * vi[i1]);
        g_v16[i0] = __float2half(v0);
        g_v16[i1] = __float2half(v1);
    }

    float q0 = g_q[i0], q1 = g_q[i1];
    float k0 = g_k[i0], k1 = g_k[i1];
    float qs = q0 * q0 + q1 * q1;
    float ks = k0 * k0 + k1 * k1;
    #pragma unroll
    for (int o = 16; o > 0; o >>= 1) {
        qs += __shfl_xor_sync(0xffffffffu, qs, o);
        ks += __shfl_xor_sync(0xffffffffu, ks, o);
    }
    const float eps = 1.1920929e-7f;
    const float rq = rsqrtf(qs * (1.f / 64.f) + eps);
    const float rk = rsqrtf(ks * (1.f / 64.f) + eps);
    q0 *= rq; q1 *= rq; k0 *= rk; k1 *= rk;

    float c = 1.f, s = 0.f;
    if (j < 16) {
        float invf = exp2f(-10.0f * (float)j * (1.0f / 15.0f));
        sincosf((float)t * invf, &s, &c);
    }
    const float QSC = 0.125f * 1.44269504f;   // 1/sqrt(hd) * log2(e)
    float qa = (q0 * c + q1 * s) * QSC;
    float qb = (q1 * c - q0 * s) * QSC;
    float ka =  k0 * c + k1 * s;
    float kb =  k1 * c - k0 * s;

    g_q16[i0] = __float2half(qa);
    g_q16[i1] = __float2half(qb);
    g_k16[i0] = __float2half(ka);
    g_k16[i1] = __float2half(kb);
}

// ---------------------------------------------------------------------------
// Split-K fp16 flash attention, causal, exp2 domain.
// Grid (16 qtiles, 16 heads, 2 splits). 128-row Q tiles, 64-row K/V tiles,
// 8 warps. z=0 handles kt in [0, qt], z=1 handles [qt+1, 2qt+1].
// Emits UNNORMALIZED partial O (fp32) + per-row (m, l) to gmem.
// ---------------------------------------------------------------------------
#define SW(row, q) ((row) * 128 + (((q) ^ ((row) & 7)) << 4))
#define FLASH_SMEM_BYTES (49152)

extern "C" __global__ void __launch_bounds__(256, 2)
flash_mma()
{
    extern __shared__ __align__(1024) char smd[];
    const uint32_t sb = smem_u32(smd);

    const int qt   = (int)gridDim.x - 1 - (int)blockIdx.x;  // heavy first
    const int h    = blockIdx.y;
    const int z    = blockIdx.z;
    const int tid  = threadIdx.x;
    const int lane = tid & 31;
    const int wq   = tid >> 5;
    const int q0   = qt * 128;
    const int ktbeg = z ? (qt + 1) : 0;
    const int ktend = z ? (2 * qt + 1) : qt;   // inclusive
    const size_t hcol = (size_t)h * HDIM;

    const int krow = tid >> 2;            // 0..63
    const int kq2  = (tid & 3) * 2;       // 0,2,4,6
    auto issue_kv = [&](int kt, int buf) {
        const uint32_t dst = sb + buf * 16384;
        const size_t gb = (size_t)(kt * 64 + krow) * DMODEL + hcol + kq2 * 8;
        #pragma unroll
        for (int j = 0; j < 2; j++) {
            const uint32_t so = SW(krow, kq2 + j);
            const size_t go = gb + (size_t)j * 8;
            cp_async16(dst + so,        g_k16 + go);
            cp_async16(dst + 8192 + so, g_v16 + go);
        }
        CP_COMMIT();
    };

    issue_kv(ktbeg, 0);
    {
        const int qrow = tid >> 1;
        const int qqb  = (tid & 1) * 4;
        const uint32_t dst = sb + 32768;
        const size_t gb = (size_t)(q0 + qrow) * DMODEL + hcol + qqb * 8;
        #pragma unroll
        for (int j = 0; j < 4; j++)
            cp_async16(dst + SW(qrow, qqb + j), g_q16 + gb + (size_t)j * 8);
        CP_COMMIT();
    }
    CP_WAIT(0);
    __syncthreads();

    uint32_t qf[4][4];
    #pragma unroll
    for (int ks = 0; ks < 4; ks++) {
        int row = wq * 16 + ((lane >> 3) & 1) * 8 + (lane & 7);
        int ch  = 2 * ks + (lane >> 4);
        ldsm_x4(qf[ks], sb + 32768 + SW(row, ch));
    }
    __syncthreads();

    float O[8][4];
    #pragma unroll
    for (int i = 0; i < 8; i++)
        #pragma unroll
        for (int r = 0; r < 4; r++) O[i][r] = 0.f;
    float m0r = -INFINITY, m1r = -INFINITY, l0r = 0.f, l1r = 0.f;

    const int gr = lane >> 2;
    const int gc = 2 * (lane & 3);
    const int r0 = wq * 16 + gr;
    const int r1 = r0 + 8;
    const int grow0 = q0 + r0;
    const int grow1 = q0 + r1;

    for (int kt = ktbeg; kt <= ktend; kt++) {
        const int buf = (kt - ktbeg) & 1;
        if (kt > ktbeg) { CP_WAIT(0); __syncthreads(); }
        if (kt + 1 <= ktend) issue_kv(kt + 1, buf ^ 1);

        const uint32_t KB = sb + buf * 16384;
        const uint32_t VB = KB + 8192;

        float S[8][4];
        #pragma unroll
        for (int i = 0; i < 8; i++)
            #pragma unroll
            for (int r = 0; r < 4; r++) S[i][r] = 0.f;

        #pragma unroll
        for (int ks = 0; ks < 4; ks++) {
            uint32_t bh[4][4];
            #pragma unroll
            for (int np = 0; np < 4; np++) {
                int row = np * 16 + ((lane >> 4) << 3) + (lane & 7);
                int ch  = 2 * ks + ((lane >> 3) & 1);
                ldsm_x4(bh[np], KB + SW(row, ch));
            }
            #pragma unroll
            for (int nf = 0; nf < 8; nf++)
                mma16816h(S[nf], qf[ks], &bh[nf >> 1][(nf & 1) * 2]);
        }

        if (kt >= 2 * qt) {
            const int k0c = kt * 64;
            #pragma unroll
            for (int nf = 0; nf < 8; nf++) {
                int cg = k0c + 8 * nf + gc;
                if (cg     > grow0) S[nf][0] = -1e30f;
                if (cg + 1 > grow0) S[nf][1] = -1e30f;
                if (cg     > grow1) S[nf][2] = -1e30f;
                if (cg + 1 > grow1) S[nf][3] = -1e30f;
            }
        }

        float mx0 = -INFINITY, mx1 = -INFINITY;
        #pragma unroll
        for (int nf = 0; nf < 8; nf++) {
            mx0 = fmaxf(mx0, fmaxf(S[nf][0], S[nf][1]));
            mx1 = fmaxf(mx1, fmaxf(S[nf][2], S[nf][3]));
        }
        mx0 = fmaxf(mx0, __shfl_xor_sync(0xffffffffu, mx0, 1));
        mx0 = fmaxf(mx0, __shfl_xor_sync(0xffffffffu, mx0, 2));
        mx1 = fmaxf(mx1, __shfl_xor_sync(0xffffffffu, mx1, 1));
        mx1 = fmaxf(mx1, __shfl_xor_sync(0xffffffffu, mx1, 2));

        const float mn0 = fmaxf(m0r, mx0);
        const float mn1 = fmaxf(m1r, mx1);
        const float a0 = exp2f(m0r - mn0);
        const float a1 = exp2f(m1r - mn1);

        #pragma unroll
        for (int nf = 0; nf < 8; nf++) {
            O[nf][0] *= a0; O[nf][1] *= a0;
            O[nf][2] *= a1; O[nf][3] *= a1;
        }

        // exps + PV interleaved per js (low register pressure)
        float s0 = 0.f, s1 = 0.f;
        #pragma unroll
        for (int js = 0; js < 4; js++) {
            uint32_t Ap[4];
            #pragma unroll
            for (int half = 0; half < 2; half++) {
                const int nf = 2 * js + half;
                float p0 = exp2f(S[nf][0] - mn0);
                float p1 = exp2f(S[nf][1] - mn0);
                float p2 = exp2f(S[nf][2] - mn1);
                float p3 = exp2f(S[nf][3] - mn1);
                s0 += p0 + p1;
                s1 += p2 + p3;
                Ap[half * 2 + 0] = pack_half2(p0, p1);
                Ap[half * 2 + 1] = pack_half2(p2, p3);
            }
            uint32_t vh[4][4];
            #pragma unroll
            for (int np = 0; np < 4; np++) {
                int row = js * 16 + ((lane >> 3) & 1) * 8 + (lane & 7);
                int ch  = 2 * np + (lane >> 4);
                ldsm_x4_t(vh[np], VB + SW(row, ch));
            }
            #pragma unroll
            for (int nf = 0; nf < 8; nf++)
                mma16816h(O[nf], Ap, &vh[nf >> 1][(nf & 1) * 2]);
        }
        s0 += __shfl_xor_sync(0xffffffffu, s0, 1);
        s0 += __shfl_xor_sync(0xffffffffu, s0, 2);
        s1 += __shfl_xor_sync(0xffffffffu, s1, 1);
        s1 += __shfl_xor_sync(0xffffffffu, s1, 2);
        l0r = l0r * a0 + s0;
        l1r = l1r * a1 + s1;
        m0r = mn0;
        m1r = mn1;
        __syncthreads();
    }

    // epilogue: unnormalized partial O (fp32) + (m,l) per row
    float* part = g_part + (size_t)z * T_SEQ * DMODEL;
    #pragma unroll
    for (int nf = 0; nf < 8; nf++) {
        const size_t col = hcol + 8 * nf + gc;
        *(float2*)&part[(size_t)grow0 * DMODEL + col] =
            make_float2(O[nf][0], O[nf][1]);
        *(float2*)&part[(size_t)grow1 * DMODEL + col] =
            make_float2(O[nf][2], O[nf][3]);
    }
    if ((lane & 3) == 0) {
        float* ml = g_ml + ((size_t)z * T_SEQ * NHEADS) * 2;
        ml[(grow0 * NHEADS + h) * 2 + 0] = m0r;
        ml[(grow0 * NHEADS + h) * 2 + 1] = l0r;
        ml[(grow1 * NHEADS + h) * 2 + 0] = m1r;
        ml[(grow1 * NHEADS + h) * 2 + 1] = l1r;
    }
}

// ---------------------------------------------------------------------------
// Combine the two split-K halves: y = (O0*w0 + O1*w1) / (l0*w0 + l1*w1),
// w_z = exp2(m_z - max(m0,m1)). Writes fp16 y (proj GEMM input).
// ---------------------------------------------------------------------------
extern "C" __global__ void __launch_bounds__(256)
combine_attn()
{
    const int t = blockIdx.x;
    const int c0 = threadIdx.x * 4;          // 4 cols per thread
    const int h = c0 >> 6;

    const float m0 = g_ml[((size_t)t * NHEADS + h) * 2 + 0];
    const float l0 = g_ml[((size_t)t * NHEADS + h) * 2 + 1];
    const float m1 = g_ml[((size_t)(T_SEQ + t) * NHEADS + h) * 2 + 0];
    const float l1 = g_ml[((size_t)(T_SEQ + t) * NHEADS + h) * 2 + 1];

    const float m  = fmaxf(m0, m1);
    const float w0 = exp2f(m0 - m);
    const float w1 = exp2f(m1 - m);
    const float inv = 1.f / fmaf(l0, w0, l1 * w1);
    const float f0 = w0 * inv;
    const float f1 = w1 * inv;

    const size_t idx = (size_t)t * DMODEL + c0;
    float4 p0 = *(const float4*)&g_part[idx];
    float4 p1 = *(const float4*)&g_part[(size_t)T_SEQ * DMODEL + idx];
    uint2 o;
    o.x = pack_half2(fmaf(p0.x, f0, p1.x * f1), fmaf(p0.y, f0, p1.y * f1));
    o.y = pack_half2(fmaf(p0.z, f0, p1.z * f1), fmaf(p0.w, f0, p1.w * f1));
    *(uint2*)(g_y16 + idx) = o;
}

// ---------------------------------------------------------------------------
extern "C" void kernel_launch(void* const* d_in, const int* in_sizes, int n_in,
                              void* d_out, int out_size)
{
    const float* x   = (const float*)d_in[0];
    const float* vi  = (const float*)d_in[1];
    const float* Wq  = (const float*)d_in[2];
    const float* Wk  = (const float*)d_in[3];
    const float* Wv  = (const float*)d_in[4];
    const float* Wp  = (const float*)d_in[5];
    const float* lam = (const float*)d_in[6];
    float* out = (float*)d_out;

    float *gq, *gk, *gv;
    __half *gx16, *gy16, *gWqkv16, *gWp16;
    cudaGetSymbolAddress((void**)&gq, g_q);
    cudaGetSymbolAddress((void**)&gk, g_k);
    cudaGetSymbolAddress((void**)&gv, g_v);
    cudaGetSymbolAddress((void**)&gx16, g_x16);
    cudaGetSymbolAddress((void**)&gy16, g_y16);
    cudaGetSymbolAddress((void**)&gWqkv16, g_Wqkv16);
    cudaGetSymbolAddress((void**)&gWp16, g_Wp16);

    cudaFuncSetAttribute(gemm_f16, cudaFuncAttributeMaxDynamicSharedMemorySize,
                         GEMM_SMEM_BYTES);
    cudaFuncSetAttribute(flash_mma, cudaFuncAttributeMaxDynamicSharedMemorySize,
                         FLASH_SMEM_BYTES);

    pack16<<<dim3(256, 5), 256>>>(x, Wq, Wk, Wv, Wp);

    // fused QKV: N = 3072
    gemm_f16<<<dim3(3 * DMODEL / 128, T_SEQ / 128), 256, GEMM_SMEM_BYTES>>>(
        gx16, gWqkv16, gq, gk, gv);

    qkv_post<<<T_SEQ * NHEADS / 8, 256>>>(vi, lam);

    flash_mma<<<dim3(T_SEQ / 128, NHEADS, 2), 256, FLASH_SMEM_BYTES>>>();
    combine_attn<<<T_SEQ, 256>>>();

    gemm_f16<<<dim3(DMODEL / 128, T_SEQ / 128), 256, GEMM_SMEM_BYTES>>>(
        gy16, gWp16, out, out, out);
}

// round 11
// speedup vs baseline: 8.3544x; 1.0469x over previous
#include <cuda_runtime.h>
#include <cuda_bf16.h>
#include <cuda_fp16.h>
#include <math.h>
#include <stdint.h>

#define T_SEQ  2048
#define DMODEL 1024
#define NHEADS 16
#define HDIM   64
#define KDIM   1024
#define BK     64
#define NSTAGES (KDIM / BK)      // 16
#define NPIPE  3

// ---------------------------------------------------------------------------
// Scratch (static device globals — no allocation allowed in kernel_launch)
// ---------------------------------------------------------------------------
__device__ float g_q[T_SEQ * DMODEL];
__device__ float g_k[T_SEQ * DMODEL];
__device__ float g_v[T_SEQ * DMODEL];
__device__ __align__(16) __half g_x16[T_SEQ * DMODEL];
__device__ __align__(16) __half g_y16[T_SEQ * DMODEL];
__device__ __align__(16) __half g_Wqkv16[3 * DMODEL * DMODEL];
__device__ __align__(16) __half g_Wp16[DMODEL * DMODEL];
// fp16 q/k/v for attention (q pre-scaled by 0.125*log2e)
__device__ __align__(16) __half g_q16[T_SEQ * DMODEL];
__device__ __align__(16) __half g_k16[T_SEQ * DMODEL];
__device__ __align__(16) __half g_v16[T_SEQ * DMODEL];
// split-K attention partials (uniformly scaled by 2^-12; cancels in combine)
__device__ __align__(16) float g_part[2 * T_SEQ * DMODEL];
__device__ float g_l[2 * T_SEQ * NHEADS];   // [z][t][h] row sums

// ---------------------------------------------------------------------------
__device__ __forceinline__ uint32_t smem_u32(const void* p) {
    uint32_t a;
    asm("{ .reg .u64 t; cvta.to.shared.u64 t, %1; cvt.u32.u64 %0, t; }"
        : "=r"(a) : "l"(p));
    return a;
}

__device__ __forceinline__ void ldsm_x4(uint32_t* r, uint32_t addr) {
    asm volatile("ldmatrix.sync.aligned.m8n8.x4.shared.b16 {%0,%1,%2,%3}, [%4];"
                 : "=r"(r[0]), "=r"(r[1]), "=r"(r[2]), "=r"(r[3]) : "r"(addr));
}

__device__ __forceinline__ void ldsm_x4_t(uint32_t* r, uint32_t addr) {
    asm volatile("ldmatrix.sync.aligned.m8n8.x4.trans.shared.b16 {%0,%1,%2,%3}, [%4];"
                 : "=r"(r[0]), "=r"(r[1]), "=r"(r[2]), "=r"(r[3]) : "r"(addr));
}

// fp16 MMA, fp32 accumulate
__device__ __forceinline__ void mma16816h(float* d, const uint32_t* a,
                                          const uint32_t* b) {
    asm volatile(
        "mma.sync.aligned.m16n8k16.row.col.f32.f16.f16.f32 "
        "{%0,%1,%2,%3}, {%4,%5,%6,%7}, {%8,%9}, {%0,%1,%2,%3};"
        : "+f"(d[0]), "+f"(d[1]), "+f"(d[2]), "+f"(d[3])
        : "r"(a[0]), "r"(a[1]), "r"(a[2]), "r"(a[3]), "r"(b[0]), "r"(b[1]));
}

__device__ __forceinline__ uint32_t pack_half2(float lo, float hi) {
    uint32_t r;
    asm("cvt.rn.f16x2.f32 %0, %1, %2;" : "=r"(r) : "f"(hi), "f"(lo));
    return r;
}

__device__ __forceinline__ float ex2(float x) {
    float r;
    asm("ex2.approx.f32 %0, %1;" : "=f"(r) : "f"(x));
    return r;
}

__device__ __forceinline__ void cp_async16(uint32_t dst, const void* src) {
    asm volatile("cp.async.cg.shared.global [%0], [%1], 16;"
                 :: "r"(dst), "l"(src));
}
#define CP_COMMIT() asm volatile("cp.async.commit_group;" ::: "memory")
#define CP_WAIT(n)  asm volatile("cp.async.wait_group %0;" :: "n"(n) : "memory")

// ---------------------------------------------------------------------------
// fp32 -> fp16 conversion: y selects among {x, Wq, Wk, Wv, Wp}
// ---------------------------------------------------------------------------
extern "C" __global__ void pack16(const float* __restrict__ x,
                                  const float* __restrict__ wq,
                                  const float* __restrict__ wk,
                                  const float* __restrict__ wv,
                                  const float* __restrict__ wp)
{
    const int y = blockIdx.y;
    const float* s;
    __half* d;
    int n4;
    if (y == 0)      { s = x;  d = g_x16;                          n4 = T_SEQ * DMODEL / 4; }
    else if (y == 1) { s = wq; d = g_Wqkv16;                       n4 = DMODEL * DMODEL / 4; }
    else if (y == 2) { s = wk; d = g_Wqkv16 + DMODEL * DMODEL;     n4 = DMODEL * DMODEL / 4; }
    else if (y == 3) { s = wv; d = g_Wqkv16 + 2 * DMODEL * DMODEL; n4 = DMODEL * DMODEL / 4; }
    else             { s = wp; d = g_Wp16;                         n4 = DMODEL * DMODEL / 4; }

    for (int i = blockIdx.x * blockDim.x + threadIdx.x; i < n4;
         i += gridDim.x * blockDim.x) {
        float4 v = ((const float4*)s)[i];
        uint2 o;
        o.x = pack_half2(v.x, v.y);
        o.y = pack_half2(v.z, v.w);
        ((uint2*)d)[i] = o;
    }
}

// ---------------------------------------------------------------------------
// mma.sync fp16 GEMM, cp.async 3-stage pipeline, 2 CTAs/SM.
// ---------------------------------------------------------------------------
#define GEMM_SMEM_BYTES (NPIPE * 32768)

extern "C" __global__ void __launch_bounds__(256, 2)
gemm_f16(const __half* __restrict__ A,
         const __half* __restrict__ B,
         float* __restrict__ C0, float* __restrict__ C1,
         float* __restrict__ C2)
{
    extern __shared__ __align__(1024) char smem[];
    const uint32_t sbase = smem_u32(smem);

    const int tid  = threadIdx.x;
    const int wid  = tid >> 5;
    const int lane = tid & 31;
    const int n0 = blockIdx.x * 128;
    const int m0 = blockIdx.y * 128;
    const int wm = (wid >> 2) * 64;
    const int wn = (wid & 3) * 32;

    const int lrow = tid >> 3;
    const int lq   = tid & 7;
    const __half* Ag = A + (size_t)(m0 + lrow) * KDIM + lq * 8;
    const __half* Bg = B + (size_t)(n0 + lrow) * KDIM + lq * 8;
    const uint32_t st_off = lrow * 128 + ((lq ^ (lrow & 7)) << 4);

    uint32_t aoff[4][4], boff[4][2];
    #pragma unroll
    for (int ks = 0; ks < 4; ks++) {
        #pragma unroll
        for (int mf = 0; mf < 4; mf++) {
            int row = wm + 16 * mf + ((lane >> 3) & 1) * 8 + (lane & 7);
            int ch  = 2 * ks + (lane >> 4);
            aoff[ks][mf] = row * 128 + ((ch ^ (row & 7)) << 4);
        }
        #pragma unroll
        for (int np = 0; np < 2; np++) {
            int row = wn + 16 * np + ((lane >> 4) << 3) + (lane & 7);
            int ch  = 2 * ks + ((lane >> 3) & 1);
            boff[ks][np] = row * 128 + ((ch ^ (row & 7)) << 4);
        }
    }

    float acc[4][4][4];
    #pragma unroll
    for (int i = 0; i < 4; i++)
        #pragma unroll
        for (int j = 0; j < 4; j++)
            #pragma unroll
            for (int r = 0; r < 4; r++) acc[i][j][r] = 0.f;

    auto issue = [&](int s) {
        const uint32_t dst = sbase + (s % NPIPE) * 32768 + st_off;
        const size_t ko = (size_t)s * BK;
        #pragma unroll
        for (int j = 0; j < 4; j++) {
            cp_async16(dst + j * 4096,         Ag + (size_t)32 * j * KDIM + ko);
            cp_async16(dst + 16384 + j * 4096, Bg + (size_t)32 * j * KDIM + ko);
        }
        CP_COMMIT();
    };

    #pragma unroll
    for (int s = 0; s < NPIPE - 1; s++) issue(s);

    for (int s = 0; s < NSTAGES; s++) {
        if (s + 1 < NSTAGES) { CP_WAIT(NPIPE - 2); } else { CP_WAIT(0); }
        __syncthreads();
        if (s + NPIPE - 1 < NSTAGES) issue(s + NPIPE - 1);

        const uint32_t ab32 = sbase + (s % NPIPE) * 32768;
        const uint32_t bb32 = ab32 + 16384;
        #pragma unroll
        for (int ks = 0; ks < 4; ks++) {
            uint32_t af[4][4], bf[2][4];
            #pragma unroll
            for (int mf = 0; mf < 4; mf++)
                ldsm_x4(af[mf], ab32 + aoff[ks][mf]);
            #pragma unroll
            for (int np = 0; np < 2; np++)
                ldsm_x4(bf[np], bb32 + boff[ks][np]);
            #pragma unroll
            for (int mf = 0; mf < 4; mf++)
                #pragma unroll
                for (int nf = 0; nf < 4; nf++)
                    mma16816h(acc[mf][nf], af[mf], &bf[nf >> 1][(nf & 1) * 2]);
        }
        __syncthreads();
    }

    const int sel = n0 >> 10;
    float* __restrict__ C = (sel == 0) ? C0 : (sel == 1) ? C1 : C2;
    const int nl = n0 & 1023;
    const int gr = lane >> 2;
    const int gc = (lane & 3) * 2;
    #pragma unroll
    for (int mf = 0; mf < 4; mf++)
        #pragma unroll
        for (int nf = 0; nf < 4; nf++) {
            const int row = m0 + wm + 16 * mf + gr;
            const int col = nl + wn + 8 * nf + gc;
            *(float2*)&C[(size_t)row * DMODEL + col] =
                make_float2(acc[mf][nf][0], acc[mf][nf][1]);
            *(float2*)&C[(size_t)(row + 8) * DMODEL + col] =
                make_float2(acc[mf][nf][2], acc[mf][nf][3]);
        }
}

// ---------------------------------------------------------------------------
// Fused post: one warp per (t,h). Lane j owns dims j and j+32.
// q is pre-scaled by 0.125 * log2(e) so attention works in exp2 domain.
// ---------------------------------------------------------------------------
extern "C" __global__ void __launch_bounds__(256)
qkv_post(const float* __restrict__ vi, const float* __restrict__ lambdas)
{
    const int u = blockIdx.x * 8 + (threadIdx.x >> 5);   // unit = t*16+h
    const int j = threadIdx.x & 31;
    const int t = u >> 4;
    const int h = u & 15;
    const int base = t * DMODEL + h * HDIM;
    const int i0 = base + j;
    const int i1 = base + j + 32;

    const float l0 = lambdas[0], l1 = lambdas[1];
    {
        float v0 = fmaf(l0, g_v[i0], l1 * vi[i0]);
        float v1 = fmaf(l0, g_v[i1], l1 * vi[i1]);
        g_v16[i0] = __float2half(v0);
        g_v16[i1] = __float2half(v1);
    }

    float q0 = g_q[i0], q1 = g_q[i1];
    float k0 = g_k[i0], k1 = g_k[i1];
    float qs = q0 * q0 + q1 * q1;
    float ks = k0 * k0 + k1 * k1;
    #pragma unroll
    for (int o = 16; o > 0; o >>= 1) {
        qs += __shfl_xor_sync(0xffffffffu, qs, o);
        ks += __shfl_xor_sync(0xffffffffu, ks, o);
    }
    const float eps = 1.1920929e-7f;
    const float rq = rsqrtf(qs * (1.f / 64.f) + eps);
    const float rk = rsqrtf(ks * (1.f / 64.f) + eps);
    q0 *= rq; q1 *= rq; k0 *= rk; k1 *= rk;

    float c = 1.f, s = 0.f;
    if (j < 16) {
        float invf = exp2f(-10.0f * (float)j * (1.0f / 15.0f));
        sincosf((float)t * invf, &s, &c);
    }
    const float QSC = 0.125f * 1.44269504f;   // 1/sqrt(hd) * log2(e)
    float qa = (q0 * c + q1 * s) * QSC;
    float qb = (q1 * c - q0 * s) * QSC;
    float ka =  k0 * c + k1 * s;
    float kb =  k1 * c - k0 * s;

    g_q16[i0] = __float2half(qa);
    g_q16[i1] = __float2half(qb);
    g_k16[i0] = __float2half(ka);
    g_k16[i1] = __float2half(kb);
}

// ---------------------------------------------------------------------------
// Split-K fp16 flash attention, causal, exp2 domain, FIXED softmax max.
// Scores satisfy |S| <= 64*0.125*log2(e) = 11.54 < 12 (rmsnorm bound), so
// p = ex2(S - 12) never overflows and no online max tracking is needed.
// All partials carry a uniform 2^-12 scale that cancels in combine.
// Grid (16 qtiles, 16 heads, 2 splits); 128-row Q, 64-row K/V, 8 warps.
// ---------------------------------------------------------------------------
#define SW(row, q) ((row) * 128 + (((q) ^ ((row) & 7)) << 4))
#define FLASH_SMEM_BYTES (49152)
#define MAXLOG 12.0f

extern "C" __global__ void __launch_bounds__(256, 2)
flash_mma()
{
    extern __shared__ __align__(1024) char smd[];
    const uint32_t sb = smem_u32(smd);

    const int qt   = (int)gridDim.x - 1 - (int)blockIdx.x;  // heavy first
    const int h    = blockIdx.y;
    const int z    = blockIdx.z;
    const int tid  = threadIdx.x;
    const int lane = tid & 31;
    const int wq   = tid >> 5;
    const int q0   = qt * 128;
    const int ktbeg = z ? (qt + 1) : 0;
    const int ktend = z ? (2 * qt + 1) : qt;   // inclusive
    const size_t hcol = (size_t)h * HDIM;

    const int krow = tid >> 2;            // 0..63
    const int kq2  = (tid & 3) * 2;       // 0,2,4,6
    auto issue_kv = [&](int kt, int buf) {
        const uint32_t dst = sb + buf * 16384;
        const size_t gb = (size_t)(kt * 64 + krow) * DMODEL + hcol + kq2 * 8;
        #pragma unroll
        for (int j = 0; j < 2; j++) {
            const uint32_t so = SW(krow, kq2 + j);
            const size_t go = gb + (size_t)j * 8;
            cp_async16(dst + so,        g_k16 + go);
            cp_async16(dst + 8192 + so, g_v16 + go);
        }
        CP_COMMIT();
    };

    issue_kv(ktbeg, 0);
    {
        const int qrow = tid >> 1;
        const int qqb  = (tid & 1) * 4;
        const uint32_t dst = sb + 32768;
        const size_t gb = (size_t)(q0 + qrow) * DMODEL + hcol + qqb * 8;
        #pragma unroll
        for (int j = 0; j < 4; j++)
            cp_async16(dst + SW(qrow, qqb + j), g_q16 + gb + (size_t)j * 8);
        CP_COMMIT();
    }
    CP_WAIT(0);
    __syncthreads();

    uint32_t qf[4][4];
    #pragma unroll
    for (int ks = 0; ks < 4; ks++) {
        int row = wq * 16 + ((lane >> 3) & 1) * 8 + (lane & 7);
        int ch  = 2 * ks + (lane >> 4);
        ldsm_x4(qf[ks], sb + 32768 + SW(row, ch));
    }
    __syncthreads();

    float O[8][4];
    #pragma unroll
    for (int i = 0; i < 8; i++)
        #pragma unroll
        for (int r = 0; r < 4; r++) O[i][r] = 0.f;
    float l0r = 0.f, l1r = 0.f;

    const int gr = lane >> 2;
    const int gc = 2 * (lane & 3);
    const int r0 = wq * 16 + gr;
    const int r1 = r0 + 8;
    const int grow0 = q0 + r0;
    const int grow1 = q0 + r1;

    for (int kt = ktbeg; kt <= ktend; kt++) {
        const int buf = (kt - ktbeg) & 1;
        if (kt > ktbeg) { CP_WAIT(0); __syncthreads(); }
        if (kt + 1 <= ktend) issue_kv(kt + 1, buf ^ 1);

        const uint32_t KB = sb + buf * 16384;
        const uint32_t VB = KB + 8192;

        float S[8][4];
        #pragma unroll
        for (int i = 0; i < 8; i++)
            #pragma unroll
            for (int r = 0; r < 4; r++) S[i][r] = -MAXLOG;

        #pragma unroll
        for (int ks = 0; ks < 4; ks++) {
            uint32_t bh[4][4];
            #pragma unroll
            for (int np = 0; np < 4; np++) {
                int row = np * 16 + ((lane >> 4) << 3) + (lane & 7);
                int ch  = 2 * ks + ((lane >> 3) & 1);
                ldsm_x4(bh[np], KB + SW(row, ch));
            }
            #pragma unroll
            for (int nf = 0; nf < 8; nf++)
                mma16816h(S[nf], qf[ks], &bh[nf >> 1][(nf & 1) * 2]);
        }

        if (kt >= 2 * qt) {
            const int k0c = kt * 64;
            #pragma unroll
            for (int nf = 0; nf < 8; nf++) {
                int cg = k0c + 8 * nf + gc;
                if (cg     > grow0) S[nf][0] = -1e30f;
                if (cg + 1 > grow0) S[nf][1] = -1e30f;
                if (cg     > grow1) S[nf][2] = -1e30f;
                if (cg + 1 > grow1) S[nf][3] = -1e30f;
            }
        }

        // p = ex2(S - MAXLOG) (bias pre-seeded in accumulator init); PV per js
        #pragma unroll
        for (int js = 0; js < 4; js++) {
            uint32_t Ap[4];
            #pragma unroll
            for (int half = 0; half < 2; half++) {
                const int nf = 2 * js + half;
                float p0 = ex2(S[nf][0]);
                float p1 = ex2(S[nf][1]);
                float p2 = ex2(S[nf][2]);
                float p3 = ex2(S[nf][3]);
                l0r += p0 + p1;
                l1r += p2 + p3;
                Ap[half * 2 + 0] = pack_half2(p0, p1);
                Ap[half * 2 + 1] = pack_half2(p2, p3);
            }
            uint32_t vh[4][4];
            #pragma unroll
            for (int np = 0; np < 4; np++) {
                int row = js * 16 + ((lane >> 3) & 1) * 8 + (lane & 7);
                int ch  = 2 * np + (lane >> 4);
                ldsm_x4_t(vh[np], VB + SW(row, ch));
            }
            #pragma unroll
            for (int nf = 0; nf < 8; nf++)
                mma16816h(O[nf], Ap, &vh[nf >> 1][(nf & 1) * 2]);
        }
        __syncthreads();
    }

    // one final l reduction across the 4 lanes of each row group
    l0r += __shfl_xor_sync(0xffffffffu, l0r, 1);
    l0r += __shfl_xor_sync(0xffffffffu, l0r, 2);
    l1r += __shfl_xor_sync(0xffffffffu, l1r, 1);
    l1r += __shfl_xor_sync(0xffffffffu, l1r, 2);

    // epilogue: unnormalized partial O (fp32, scale 2^-12) + l per row
    float* part = g_part + (size_t)z * T_SEQ * DMODEL;
    #pragma unroll
    for (int nf = 0; nf < 8; nf++) {
        const size_t col = hcol + 8 * nf + gc;
        *(float2*)&part[(size_t)grow0 * DMODEL + col] =
            make_float2(O[nf][0], O[nf][1]);
        *(float2*)&part[(size_t)grow1 * DMODEL + col] =
            make_float2(O[nf][2], O[nf][3]);
    }
    if ((lane & 3) == 0) {
        float* lp = g_l + (size_t)z * T_SEQ * NHEADS;
        lp[grow0 * NHEADS + h] = l0r;
        lp[grow1 * NHEADS + h] = l1r;
    }
}

// ---------------------------------------------------------------------------
// Combine the two split-K halves: y = (O0 + O1) / (l0 + l1).
// (Uniform 2^-12 score scale cancels.) Writes fp16 y for the proj GEMM.
// ---------------------------------------------------------------------------
extern "C" __global__ void __launch_bounds__(256)
combine_attn()
{
    const int t = blockIdx.x;
    const int c0 = threadIdx.x * 4;          // 4 cols per thread
    const int h = c0 >> 6;

    const float l0 = g_l[(size_t)t * NHEADS + h];
    const float l1 = g_l[(size_t)(T_SEQ + t) * NHEADS + h];
    const float inv = 1.f / (l0 + l1);

    const size_t idx = (size_t)t * DMODEL + c0;
    float4 p0 = *(const float4*)&g_part[idx];
    float4 p1 = *(const float4*)&g_part[(size_t)T_SEQ * DMODEL + idx];
    uint2 o;
    o.x = pack_half2((p0.x + p1.x) * inv, (p0.y + p1.y) * inv);
    o.y = pack_half2((p0.z + p1.z) * inv, (p0.w + p1.w) * inv);
    *(uint2*)(g_y16 + idx) = o;
}

// ---------------------------------------------------------------------------
extern "C" void kernel_launch(void* const* d_in, const int* in_sizes, int n_in,
                              void* d_out, int out_size)
{
    const float* x   = (const float*)d_in[0];
    const float* vi  = (const float*)d_in[1];
    const float* Wq  = (const float*)d_in[2];
    const float* Wk  = (const float*)d_in[3];
    const float* Wv  = (const float*)d_in[4];
    const float* Wp  = (const float*)d_in[5];
    const float* lam = (const float*)d_in[6];
    float* out = (float*)d_out;

    float *gq, *gk, *gv;
    __half *gx16, *gy16, *gWqkv16, *gWp16;
    cudaGetSymbolAddress((void**)&gq, g_q);
    cudaGetSymbolAddress((void**)&gk, g_k);
    cudaGetSymbolAddress((void**)&gv, g_v);
    cudaGetSymbolAddress((void**)&gx16, g_x16);
    cudaGetSymbolAddress((void**)&gy16, g_y16);
    cudaGetSymbolAddress((void**)&gWqkv16, g_Wqkv16);
    cudaGetSymbolAddress((void**)&gWp16, g_Wp16);

    cudaFuncSetAttribute(gemm_f16, cudaFuncAttributeMaxDynamicSharedMemorySize,
                         GEMM_SMEM_BYTES);
    cudaFuncSetAttribute(flash_mma, cudaFuncAttributeMaxDynamicSharedMemorySize,
                         FLASH_SMEM_BYTES);

    pack16<<<dim3(256, 5), 256>>>(x, Wq, Wk, Wv, Wp);

    // fused QKV: N = 3072
    gemm_f16<<<dim3(3 * DMODEL / 128, T_SEQ / 128), 256, GEMM_SMEM_BYTES>>>(
        gx16, gWqkv16, gq, gk, gv);

    qkv_post<<<T_SEQ * NHEADS / 8, 256>>>(vi, lam);

    flash_mma<<<dim3(T_SEQ / 128, NHEADS, 2), 256, FLASH_SMEM_BYTES>>>();
    combine_attn<<<T_SEQ, 256>>>();

    gemm_f16<<<dim3(DMODEL / 128, T_SEQ / 128), 256, GEMM_SMEM_BYTES>>>(
        gy16, gWp16, out, out, out);
}